// round 1
// baseline (speedup 1.0000x reference)
#include <cuda_runtime.h>
#include <math.h>

#define NNODES 500
#define NP     512
#define NFEAT  32768
#define NEDGE  16000
#define NSCALE 4
#define CHEB_DEG 16
#define NCOEF (CHEB_DEG + 1)
#define DCTN 128

// ---------------- device scratch (static, allocation-free) ----------------
__device__ float g_M [NP * NP];            // L, then M = (L - c0 I)/h
__device__ float g_Ta[NP * NP];            // Chebyshev T buffers (rotating)
__device__ float g_Tb[NP * NP];
__device__ float g_Tc[NP * NP];
__device__ float g_W [NSCALE * NP * NP];   // W_s = e^{-s L}
__device__ float g_deg [NP];
__device__ float g_dinv[NP];
__device__ float g_c0h[2];                 // c0, h
__device__ float g_coef[NCOEF];            // Chebyshev coeffs for e^{-s0 * (c0 + h t)}

// ---------------- packed f32x2 helpers ----------------
__device__ __forceinline__ void fma2(unsigned long long &d,
                                     unsigned long long a,
                                     unsigned long long b) {
    asm("fma.rn.f32x2 %0, %1, %2, %0;" : "+l"(d) : "l"(a), "l"(b));
}
__device__ __forceinline__ unsigned long long splat2(float a) {
    unsigned long long r;
    unsigned int ai = __float_as_uint(a);
    asm("mov.b64 %0, {%1, %1};" : "=l"(r) : "r"(ai));
    return r;
}
__device__ __forceinline__ float2 unpack2(unsigned long long v) {
    unsigned int lo, hi;
    asm("mov.b64 {%0, %1}, %2;" : "=r"(lo), "=r"(hi) : "l"(v));
    float2 f;
    f.x = __uint_as_float(lo);
    f.y = __uint_as_float(hi);
    return f;
}

// ---------------- graph / Laplacian build ----------------
__global__ void k_zero() {
    int i = blockIdx.x * blockDim.x + threadIdx.x;
    if (i < NP * NP) g_M[i] = 0.f;
    if (i < NP) g_deg[i] = 0.f;
}

__global__ void k_degree(const int* __restrict__ ei) {
    int e = blockIdx.x * blockDim.x + threadIdx.x;
    if (e < NEDGE) atomicAdd(&g_deg[ei[NEDGE + e]], 1.0f);
}

__global__ void k_dinv() {
    int i = blockIdx.x * blockDim.x + threadIdx.x;
    if (i < NP) g_dinv[i] = (i < NNODES) ? rsqrtf(fmaxf(g_deg[i], 1.0f)) : 0.f;
}

__global__ void k_adj(const int* __restrict__ ei) {
    int e = blockIdx.x * blockDim.x + threadIdx.x;
    if (e < NEDGE) {
        int s = ei[e], d = ei[NEDGE + e];
        float v = -g_dinv[s] * g_dinv[d];
        g_M[s * NP + d] = v;   // set-semantics: duplicates write same value
        g_M[d * NP + s] = v;
    }
}

__global__ void k_diag() {
    int i = blockIdx.x * blockDim.x + threadIdx.x;
    if (i < NNODES) g_M[i * NP + i] += 1.0f;
}

// Gershgorin bounds over all 512 rows (pad rows give [0,0], which is fine)
__global__ void k_gersh() {
    __shared__ float slo[512], shi[512];
    int i = threadIdx.x;
    float c = g_M[i * NP + i];
    float r = 0.f;
    for (int j = 0; j < NP; j++) r += fabsf(g_M[i * NP + j]);
    r -= fabsf(c);
    slo[i] = c - r;
    shi[i] = c + r;
    __syncthreads();
    for (int s = 256; s > 0; s >>= 1) {
        if (i < s) {
            slo[i] = fminf(slo[i], slo[i + s]);
            shi[i] = fmaxf(shi[i], shi[i + s]);
        }
        __syncthreads();
    }
    if (i == 0) {
        float lo = slo[0], hi = shi[0];
        float c0 = 0.5f * (hi + lo);
        float h  = 0.5f * (hi - lo);
        h = fmaxf(h, 1e-4f) * 1.0001f;   // strict containment margin
        g_c0h[0] = c0;
        g_c0h[1] = h;
    }
}

// Chebyshev coefficients of f(t) = exp(-s0*(c0 + h*t)) on [-1,1] via DCT (fp64)
__global__ void k_coef(const float* __restrict__ scales) {
    int k = threadIdx.x;
    if (k < NCOEF) {
        const double PI = 3.14159265358979323846;
        double s0 = (double)scales[0];
        double c0 = (double)g_c0h[0];
        double h  = (double)g_c0h[1];
        double acc = 0.0;
        for (int j = 0; j < DCTN; j++) {
            double th = PI * (j + 0.5) / (double)DCTN;
            double f  = exp(-s0 * (c0 + h * cos(th)));
            acc += f * cos((double)k * th);
        }
        g_coef[k] = (float)(acc * ((k == 0) ? 1.0 : 2.0) / (double)DCTN);
    }
}

// M = (L - c0 I)/h in place; T0 = I, T1 = M; W0 = c0*I + c1*M
__global__ void k_scaleM_initT() {
    int i = blockIdx.x * blockDim.x + threadIdx.x;
    if (i < NP * NP) {
        int r = i >> 9, c = i & (NP - 1);
        float c0 = g_c0h[0], h = g_c0h[1];
        float diag = (r == c) ? 1.f : 0.f;
        float m = (g_M[i] - c0 * diag) / h;
        g_M[i]  = m;
        g_Ta[i] = diag;
        g_Tb[i] = m;
        g_W[i]  = g_coef[0] * diag + g_coef[1] * m;
    }
}

// ---------------- small 512x512x512 SGEMM ----------------
// MODE 0: D = 2*(A@B) - Q ; g_W[0] += coef[kc]*D   (Chebyshev step)
// MODE 1: D = A@B                                   (squaring)
template <int MODE>
__global__ void __launch_bounds__(256) k_small(const float* __restrict__ A,
                                               const float* __restrict__ B,
                                               const float* __restrict__ Q,
                                               float* __restrict__ D,
                                               int kc) {
    __shared__ __align__(16) float As[32][68];
    __shared__ __align__(16) float Bs[32][64];
    int t = threadIdx.x;
    int m0 = blockIdx.y * 64, n0 = blockIdx.x * 64;
    float acc[4][4] = {};

    for (int kt = 0; kt < NP; kt += 32) {
#pragma unroll
        for (int l = 0; l < 2; l++) {
            int f = t + l * 256;
            int row = f >> 3, kq = f & 7;
            float4 v = *(const float4*)(A + (size_t)(m0 + row) * NP + kt + kq * 4);
            As[kq * 4 + 0][row] = v.x;
            As[kq * 4 + 1][row] = v.y;
            As[kq * 4 + 2][row] = v.z;
            As[kq * 4 + 3][row] = v.w;
        }
#pragma unroll
        for (int l = 0; l < 2; l++) {
            int f = t + l * 256;
            int row = f >> 4, nq = f & 15;
            *(float4*)&Bs[row][nq * 4] =
                *(const float4*)(B + (size_t)(kt + row) * NP + n0 + nq * 4);
        }
        __syncthreads();
        int tm = (t >> 4) * 4, tn = (t & 15) * 4;
#pragma unroll
        for (int kk = 0; kk < 32; kk++) {
            float4 a = *(const float4*)&As[kk][tm];
            float4 b = *(const float4*)&Bs[kk][tn];
            acc[0][0] += a.x * b.x; acc[0][1] += a.x * b.y; acc[0][2] += a.x * b.z; acc[0][3] += a.x * b.w;
            acc[1][0] += a.y * b.x; acc[1][1] += a.y * b.y; acc[1][2] += a.y * b.z; acc[1][3] += a.y * b.w;
            acc[2][0] += a.z * b.x; acc[2][1] += a.z * b.y; acc[2][2] += a.z * b.z; acc[2][3] += a.z * b.w;
            acc[3][0] += a.w * b.x; acc[3][1] += a.w * b.y; acc[3][2] += a.w * b.z; acc[3][3] += a.w * b.w;
        }
        __syncthreads();
    }

    int tm = (t >> 4) * 4, tn = (t & 15) * 4;
    float ck = (MODE == 0) ? g_coef[kc] : 0.f;
#pragma unroll
    for (int r = 0; r < 4; r++) {
#pragma unroll
        for (int c = 0; c < 4; c++) {
            int idx = (m0 + tm + r) * NP + (n0 + tn + c);
            float v = acc[r][c];
            if (MODE == 0) {
                v = 2.f * v - Q[idx];
                D[idx] = v;
                g_W[idx] += ck * v;
            } else {
                D[idx] = v;
            }
        }
    }
}

// ---------------- big GEMM: out[s] = W_s(500x512) @ x(512x32768) ----------------
// 128x128 tile, BK=16, 256 threads, 8x8 micro with packed fma.rn.f32x2
__global__ void __launch_bounds__(256) k_big(const float* __restrict__ x,
                                             float* __restrict__ out) {
    __shared__ __align__(16) float As[16][132];
    __shared__ __align__(16) float Bs[16][128];
    const float* W = g_W + (size_t)blockIdx.z * NP * NP;
    int m0 = blockIdx.y * 128, n0 = blockIdx.x * 128;
    int t = threadIdx.x;
    unsigned long long acc[8][4] = {};

    for (int kt = 0; kt < NP; kt += 16) {
#pragma unroll
        for (int l = 0; l < 2; l++) {
            int f = t + l * 256;
            int row = f >> 2, kq = f & 3;
            float4 v = *(const float4*)(W + (size_t)(m0 + row) * NP + kt + kq * 4);
            As[kq * 4 + 0][row] = v.x;
            As[kq * 4 + 1][row] = v.y;
            As[kq * 4 + 2][row] = v.z;
            As[kq * 4 + 3][row] = v.w;
        }
#pragma unroll
        for (int l = 0; l < 2; l++) {
            int f = t + l * 256;
            int row = f >> 5, nq = f & 31;
            int krow = kt + row;
            float4 v = make_float4(0.f, 0.f, 0.f, 0.f);
            if (krow < NNODES)
                v = *(const float4*)(x + (size_t)krow * NFEAT + n0 + nq * 4);
            *(float4*)&Bs[row][nq * 4] = v;
        }
        __syncthreads();
        int tm = (t >> 4) * 8, tn = (t & 15) * 8;
#pragma unroll
        for (int kk = 0; kk < 16; kk++) {
            float4 a0 = *(const float4*)&As[kk][tm];
            float4 a1 = *(const float4*)&As[kk][tm + 4];
            ulonglong2 b0 = *(const ulonglong2*)&Bs[kk][tn];
            ulonglong2 b1 = *(const ulonglong2*)&Bs[kk][tn + 4];
            float av[8] = {a0.x, a0.y, a0.z, a0.w, a1.x, a1.y, a1.z, a1.w};
#pragma unroll
            for (int r = 0; r < 8; r++) {
                unsigned long long ap = splat2(av[r]);
                fma2(acc[r][0], ap, b0.x);
                fma2(acc[r][1], ap, b0.y);
                fma2(acc[r][2], ap, b1.x);
                fma2(acc[r][3], ap, b1.y);
            }
        }
        __syncthreads();
    }

    int tm = (t >> 4) * 8, tn = (t & 15) * 8;
#pragma unroll
    for (int r = 0; r < 8; r++) {
        int m = m0 + tm + r;
        if (m < NNODES) {
            float2 c0 = unpack2(acc[r][0]);
            float2 c1 = unpack2(acc[r][1]);
            float2 c2 = unpack2(acc[r][2]);
            float2 c3 = unpack2(acc[r][3]);
            size_t base = ((size_t)blockIdx.z * NNODES + m) * NFEAT + n0 + tn;
            *(float4*)(out + base)     = make_float4(c0.x, c0.y, c1.x, c1.y);
            *(float4*)(out + base + 4) = make_float4(c2.x, c2.y, c3.x, c3.y);
        }
    }
}

// ---------------- launch ----------------
extern "C" void kernel_launch(void* const* d_in, const int* in_sizes, int n_in,
                              void* d_out, int out_size) {
    const float* x      = (const float*)d_in[0];
    const int*   ei     = (const int*)d_in[1];
    const float* scales = (const float*)d_in[2];
    float* out = (float*)d_out;

    float *pM, *pTa, *pTb, *pTc, *pW;
    cudaGetSymbolAddress((void**)&pM,  g_M);
    cudaGetSymbolAddress((void**)&pTa, g_Ta);
    cudaGetSymbolAddress((void**)&pTb, g_Tb);
    cudaGetSymbolAddress((void**)&pTc, g_Tc);
    cudaGetSymbolAddress((void**)&pW,  g_W);

    k_zero<<<(NP * NP + 255) / 256, 256>>>();
    k_degree<<<(NEDGE + 255) / 256, 256>>>(ei);
    k_dinv<<<(NP + 255) / 256, 256>>>();
    k_adj<<<(NEDGE + 255) / 256, 256>>>(ei);
    k_diag<<<(NNODES + 255) / 256, 256>>>();
    k_gersh<<<1, 512>>>();
    k_coef<<<1, 32>>>(scales);
    k_scaleM_initT<<<(NP * NP + 255) / 256, 256>>>();

    // Chebyshev recurrence: T_k = 2 M T_{k-1} - T_{k-2}; W0 += c_k T_k
    float* T[3] = {pTa, pTb, pTc};   // T0 = I, T1 = M
    int pp = 0, pv = 1, ot = 2;
    dim3 gs(8, 8);
    for (int k = 2; k <= CHEB_DEG; k++) {
        k_small<0><<<gs, 256>>>(pM, T[pv], T[pp], T[ot], k);
        int tmp = pp; pp = pv; pv = ot; ot = tmp;
    }

    // Squaring ladder: W(2s) = W(s)^2
    for (int j = 0; j < 3; j++) {
        k_small<1><<<gs, 256>>>(pW + (size_t)j * NP * NP,
                                pW + (size_t)j * NP * NP,
                                pW + (size_t)j * NP * NP,  // unused in MODE 1
                                pW + (size_t)(j + 1) * NP * NP, 0);
    }

    // out[s] = W_s @ x
    dim3 gb(NFEAT / 128, NP / 128, NSCALE);
    k_big<<<gb, 256>>>(x, out);
}

// round 3
// speedup vs baseline: 1.6448x; 1.6448x over previous
#include <cuda_runtime.h>
#include <cuda_bf16.h>
#include <math.h>
#include <stdint.h>

#define NNODES 500
#define NP     512
#define NFEAT  32768
#define NEDGE  16000
#define NSCALE 4
#define CHEB_DEG 16
#define NCOEF (CHEB_DEG + 1)
#define DCTN 128

// ---------------- device scratch (static, allocation-free) ----------------
__device__ float g_M [NP * NP];
__device__ float g_Ta[NP * NP];
__device__ float g_Tb[NP * NP];
__device__ float g_Tc[NP * NP];
__device__ float g_W [NSCALE * NP * NP];
__device__ float g_deg [NP];
__device__ float g_dinv[NP];
__device__ float g_c0h[2];
__device__ float g_coef[NCOEF];

// Packed, pre-swizzled (SW128) bf16 operand tiles for the HMMA big GEMM.
// A (W): [scale][m_tile(4)][k_chunk(8)] tiles of 128m x 64k (16KB each)
// B (xT): [n_tile(256)][k_chunk(8)] tiles of 128n x 64k (16KB each)
__device__ __nv_bfloat16 g_Ah[NSCALE * 4 * 8 * 8192];
__device__ __nv_bfloat16 g_Al[NSCALE * 4 * 8 * 8192];
__device__ __nv_bfloat16 g_Bh[256 * 8 * 8192];
__device__ __nv_bfloat16 g_Bl[256 * 8 * 8192];

// ---------------- packed f32x2 helpers ----------------
__device__ __forceinline__ void fma2(unsigned long long &d,
                                     unsigned long long a,
                                     unsigned long long b) {
    asm("fma.rn.f32x2 %0, %1, %2, %0;" : "+l"(d) : "l"(a), "l"(b));
}
__device__ __forceinline__ unsigned long long splat2(float a) {
    unsigned long long r;
    unsigned int ai = __float_as_uint(a);
    asm("mov.b64 %0, {%1, %1};" : "=l"(r) : "r"(ai));
    return r;
}
__device__ __forceinline__ float2 unpack2(unsigned long long v) {
    unsigned int lo, hi;
    asm("mov.b64 {%0, %1}, %2;" : "=r"(lo), "=r"(hi) : "l"(v));
    float2 f;
    f.x = __uint_as_float(lo);
    f.y = __uint_as_float(hi);
    return f;
}

// ---------------- graph / Laplacian build ----------------
__global__ void k_zero() {
    int i = blockIdx.x * blockDim.x + threadIdx.x;
    if (i < NP * NP) g_M[i] = 0.f;
    if (i < NP) g_deg[i] = 0.f;
}

__global__ void k_degree(const int* __restrict__ ei) {
    int e = blockIdx.x * blockDim.x + threadIdx.x;
    if (e < NEDGE) atomicAdd(&g_deg[ei[NEDGE + e]], 1.0f);
}

__global__ void k_dinv() {
    int i = blockIdx.x * blockDim.x + threadIdx.x;
    if (i < NP) g_dinv[i] = (i < NNODES) ? rsqrtf(fmaxf(g_deg[i], 1.0f)) : 0.f;
}

__global__ void k_adj(const int* __restrict__ ei) {
    int e = blockIdx.x * blockDim.x + threadIdx.x;
    if (e < NEDGE) {
        int s = ei[e], d = ei[NEDGE + e];
        float v = -g_dinv[s] * g_dinv[d];
        g_M[s * NP + d] = v;
        g_M[d * NP + s] = v;
    }
}

__global__ void k_diag() {
    int i = blockIdx.x * blockDim.x + threadIdx.x;
    if (i < NNODES) g_M[i * NP + i] += 1.0f;
}

__global__ void k_gersh() {
    __shared__ float slo[512], shi[512];
    int i = threadIdx.x;
    float c = g_M[i * NP + i];
    float r = 0.f;
    for (int j = 0; j < NP; j++) r += fabsf(g_M[i * NP + j]);
    r -= fabsf(c);
    slo[i] = c - r;
    shi[i] = c + r;
    __syncthreads();
    for (int s = 256; s > 0; s >>= 1) {
        if (i < s) {
            slo[i] = fminf(slo[i], slo[i + s]);
            shi[i] = fmaxf(shi[i], shi[i + s]);
        }
        __syncthreads();
    }
    if (i == 0) {
        float lo = slo[0], hi = shi[0];
        float c0 = 0.5f * (hi + lo);
        float h  = 0.5f * (hi - lo);
        h = fmaxf(h, 1e-4f) * 1.0001f;
        g_c0h[0] = c0;
        g_c0h[1] = h;
    }
}

__global__ void k_coef(const float* __restrict__ scales) {
    int k = threadIdx.x;
    if (k < NCOEF) {
        const double PI = 3.14159265358979323846;
        double s0 = (double)scales[0];
        double c0 = (double)g_c0h[0];
        double h  = (double)g_c0h[1];
        double acc = 0.0;
        for (int j = 0; j < DCTN; j++) {
            double th = PI * (j + 0.5) / (double)DCTN;
            double f  = exp(-s0 * (c0 + h * cos(th)));
            acc += f * cos((double)k * th);
        }
        g_coef[k] = (float)(acc * ((k == 0) ? 1.0 : 2.0) / (double)DCTN);
    }
}

__global__ void k_scaleM_initT() {
    int i = blockIdx.x * blockDim.x + threadIdx.x;
    if (i < NP * NP) {
        int r = i >> 9, c = i & (NP - 1);
        float c0 = g_c0h[0], h = g_c0h[1];
        float diag = (r == c) ? 1.f : 0.f;
        float m = (g_M[i] - c0 * diag) / h;
        g_M[i]  = m;
        g_Ta[i] = diag;
        g_Tb[i] = m;
        g_W[i]  = g_coef[0] * diag + g_coef[1] * m;
    }
}

// ---------------- small 512x512x512 SGEMM (Chebyshev chain + squaring) ----
// inner product uses packed fma.rn.f32x2 (2x fp32 rate)
template <int MODE>
__global__ void __launch_bounds__(256) k_small(const float* __restrict__ A,
                                               const float* __restrict__ B,
                                               const float* __restrict__ Q,
                                               float* __restrict__ D,
                                               int kc) {
    __shared__ __align__(16) float As[32][68];
    __shared__ __align__(16) float Bs[32][64];
    int t = threadIdx.x;
    int m0 = blockIdx.y * 64, n0 = blockIdx.x * 64;
    unsigned long long acc2[4][2] = {};

    for (int kt = 0; kt < NP; kt += 32) {
#pragma unroll
        for (int l = 0; l < 2; l++) {
            int f = t + l * 256;
            int row = f >> 3, kq = f & 7;
            float4 v = *(const float4*)(A + (size_t)(m0 + row) * NP + kt + kq * 4);
            As[kq * 4 + 0][row] = v.x;
            As[kq * 4 + 1][row] = v.y;
            As[kq * 4 + 2][row] = v.z;
            As[kq * 4 + 3][row] = v.w;
        }
#pragma unroll
        for (int l = 0; l < 2; l++) {
            int f = t + l * 256;
            int row = f >> 4, nq = f & 15;
            *(float4*)&Bs[row][nq * 4] =
                *(const float4*)(B + (size_t)(kt + row) * NP + n0 + nq * 4);
        }
        __syncthreads();
        int tm = (t >> 4) * 4, tn = (t & 15) * 4;
#pragma unroll
        for (int kk = 0; kk < 32; kk++) {
            float4 a = *(const float4*)&As[kk][tm];
            ulonglong2 b = *(const ulonglong2*)&Bs[kk][tn];
            float av[4] = {a.x, a.y, a.z, a.w};
#pragma unroll
            for (int r = 0; r < 4; r++) {
                unsigned long long ap = splat2(av[r]);
                fma2(acc2[r][0], ap, b.x);
                fma2(acc2[r][1], ap, b.y);
            }
        }
        __syncthreads();
    }

    int tm = (t >> 4) * 4, tn = (t & 15) * 4;
    float ck = (MODE == 0) ? g_coef[kc] : 0.f;
#pragma unroll
    for (int r = 0; r < 4; r++) {
        float2 p0 = unpack2(acc2[r][0]);
        float2 p1 = unpack2(acc2[r][1]);
        float vals[4] = {p0.x, p0.y, p1.x, p1.y};
#pragma unroll
        for (int c = 0; c < 4; c++) {
            int idx = (m0 + tm + r) * NP + (n0 + tn + c);
            float v = vals[c];
            if (MODE == 0) {
                v = 2.f * v - Q[idx];
                D[idx] = v;
                g_W[idx] += ck * v;
            } else {
                D[idx] = v;
            }
        }
    }
}

// ---------------- bf16 hi/lo conversion + tile packing ----------------
// Pack W (4 scales, 512x512 fp32, K-major) into SW128-swizzled 128x64 tiles
__global__ void k_convW() {
    int i = blockIdx.x * blockDim.x + threadIdx.x;
    if (i >= NSCALE * NP * NP) return;
    int s = i >> 18;
    int m = (i >> 9) & 511;
    int k = i & 511;
    float v = g_W[i];
    __nv_bfloat16 h = __float2bfloat16(v);
    __nv_bfloat16 l = __float2bfloat16(v - __bfloat162float(h));
    int tile = ((s * 4 + (m >> 7)) * 8) + (k >> 6);
    int off = (m & 127) * 128 + (k & 63) * 2;
    off ^= (off >> 3) & 0x70;
    int idx = tile * 8192 + (off >> 1);
    g_Ah[idx] = h;
    g_Al[idx] = l;
}

// Transpose x (500x32768 fp32) into SW128-swizzled 128n x 64k bf16 hi/lo tiles
__global__ void __launch_bounds__(256) k_convX(const float* __restrict__ x) {
    __shared__ float t[32][132];
    int nt = blockIdx.x;          // 0..255 (n tile of 128)
    int kb = blockIdx.y;          // 0..15  (32 k-rows each)
    int tid = threadIdx.x;

#pragma unroll
    for (int it = 0; it < 4; it++) {
        int f = tid + it * 256;   // 0..1023 float4 slots (32 rows x 32 f4)
        int row = f >> 5, c4 = f & 31;
        int kg = kb * 32 + row;
        float4 v = make_float4(0.f, 0.f, 0.f, 0.f);
        if (kg < NNODES)
            v = *(const float4*)(x + (size_t)kg * NFEAT + nt * 128 + c4 * 4);
        t[row][c4 * 4 + 0] = v.x;
        t[row][c4 * 4 + 1] = v.y;
        t[row][c4 * 4 + 2] = v.z;
        t[row][c4 * 4 + 3] = v.w;
    }
    __syncthreads();

    size_t tile_bytes = (size_t)(nt * 8 + (kb >> 1)) * 16384;
    int halfk = (kb & 1) * 32;
    char* bh = (char*)g_Bh + tile_bytes;
    char* bl = (char*)g_Bl + tile_bytes;

#pragma unroll
    for (int it = 0; it < 2; it++) {
        int j = tid + it * 256;   // 0..511 : n(128) x 4 groups of 8k
        int n = j >> 2, q = j & 3;
        __align__(16) __nv_bfloat16 hs[8];
        __align__(16) __nv_bfloat16 ls[8];
#pragma unroll
        for (int e = 0; e < 8; e++) {
            float v = t[q * 8 + e][n];
            __nv_bfloat16 h = __float2bfloat16(v);
            hs[e] = h;
            ls[e] = __float2bfloat16(v - __bfloat162float(h));
        }
        int off = n * 128 + (halfk + q * 8) * 2;
        off ^= (off >> 3) & 0x70;
        *(uint4*)(bh + off) = *(const uint4*)hs;
        *(uint4*)(bl + off) = *(const uint4*)ls;
    }
}

// ---------------- HMMA helpers (sm_80+ features only) ----------------
__device__ __forceinline__ void ldmx4(uint32_t* r, uint32_t addr) {
    asm volatile("ldmatrix.sync.aligned.m8n8.x4.shared.b16 {%0,%1,%2,%3}, [%4];"
                 : "=r"(r[0]), "=r"(r[1]), "=r"(r[2]), "=r"(r[3]) : "r"(addr));
}
__device__ __forceinline__ void ldmx2(uint32_t* r, uint32_t addr) {
    asm volatile("ldmatrix.sync.aligned.m8n8.x2.shared.b16 {%0,%1}, [%2];"
                 : "=r"(r[0]), "=r"(r[1]) : "r"(addr));
}
__device__ __forceinline__ void mma16816(float* c, const uint32_t* a,
                                         const uint32_t* b) {
    asm volatile(
        "mma.sync.aligned.m16n8k16.row.col.f32.bf16.bf16.f32 "
        "{%0,%1,%2,%3}, {%4,%5,%6,%7}, {%8,%9}, {%0,%1,%2,%3};"
        : "+f"(c[0]), "+f"(c[1]), "+f"(c[2]), "+f"(c[3])
        : "r"(a[0]), "r"(a[1]), "r"(a[2]), "r"(a[3]), "r"(b[0]), "r"(b[1]));
}
__device__ __forceinline__ void cpasync16(uint32_t dst, const void* src) {
    asm volatile("cp.async.cg.shared.global [%0], [%1], 16;"
                 :: "r"(dst), "l"(src) : "memory");
}

// ---------------- big GEMM: out[s] = W_s @ x via HMMA 3-term bf16 ---------
#define STAGE_BYTES 65536
#define DSMEM_TOTAL (2 * STAGE_BYTES)

__global__ void __launch_bounds__(256, 1) k_bigmma(float* __restrict__ out) {
    extern __shared__ __align__(1024) char smem[];
    uint32_t sb = (uint32_t)__cvta_generic_to_shared(smem);
    int tid = threadIdx.x, wid = tid >> 5, lid = tid & 31;
    int mt = blockIdx.x & 3, s = blockIdx.x >> 2, nt = blockIdx.y;
    int wm0 = (wid >> 2) * 64;    // warp m offset (2 rows of warps)
    int wn0 = (wid & 3) * 32;     // warp n offset (4 cols of warps)

    const char* pAh = (const char*)(g_Ah + ((size_t)((s * 4 + mt) * 8)) * 8192);
    const char* pAl = (const char*)(g_Al + ((size_t)((s * 4 + mt) * 8)) * 8192);
    const char* pBh = (const char*)(g_Bh + ((size_t)(nt * 8)) * 8192);
    const char* pBl = (const char*)(g_Bl + ((size_t)(nt * 8)) * 8192);

    float acc[4][4][4] = {};

    // issue chunk c into stage buf
    auto issue = [&](int c, int buf) {
        uint32_t dst = sb + buf * STAGE_BYTES;
        size_t coff = (size_t)c * 16384;
#pragma unroll
        for (int it = 0; it < 4; it++) {
            int line = tid + it * 256;          // 1024 lines of 16B per region
            uint32_t o = line * 16;
            cpasync16(dst + o,         pAh + coff + o);
            cpasync16(dst + 16384 + o, pAl + coff + o);
            cpasync16(dst + 32768 + o, pBh + coff + o);
            cpasync16(dst + 49152 + o, pBl + coff + o);
        }
    };

    issue(0, 0);
    asm volatile("cp.async.commit_group;");
    issue(1, 1);
    asm volatile("cp.async.commit_group;");

    for (int c = 0; c < 8; c++) {
        asm volatile("cp.async.wait_group 1;");
        __syncthreads();

        uint32_t base = sb + (c & 1) * STAGE_BYTES;
        uint32_t sAh = base, sAl = base + 16384;
        uint32_t sBh = base + 32768, sBl = base + 49152;

#pragma unroll
        for (int kk = 0; kk < 4; kk++) {
            uint32_t ah[4][4], al[4][4], bh[4][2], bl[4][2];
#pragma unroll
            for (int i = 0; i < 4; i++) {
                uint32_t off = (uint32_t)(wm0 + i * 16 + (lid & 15)) * 128 +
                               kk * 32 + (lid >> 4) * 16;
                off ^= (off >> 3) & 0x70;
                ldmx4(ah[i], sAh + off);
                ldmx4(al[i], sAl + off);
            }
#pragma unroll
            for (int j = 0; j < 4; j++) {
                uint32_t off = (uint32_t)(wn0 + j * 8 + (lid & 7)) * 128 +
                               kk * 32 + ((lid >> 3) & 1) * 16;
                off ^= (off >> 3) & 0x70;
                ldmx2(bh[j], sBh + off);
                ldmx2(bl[j], sBl + off);
            }
#pragma unroll
            for (int i = 0; i < 4; i++) {
#pragma unroll
                for (int j = 0; j < 4; j++) {
                    mma16816(acc[i][j], ah[i], bh[j]);
                    mma16816(acc[i][j], ah[i], bl[j]);
                    mma16816(acc[i][j], al[i], bh[j]);
                }
            }
        }
        __syncthreads();
        if (c + 2 < 8) issue(c + 2, c & 1);
        asm volatile("cp.async.commit_group;");
    }

    // epilogue: fragment -> gmem
    int qrow = lid >> 2, qcol = (lid & 3) * 2;
#pragma unroll
    for (int i = 0; i < 4; i++) {
        int m0g = mt * 128 + wm0 + i * 16 + qrow;
#pragma unroll
        for (int j = 0; j < 4; j++) {
            int n = nt * 128 + wn0 + j * 8 + qcol;
            if (m0g < NNODES) {
                size_t idx = ((size_t)s * NNODES + m0g) * NFEAT + n;
                *(float2*)(out + idx) = make_float2(acc[i][j][0], acc[i][j][1]);
            }
            if (m0g + 8 < NNODES) {
                size_t idx = ((size_t)s * NNODES + m0g + 8) * NFEAT + n;
                *(float2*)(out + idx) = make_float2(acc[i][j][2], acc[i][j][3]);
            }
        }
    }
}

// ---------------- launch ----------------
extern "C" void kernel_launch(void* const* d_in, const int* in_sizes, int n_in,
                              void* d_out, int out_size) {
    const float* x      = (const float*)d_in[0];
    const int*   ei     = (const int*)d_in[1];
    const float* scales = (const float*)d_in[2];
    float* out = (float*)d_out;

    float *pM, *pTa, *pTb, *pTc, *pW;
    cudaGetSymbolAddress((void**)&pM,  g_M);
    cudaGetSymbolAddress((void**)&pTa, g_Ta);
    cudaGetSymbolAddress((void**)&pTb, g_Tb);
    cudaGetSymbolAddress((void**)&pTc, g_Tc);
    cudaGetSymbolAddress((void**)&pW,  g_W);

    static int smem_set = 0;
    if (!smem_set) {
        cudaFuncSetAttribute(k_bigmma, cudaFuncAttributeMaxDynamicSharedMemorySize,
                             DSMEM_TOTAL);
        smem_set = 1;
    }

    // graph / Laplacian build
    k_zero<<<(NP * NP + 255) / 256, 256>>>();
    k_degree<<<(NEDGE + 255) / 256, 256>>>(ei);
    k_dinv<<<(NP + 255) / 256, 256>>>();
    k_adj<<<(NEDGE + 255) / 256, 256>>>(ei);
    k_diag<<<(NNODES + 255) / 256, 256>>>();
    k_gersh<<<1, 512>>>();
    k_coef<<<1, 32>>>(scales);
    k_scaleM_initT<<<(NP * NP + 255) / 256, 256>>>();

    // x transpose + bf16 hi/lo pack
    dim3 gx(256, 16);
    k_convX<<<gx, 256>>>(x);

    // Chebyshev recurrence: T_k = 2 M T_{k-1} - T_{k-2}; W0 += c_k T_k
    float* T[3] = {pTa, pTb, pTc};
    int pp = 0, pv = 1, ot = 2;
    dim3 gs(8, 8);
    for (int k = 2; k <= CHEB_DEG; k++) {
        k_small<0><<<gs, 256>>>(pM, T[pv], T[pp], T[ot], k);
        int tmp = pp; pp = pv; pv = ot; ot = tmp;
    }

    // Squaring ladder: W(2s) = W(s)^2
    for (int j = 0; j < 3; j++) {
        k_small<1><<<gs, 256>>>(pW + (size_t)j * NP * NP,
                                pW + (size_t)j * NP * NP,
                                pW + (size_t)j * NP * NP,
                                pW + (size_t)(j + 1) * NP * NP, 0);
    }

    // W bf16 hi/lo pack
    k_convW<<<(NSCALE * NP * NP + 255) / 256, 256>>>();

    // big HMMA GEMM: blockIdx.x = mt + 4*s (16), blockIdx.y = n tile (256)
    dim3 gb(16, 256);
    k_bigmma<<<gb, 256, DSMEM_TOTAL>>>(out);
}

// round 4
// speedup vs baseline: 1.8005x; 1.0947x over previous
#include <cuda_runtime.h>
#include <cuda_bf16.h>
#include <math.h>
#include <stdint.h>

#define NNODES 500
#define NP     512
#define NFEAT  32768
#define NEDGE  16000
#define NSCALE 4
#define CHEB_DEG 12
#define NCOEF (CHEB_DEG + 1)
#define DCTN 128

// ---------------- device scratch (static, allocation-free) ----------------
__device__ float g_M [NP * NP];
__device__ float g_Ta[NP * NP];
__device__ float g_Tb[NP * NP];
__device__ float g_Tc[NP * NP];
__device__ float g_W [NSCALE * NP * NP];
__device__ float g_deg [NP];
__device__ float g_dinv[NP];
__device__ float g_c0h[2];
__device__ float g_coef[NCOEF];

// Packed, pre-swizzled (SW128) bf16 operand tiles for the HMMA big GEMM.
// A (W): [scale][m_tile(4)][k_chunk(8)] tiles of 128m x 64k (16KB each)
// B (xT): [n_tile(256)][k_chunk(8)] tiles of 128n x 64k (16KB each)
__device__ __nv_bfloat16 g_Ah[NSCALE * 4 * 8 * 8192];
__device__ __nv_bfloat16 g_Al[NSCALE * 4 * 8 * 8192];
__device__ __nv_bfloat16 g_Bh[256 * 8 * 8192];
__device__ __nv_bfloat16 g_Bl[256 * 8 * 8192];

// ---------------- packed f32x2 helpers ----------------
__device__ __forceinline__ void fma2(unsigned long long &d,
                                     unsigned long long a,
                                     unsigned long long b) {
    asm("fma.rn.f32x2 %0, %1, %2, %0;" : "+l"(d) : "l"(a), "l"(b));
}
__device__ __forceinline__ unsigned long long splat2(float a) {
    unsigned long long r;
    unsigned int ai = __float_as_uint(a);
    asm("mov.b64 %0, {%1, %1};" : "=l"(r) : "r"(ai));
    return r;
}
__device__ __forceinline__ float2 unpack2(unsigned long long v) {
    unsigned int lo, hi;
    asm("mov.b64 {%0, %1}, %2;" : "=r"(lo), "=r"(hi) : "l"(v));
    float2 f;
    f.x = __uint_as_float(lo);
    f.y = __uint_as_float(hi);
    return f;
}

// ---------------- graph / Laplacian build ----------------
__global__ void k_zero() {
    int i = blockIdx.x * blockDim.x + threadIdx.x;
    if (i < NP * NP) g_M[i] = 0.f;
    if (i < NP) g_deg[i] = 0.f;
}

__global__ void k_degree(const int* __restrict__ ei) {
    int e = blockIdx.x * blockDim.x + threadIdx.x;
    if (e < NEDGE) atomicAdd(&g_deg[ei[NEDGE + e]], 1.0f);
}

__global__ void k_dinv() {
    int i = blockIdx.x * blockDim.x + threadIdx.x;
    if (i < NP) g_dinv[i] = (i < NNODES) ? rsqrtf(fmaxf(g_deg[i], 1.0f)) : 0.f;
}

__global__ void k_adj(const int* __restrict__ ei) {
    int e = blockIdx.x * blockDim.x + threadIdx.x;
    if (e < NEDGE) {
        int s = ei[e], d = ei[NEDGE + e];
        float v = -g_dinv[s] * g_dinv[d];
        g_M[s * NP + d] = v;
        g_M[d * NP + s] = v;
    }
}

__global__ void k_diag() {
    int i = blockIdx.x * blockDim.x + threadIdx.x;
    if (i < NNODES) g_M[i * NP + i] += 1.0f;
}

__global__ void k_gersh() {
    __shared__ float slo[512], shi[512];
    int i = threadIdx.x;
    float c = g_M[i * NP + i];
    float r = 0.f;
    for (int j = 0; j < NP; j++) r += fabsf(g_M[i * NP + j]);
    r -= fabsf(c);
    slo[i] = c - r;
    shi[i] = c + r;
    __syncthreads();
    for (int s = 256; s > 0; s >>= 1) {
        if (i < s) {
            slo[i] = fminf(slo[i], slo[i + s]);
            shi[i] = fmaxf(shi[i], shi[i + s]);
        }
        __syncthreads();
    }
    if (i == 0) {
        float lo = slo[0], hi = shi[0];
        float c0 = 0.5f * (hi + lo);
        float h  = 0.5f * (hi - lo);
        h = fmaxf(h, 1e-4f) * 1.0001f;
        g_c0h[0] = c0;
        g_c0h[1] = h;
    }
}

__global__ void k_coef(const float* __restrict__ scales) {
    int k = threadIdx.x;
    if (k < NCOEF) {
        const double PI = 3.14159265358979323846;
        double s0 = (double)scales[0];
        double c0 = (double)g_c0h[0];
        double h  = (double)g_c0h[1];
        double acc = 0.0;
        for (int j = 0; j < DCTN; j++) {
            double th = PI * (j + 0.5) / (double)DCTN;
            double f  = exp(-s0 * (c0 + h * cos(th)));
            acc += f * cos((double)k * th);
        }
        g_coef[k] = (float)(acc * ((k == 0) ? 1.0 : 2.0) / (double)DCTN);
    }
}

__global__ void k_scaleM_initT() {
    int i = blockIdx.x * blockDim.x + threadIdx.x;
    if (i < NP * NP) {
        int r = i >> 9, c = i & (NP - 1);
        float c0 = g_c0h[0], h = g_c0h[1];
        float diag = (r == c) ? 1.f : 0.f;
        float m = (g_M[i] - c0 * diag) / h;
        g_M[i]  = m;
        g_Ta[i] = diag;
        g_Tb[i] = m;
        g_W[i]  = g_coef[0] * diag + g_coef[1] * m;
    }
}

// ---------------- small 512x512x512 SGEMM (Chebyshev chain + squaring) ----
template <int MODE>
__global__ void __launch_bounds__(256) k_small(const float* __restrict__ A,
                                               const float* __restrict__ B,
                                               const float* __restrict__ Q,
                                               float* __restrict__ D,
                                               int kc) {
    __shared__ __align__(16) float As[32][68];
    __shared__ __align__(16) float Bs[32][64];
    int t = threadIdx.x;
    int m0 = blockIdx.y * 64, n0 = blockIdx.x * 64;
    unsigned long long acc2[4][2] = {};

    for (int kt = 0; kt < NP; kt += 32) {
#pragma unroll
        for (int l = 0; l < 2; l++) {
            int f = t + l * 256;
            int row = f >> 3, kq = f & 7;
            float4 v = *(const float4*)(A + (size_t)(m0 + row) * NP + kt + kq * 4);
            As[kq * 4 + 0][row] = v.x;
            As[kq * 4 + 1][row] = v.y;
            As[kq * 4 + 2][row] = v.z;
            As[kq * 4 + 3][row] = v.w;
        }
#pragma unroll
        for (int l = 0; l < 2; l++) {
            int f = t + l * 256;
            int row = f >> 4, nq = f & 15;
            *(float4*)&Bs[row][nq * 4] =
                *(const float4*)(B + (size_t)(kt + row) * NP + n0 + nq * 4);
        }
        __syncthreads();
        int tm = (t >> 4) * 4, tn = (t & 15) * 4;
#pragma unroll
        for (int kk = 0; kk < 32; kk++) {
            float4 a = *(const float4*)&As[kk][tm];
            ulonglong2 b = *(const ulonglong2*)&Bs[kk][tn];
            float av[4] = {a.x, a.y, a.z, a.w};
#pragma unroll
            for (int r = 0; r < 4; r++) {
                unsigned long long ap = splat2(av[r]);
                fma2(acc2[r][0], ap, b.x);
                fma2(acc2[r][1], ap, b.y);
            }
        }
        __syncthreads();
    }

    int tm = (t >> 4) * 4, tn = (t & 15) * 4;
    float ck = (MODE == 0) ? g_coef[kc] : 0.f;
#pragma unroll
    for (int r = 0; r < 4; r++) {
        float2 p0 = unpack2(acc2[r][0]);
        float2 p1 = unpack2(acc2[r][1]);
        float vals[4] = {p0.x, p0.y, p1.x, p1.y};
#pragma unroll
        for (int c = 0; c < 4; c++) {
            int idx = (m0 + tm + r) * NP + (n0 + tn + c);
            float v = vals[c];
            if (MODE == 0) {
                v = 2.f * v - Q[idx];
                D[idx] = v;
                g_W[idx] += ck * v;
            } else {
                D[idx] = v;
            }
        }
    }
}

// ---------------- bf16 hi/lo conversion + tile packing ----------------
__global__ void k_convW() {
    int i = blockIdx.x * blockDim.x + threadIdx.x;
    if (i >= NSCALE * NP * NP) return;
    int s = i >> 18;
    int m = (i >> 9) & 511;
    int k = i & 511;
    float v = g_W[i];
    __nv_bfloat16 h = __float2bfloat16(v);
    __nv_bfloat16 l = __float2bfloat16(v - __bfloat162float(h));
    int tile = ((s * 4 + (m >> 7)) * 8) + (k >> 6);
    int off = (m & 127) * 128 + (k & 63) * 2;
    off ^= (off >> 3) & 0x70;
    int idx = tile * 8192 + (off >> 1);
    g_Ah[idx] = h;
    g_Al[idx] = l;
}

__global__ void __launch_bounds__(256) k_convX(const float* __restrict__ x) {
    __shared__ float t[32][132];
    int nt = blockIdx.x;          // 0..255 (n tile of 128)
    int kb = blockIdx.y;          // 0..15  (32 k-rows each)
    int tid = threadIdx.x;

#pragma unroll
    for (int it = 0; it < 4; it++) {
        int f = tid + it * 256;
        int row = f >> 5, c4 = f & 31;
        int kg = kb * 32 + row;
        float4 v = make_float4(0.f, 0.f, 0.f, 0.f);
        if (kg < NNODES)
            v = *(const float4*)(x + (size_t)kg * NFEAT + nt * 128 + c4 * 4);
        t[row][c4 * 4 + 0] = v.x;
        t[row][c4 * 4 + 1] = v.y;
        t[row][c4 * 4 + 2] = v.z;
        t[row][c4 * 4 + 3] = v.w;
    }
    __syncthreads();

    size_t tile_bytes = (size_t)(nt * 8 + (kb >> 1)) * 16384;
    int halfk = (kb & 1) * 32;
    char* bh = (char*)g_Bh + tile_bytes;
    char* bl = (char*)g_Bl + tile_bytes;

#pragma unroll
    for (int it = 0; it < 2; it++) {
        int j = tid + it * 256;
        int n = j >> 2, q = j & 3;
        __align__(16) __nv_bfloat16 hs[8];
        __align__(16) __nv_bfloat16 ls[8];
#pragma unroll
        for (int e = 0; e < 8; e++) {
            float v = t[q * 8 + e][n];
            __nv_bfloat16 h = __float2bfloat16(v);
            hs[e] = h;
            ls[e] = __float2bfloat16(v - __bfloat162float(h));
        }
        int off = n * 128 + (halfk + q * 8) * 2;
        off ^= (off >> 3) & 0x70;
        *(uint4*)(bh + off) = *(const uint4*)hs;
        *(uint4*)(bl + off) = *(const uint4*)ls;
    }
}

// ---------------- HMMA helpers ----------------
__device__ __forceinline__ void ldmx4(uint32_t* r, uint32_t addr) {
    asm volatile("ldmatrix.sync.aligned.m8n8.x4.shared.b16 {%0,%1,%2,%3}, [%4];"
                 : "=r"(r[0]), "=r"(r[1]), "=r"(r[2]), "=r"(r[3]) : "r"(addr));
}
__device__ __forceinline__ void mma16816(float* c, const uint32_t* a,
                                         const uint32_t* b) {
    asm volatile(
        "mma.sync.aligned.m16n8k16.row.col.f32.bf16.bf16.f32 "
        "{%0,%1,%2,%3}, {%4,%5,%6,%7}, {%8,%9}, {%0,%1,%2,%3};"
        : "+f"(c[0]), "+f"(c[1]), "+f"(c[2]), "+f"(c[3])
        : "r"(a[0]), "r"(a[1]), "r"(a[2]), "r"(a[3]), "r"(b[0]), "r"(b[1]));
}
__device__ __forceinline__ void cpasync16(uint32_t dst, const void* src) {
    asm volatile("cp.async.cg.shared.global [%0], [%1], 16;"
                 :: "r"(dst), "l"(src) : "memory");
}

// ---------------- big GEMM: out[s] = W_s @ x via HMMA 3-term bf16 ---------
// CTA tile 128m x 256n, K chunks of 64, 8 warps as 2m x 4n (warp tile 64x64)
#define STAGE_BYTES 98304
#define DSMEM_TOTAL (2 * STAGE_BYTES)

__global__ void __launch_bounds__(256, 1) k_bigmma(float* __restrict__ out) {
    extern __shared__ __align__(1024) char smem[];
    uint32_t sb = (uint32_t)__cvta_generic_to_shared(smem);
    int tid = threadIdx.x, wid = tid >> 5, lid = tid & 31;
    int mt = blockIdx.x & 3, s = blockIdx.x >> 2, nt = blockIdx.y;
    int wm0 = (wid >> 2) * 64;    // 2 warp rows (m)
    int wn0 = (wid & 3) * 64;     // 4 warp cols (n)

    const char* pAh = (const char*)(g_Ah + ((size_t)((s * 4 + mt) * 8)) * 8192);
    const char* pAl = (const char*)(g_Al + ((size_t)((s * 4 + mt) * 8)) * 8192);

    float acc[4][8][4] = {};

    auto issue = [&](int c, int buf) {
        uint32_t dst = sb + buf * STAGE_BYTES;
        size_t aoff = (size_t)c * 16384;
#pragma unroll
        for (int it = 0; it < 4; it++) {
            uint32_t o = (uint32_t)(tid + it * 256) * 16;
            cpasync16(dst + o,         pAh + aoff + o);
            cpasync16(dst + 16384 + o, pAl + aoff + o);
        }
#pragma unroll
        for (int it = 0; it < 8; it++) {
            int line = tid + it * 256;           // 0..2047
            int t0 = line >> 10;                 // which of the 2 B tiles
            uint32_t o = (uint32_t)(line & 1023) * 16;
            size_t src = ((size_t)((nt * 2 + t0) * 8 + c)) * 16384 + o;
            uint32_t so = (uint32_t)line * 16;
            cpasync16(dst + 32768 + so, (const char*)g_Bh + src);
            cpasync16(dst + 65536 + so, (const char*)g_Bl + src);
        }
    };

    issue(0, 0);
    asm volatile("cp.async.commit_group;");
    issue(1, 1);
    asm volatile("cp.async.commit_group;");

    for (int c = 0; c < 8; c++) {
        asm volatile("cp.async.wait_group 1;");
        __syncthreads();

        uint32_t base = sb + (c & 1) * STAGE_BYTES;
        uint32_t sAh = base, sAl = base + 16384;
        uint32_t sBh = base + 32768, sBl = base + 65536;

#pragma unroll
        for (int kk = 0; kk < 4; kk++) {
            uint32_t ah[4][4], al[4][4], bh[4][4], bl[4][4];
#pragma unroll
            for (int i = 0; i < 4; i++) {
                uint32_t off = (uint32_t)(wm0 + i * 16 + (lid & 15)) * 128 +
                               kk * 32 + (lid >> 4) * 16;
                off ^= (off >> 3) & 0x70;
                ldmx4(ah[i], sAh + off);
                ldmx4(al[i], sAl + off);
            }
#pragma unroll
            for (int g = 0; g < 4; g++) {
                int nl = wn0 + g * 16 + ((lid >> 4) & 1) * 8 + (lid & 7);
                uint32_t off = (uint32_t)(nl & 127) * 128 +
                               kk * 32 + ((lid >> 3) & 1) * 16;
                off ^= (off >> 3) & 0x70;
                uint32_t toff = (uint32_t)(nl >> 7) * 16384;
                ldmx4(bh[g], sBh + toff + off);
                ldmx4(bl[g], sBl + toff + off);
            }
#pragma unroll
            for (int i = 0; i < 4; i++) {
#pragma unroll
                for (int j = 0; j < 8; j++) {
                    int g = j >> 1, h = (j & 1) * 2;
                    mma16816(acc[i][j], ah[i], &bh[g][h]);
                    mma16816(acc[i][j], ah[i], &bl[g][h]);
                    mma16816(acc[i][j], al[i], &bh[g][h]);
                }
            }
        }
        __syncthreads();
        if (c + 2 < 8) issue(c + 2, c & 1);
        asm volatile("cp.async.commit_group;");
    }

    // epilogue
    int qrow = lid >> 2, qcol = (lid & 3) * 2;
#pragma unroll
    for (int i = 0; i < 4; i++) {
        int m0g = mt * 128 + wm0 + i * 16 + qrow;
#pragma unroll
        for (int j = 0; j < 8; j++) {
            int n = nt * 256 + wn0 + j * 8 + qcol;
            if (m0g < NNODES) {
                size_t idx = ((size_t)s * NNODES + m0g) * NFEAT + n;
                *(float2*)(out + idx) = make_float2(acc[i][j][0], acc[i][j][1]);
            }
            if (m0g + 8 < NNODES) {
                size_t idx = ((size_t)s * NNODES + m0g + 8) * NFEAT + n;
                *(float2*)(out + idx) = make_float2(acc[i][j][2], acc[i][j][3]);
            }
        }
    }
}

// ---------------- launch ----------------
extern "C" void kernel_launch(void* const* d_in, const int* in_sizes, int n_in,
                              void* d_out, int out_size) {
    const float* x      = (const float*)d_in[0];
    const int*   ei     = (const int*)d_in[1];
    const float* scales = (const float*)d_in[2];
    float* out = (float*)d_out;

    float *pM, *pTa, *pTb, *pTc, *pW;
    cudaGetSymbolAddress((void**)&pM,  g_M);
    cudaGetSymbolAddress((void**)&pTa, g_Ta);
    cudaGetSymbolAddress((void**)&pTb, g_Tb);
    cudaGetSymbolAddress((void**)&pTc, g_Tc);
    cudaGetSymbolAddress((void**)&pW,  g_W);

    static int smem_set = 0;
    if (!smem_set) {
        cudaFuncSetAttribute(k_bigmma, cudaFuncAttributeMaxDynamicSharedMemorySize,
                             DSMEM_TOTAL);
        smem_set = 1;
    }

    k_zero<<<(NP * NP + 255) / 256, 256>>>();
    k_degree<<<(NEDGE + 255) / 256, 256>>>(ei);
    k_dinv<<<(NP + 255) / 256, 256>>>();
    k_adj<<<(NEDGE + 255) / 256, 256>>>(ei);
    k_diag<<<(NNODES + 255) / 256, 256>>>();
    k_gersh<<<1, 512>>>();
    k_coef<<<1, 32>>>(scales);
    k_scaleM_initT<<<(NP * NP + 255) / 256, 256>>>();

    dim3 gx(256, 16);
    k_convX<<<gx, 256>>>(x);

    float* T[3] = {pTa, pTb, pTc};
    int pp = 0, pv = 1, ot = 2;
    dim3 gs(8, 8);
    for (int k = 2; k <= CHEB_DEG; k++) {
        k_small<0><<<gs, 256>>>(pM, T[pv], T[pp], T[ot], k);
        int tmp = pp; pp = pv; pv = ot; ot = tmp;
    }

    for (int j = 0; j < 3; j++) {
        k_small<1><<<gs, 256>>>(pW + (size_t)j * NP * NP,
                                pW + (size_t)j * NP * NP,
                                pW + (size_t)j * NP * NP,
                                pW + (size_t)(j + 1) * NP * NP, 0);
    }

    k_convW<<<(NSCALE * NP * NP + 255) / 256, 256>>>();

    // big HMMA GEMM: blockIdx.x = mt + 4*s (16), blockIdx.y = n tile of 256 (128)
    dim3 gb(16, 128);
    k_bigmma<<<gb, 256, DSMEM_TOTAL>>>(out);
}

// round 5
// speedup vs baseline: 2.2709x; 1.2613x over previous
#include <cuda_runtime.h>
#include <cuda_fp16.h>
#include <math.h>
#include <stdint.h>

#define NNODES 500
#define NP     512
#define NFEAT  32768
#define NEDGE  16000
#define NSCALE 4
#define CHEB_DEG 6
#define NCOEF (CHEB_DEG + 1)
#define DCTN 128

// ---------------- device scratch (static, allocation-free) ----------------
__device__ float g_M [NP * NP];
__device__ float g_Ta[NP * NP];
__device__ float g_Tb[NP * NP];
__device__ float g_Tc[NP * NP];
__device__ float g_W [NSCALE * NP * NP];   // slots: 0.5, 1, 2, 4 (slot3 temp=0.25)
__device__ float g_deg [NP];
__device__ float g_dinv[NP];
__device__ float g_c0h[2];
__device__ float g_coef[NCOEF];

// Packed, pre-swizzled (SW128) fp16 operand tiles for the HMMA big GEMM.
// A (W): [scale][m_tile(4)][k_chunk(8)] tiles of 128m x 64k (16KB each), hi+lo
// B (xT): [n_tile(256)][k_chunk(8)] tiles of 128n x 64k (16KB each), hi only
__device__ __half g_Ah[NSCALE * 4 * 8 * 8192];
__device__ __half g_Al[NSCALE * 4 * 8 * 8192];
__device__ __half g_Bh[256 * 8 * 8192];

// ---------------- packed f32x2 helpers ----------------
__device__ __forceinline__ void fma2(unsigned long long &d,
                                     unsigned long long a,
                                     unsigned long long b) {
    asm("fma.rn.f32x2 %0, %1, %2, %0;" : "+l"(d) : "l"(a), "l"(b));
}
__device__ __forceinline__ unsigned long long splat2(float a) {
    unsigned long long r;
    unsigned int ai = __float_as_uint(a);
    asm("mov.b64 %0, {%1, %1};" : "=l"(r) : "r"(ai));
    return r;
}
__device__ __forceinline__ float2 unpack2(unsigned long long v) {
    unsigned int lo, hi;
    asm("mov.b64 {%0, %1}, %2;" : "=r"(lo), "=r"(hi) : "l"(v));
    float2 f;
    f.x = __uint_as_float(lo);
    f.y = __uint_as_float(hi);
    return f;
}

// ---------------- graph / Laplacian build ----------------
__global__ void k_zero() {
    int i = blockIdx.x * blockDim.x + threadIdx.x;
    if (i < NP * NP) g_M[i] = 0.f;
    if (i < NP) g_deg[i] = 0.f;
}

__global__ void k_degree(const int* __restrict__ ei) {
    int e = blockIdx.x * blockDim.x + threadIdx.x;
    if (e < NEDGE) atomicAdd(&g_deg[ei[NEDGE + e]], 1.0f);
}

__global__ void k_dinv() {
    int i = blockIdx.x * blockDim.x + threadIdx.x;
    if (i < NP) g_dinv[i] = (i < NNODES) ? rsqrtf(fmaxf(g_deg[i], 1.0f)) : 0.f;
}

__global__ void k_adj(const int* __restrict__ ei) {
    int e = blockIdx.x * blockDim.x + threadIdx.x;
    if (e < NEDGE) {
        int s = ei[e], d = ei[NEDGE + e];
        float v = -g_dinv[s] * g_dinv[d];
        g_M[s * NP + d] = v;
        g_M[d * NP + s] = v;
    }
}

__global__ void k_diag() {
    int i = blockIdx.x * blockDim.x + threadIdx.x;
    if (i < NNODES) g_M[i * NP + i] += 1.0f;
}

__global__ void k_gersh() {
    __shared__ float slo[512], shi[512];
    int i = threadIdx.x;
    float c = g_M[i * NP + i];
    float r = 0.f;
    for (int j = 0; j < NP; j++) r += fabsf(g_M[i * NP + j]);
    r -= fabsf(c);
    slo[i] = c - r;
    shi[i] = c + r;
    __syncthreads();
    for (int s = 256; s > 0; s >>= 1) {
        if (i < s) {
            slo[i] = fminf(slo[i], slo[i + s]);
            shi[i] = fmaxf(shi[i], shi[i + s]);
        }
        __syncthreads();
    }
    if (i == 0) {
        float lo = slo[0], hi = shi[0];
        float c0 = 0.5f * (hi + lo);
        float h  = 0.5f * (hi - lo);
        h = fmaxf(h, 1e-4f) * 1.0001f;
        g_c0h[0] = c0;
        g_c0h[1] = h;
    }
}

// Chebyshev coefs of exp(-(s0/2)(c0 + h t)) on [-1,1] (for W(0.25) when s0=0.5)
__global__ void k_coef(const float* __restrict__ scales) {
    int k = threadIdx.x;
    if (k < NCOEF) {
        const double PI = 3.14159265358979323846;
        double s0 = 0.5 * (double)scales[0];
        double c0 = (double)g_c0h[0];
        double h  = (double)g_c0h[1];
        double acc = 0.0;
        for (int j = 0; j < DCTN; j++) {
            double th = PI * (j + 0.5) / (double)DCTN;
            double f  = exp(-s0 * (c0 + h * cos(th)));
            acc += f * cos((double)k * th);
        }
        g_coef[k] = (float)(acc * ((k == 0) ? 1.0 : 2.0) / (double)DCTN);
    }
}

// M = (L - c0 I)/h; T0 = I, T1 = M; W(0.25) accumulator (slot 3) = c0 I + c1 M
__global__ void k_scaleM_initT() {
    int i = blockIdx.x * blockDim.x + threadIdx.x;
    if (i < NP * NP) {
        int r = i >> 9, c = i & (NP - 1);
        float c0 = g_c0h[0], h = g_c0h[1];
        float diag = (r == c) ? 1.f : 0.f;
        float m = (g_M[i] - c0 * diag) / h;
        g_M[i]  = m;
        g_Ta[i] = diag;
        g_Tb[i] = m;
        g_W[3 * NP * NP + i] = g_coef[0] * diag + g_coef[1] * m;
    }
}

// ---------------- small 512x512x512 SGEMM (Chebyshev chain + squaring) ----
template <int MODE>
__global__ void __launch_bounds__(256) k_small(const float* __restrict__ A,
                                               const float* __restrict__ B,
                                               const float* __restrict__ Q,
                                               float* __restrict__ D,
                                               float* __restrict__ Wacc,
                                               int kc) {
    __shared__ __align__(16) float As[32][68];
    __shared__ __align__(16) float Bs[32][64];
    int t = threadIdx.x;
    int m0 = blockIdx.y * 64, n0 = blockIdx.x * 64;
    unsigned long long acc2[4][2] = {};

    for (int kt = 0; kt < NP; kt += 32) {
#pragma unroll
        for (int l = 0; l < 2; l++) {
            int f = t + l * 256;
            int row = f >> 3, kq = f & 7;
            float4 v = *(const float4*)(A + (size_t)(m0 + row) * NP + kt + kq * 4);
            As[kq * 4 + 0][row] = v.x;
            As[kq * 4 + 1][row] = v.y;
            As[kq * 4 + 2][row] = v.z;
            As[kq * 4 + 3][row] = v.w;
        }
#pragma unroll
        for (int l = 0; l < 2; l++) {
            int f = t + l * 256;
            int row = f >> 4, nq = f & 15;
            *(float4*)&Bs[row][nq * 4] =
                *(const float4*)(B + (size_t)(kt + row) * NP + n0 + nq * 4);
        }
        __syncthreads();
        int tm = (t >> 4) * 4, tn = (t & 15) * 4;
#pragma unroll
        for (int kk = 0; kk < 32; kk++) {
            float4 a = *(const float4*)&As[kk][tm];
            ulonglong2 b = *(const ulonglong2*)&Bs[kk][tn];
            float av[4] = {a.x, a.y, a.z, a.w};
#pragma unroll
            for (int r = 0; r < 4; r++) {
                unsigned long long ap = splat2(av[r]);
                fma2(acc2[r][0], ap, b.x);
                fma2(acc2[r][1], ap, b.y);
            }
        }
        __syncthreads();
    }

    int tm = (t >> 4) * 4, tn = (t & 15) * 4;
    float ck = (MODE == 0) ? g_coef[kc] : 0.f;
#pragma unroll
    for (int r = 0; r < 4; r++) {
        float2 p0 = unpack2(acc2[r][0]);
        float2 p1 = unpack2(acc2[r][1]);
        float vals[4] = {p0.x, p0.y, p1.x, p1.y};
#pragma unroll
        for (int c = 0; c < 4; c++) {
            int idx = (m0 + tm + r) * NP + (n0 + tn + c);
            float v = vals[c];
            if (MODE == 0) {
                v = 2.f * v - Q[idx];
                D[idx] = v;
                Wacc[idx] += ck * v;
            } else {
                D[idx] = v;
            }
        }
    }
}

// ---------------- fp16 hi/lo conversion + tile packing ----------------
__global__ void k_convW() {
    int i = blockIdx.x * blockDim.x + threadIdx.x;
    if (i >= NSCALE * NP * NP) return;
    int s = i >> 18;
    int m = (i >> 9) & 511;
    int k = i & 511;
    float v = g_W[i];
    __half h = __float2half(v);
    __half l = __float2half(v - __half2float(h));
    int tile = ((s * 4 + (m >> 7)) * 8) + (k >> 6);
    int off = (m & 127) * 128 + (k & 63) * 2;
    off ^= (off >> 3) & 0x70;
    int idx = tile * 8192 + (off >> 1);
    g_Ah[idx] = h;
    g_Al[idx] = l;
}

__global__ void __launch_bounds__(256) k_convX(const float* __restrict__ x) {
    __shared__ float t[32][132];
    int nt = blockIdx.x;          // 0..255 (n tile of 128)
    int kb = blockIdx.y;          // 0..15  (32 k-rows each)
    int tid = threadIdx.x;

#pragma unroll
    for (int it = 0; it < 4; it++) {
        int f = tid + it * 256;
        int row = f >> 5, c4 = f & 31;
        int kg = kb * 32 + row;
        float4 v = make_float4(0.f, 0.f, 0.f, 0.f);
        if (kg < NNODES)
            v = *(const float4*)(x + (size_t)kg * NFEAT + nt * 128 + c4 * 4);
        t[row][c4 * 4 + 0] = v.x;
        t[row][c4 * 4 + 1] = v.y;
        t[row][c4 * 4 + 2] = v.z;
        t[row][c4 * 4 + 3] = v.w;
    }
    __syncthreads();

    size_t tile_bytes = (size_t)(nt * 8 + (kb >> 1)) * 16384;
    int halfk = (kb & 1) * 32;
    char* bh = (char*)g_Bh + tile_bytes;

#pragma unroll
    for (int it = 0; it < 2; it++) {
        int j = tid + it * 256;
        int n = j >> 2, q = j & 3;
        __align__(16) __half hs[8];
#pragma unroll
        for (int e = 0; e < 8; e++)
            hs[e] = __float2half(t[q * 8 + e][n]);
        int off = n * 128 + (halfk + q * 8) * 2;
        off ^= (off >> 3) & 0x70;
        *(uint4*)(bh + off) = *(const uint4*)hs;
    }
}

// ---------------- HMMA helpers ----------------
__device__ __forceinline__ void ldmx4(uint32_t* r, uint32_t addr) {
    asm volatile("ldmatrix.sync.aligned.m8n8.x4.shared.b16 {%0,%1,%2,%3}, [%4];"
                 : "=r"(r[0]), "=r"(r[1]), "=r"(r[2]), "=r"(r[3]) : "r"(addr));
}
__device__ __forceinline__ void mma16816(float* c, const uint32_t* a,
                                         const uint32_t* b) {
    asm volatile(
        "mma.sync.aligned.m16n8k16.row.col.f32.f16.f16.f32 "
        "{%0,%1,%2,%3}, {%4,%5,%6,%7}, {%8,%9}, {%0,%1,%2,%3};"
        : "+f"(c[0]), "+f"(c[1]), "+f"(c[2]), "+f"(c[3])
        : "r"(a[0]), "r"(a[1]), "r"(a[2]), "r"(a[3]), "r"(b[0]), "r"(b[1]));
}
__device__ __forceinline__ void cpasync16(uint32_t dst, const void* src) {
    asm volatile("cp.async.cg.shared.global [%0], [%1], 16;"
                 :: "r"(dst), "l"(src) : "memory");
}

// ---------------- big GEMM: out[s] = W_s @ x via HMMA 2-term fp16 ---------
// CTA tile 128m x 256n, K chunks of 64, 8 warps as 2m x 4n (warp tile 64x64)
#define STAGE_BYTES 65536
#define DSMEM_TOTAL (2 * STAGE_BYTES)

__global__ void __launch_bounds__(256, 1) k_bigmma(float* __restrict__ out) {
    extern __shared__ __align__(1024) char smem[];
    uint32_t sb = (uint32_t)__cvta_generic_to_shared(smem);
    int tid = threadIdx.x, wid = tid >> 5, lid = tid & 31;
    int mt = blockIdx.x & 3, s = blockIdx.x >> 2, nt = blockIdx.y;
    int wm0 = (wid >> 2) * 64;    // 2 warp rows (m)
    int wn0 = (wid & 3) * 64;     // 4 warp cols (n)

    const char* pAh = (const char*)(g_Ah + ((size_t)((s * 4 + mt) * 8)) * 8192);
    const char* pAl = (const char*)(g_Al + ((size_t)((s * 4 + mt) * 8)) * 8192);

    float acc[4][8][4] = {};

    auto issue = [&](int c, int buf) {
        uint32_t dst = sb + buf * STAGE_BYTES;
        size_t aoff = (size_t)c * 16384;
#pragma unroll
        for (int it = 0; it < 4; it++) {
            uint32_t o = (uint32_t)(tid + it * 256) * 16;
            cpasync16(dst + o,         pAh + aoff + o);
            cpasync16(dst + 16384 + o, pAl + aoff + o);
        }
#pragma unroll
        for (int it = 0; it < 8; it++) {
            int line = tid + it * 256;           // 0..2047
            int t0 = line >> 10;                 // which of the 2 B tiles
            uint32_t o = (uint32_t)(line & 1023) * 16;
            size_t src = ((size_t)((nt * 2 + t0) * 8 + c)) * 16384 + o;
            cpasync16(dst + 32768 + (uint32_t)line * 16, (const char*)g_Bh + src);
        }
    };

    issue(0, 0);
    asm volatile("cp.async.commit_group;");
    issue(1, 1);
    asm volatile("cp.async.commit_group;");

    for (int c = 0; c < 8; c++) {
        asm volatile("cp.async.wait_group 1;");
        __syncthreads();

        uint32_t base = sb + (c & 1) * STAGE_BYTES;
        uint32_t sAh = base, sAl = base + 16384, sBh = base + 32768;

#pragma unroll
        for (int kk = 0; kk < 4; kk++) {
            uint32_t ah[4][4], al[4][4], bh[4][4];
#pragma unroll
            for (int i = 0; i < 4; i++) {
                uint32_t off = (uint32_t)(wm0 + i * 16 + (lid & 15)) * 128 +
                               kk * 32 + (lid >> 4) * 16;
                off ^= (off >> 3) & 0x70;
                ldmx4(ah[i], sAh + off);
                ldmx4(al[i], sAl + off);
            }
#pragma unroll
            for (int g = 0; g < 4; g++) {
                int nl = wn0 + g * 16 + ((lid >> 4) & 1) * 8 + (lid & 7);
                uint32_t off = (uint32_t)(nl & 127) * 128 +
                               kk * 32 + ((lid >> 3) & 1) * 16;
                off ^= (off >> 3) & 0x70;
                uint32_t toff = (uint32_t)(nl >> 7) * 16384;
                ldmx4(bh[g], sBh + toff + off);
            }
#pragma unroll
            for (int i = 0; i < 4; i++) {
#pragma unroll
                for (int j = 0; j < 8; j++) {
                    int g = j >> 1, h = (j & 1) * 2;
                    mma16816(acc[i][j], ah[i], &bh[g][h]);
                    mma16816(acc[i][j], al[i], &bh[g][h]);
                }
            }
        }
        __syncthreads();
        if (c + 2 < 8) issue(c + 2, c & 1);
        asm volatile("cp.async.commit_group;");
    }

    // epilogue
    int qrow = lid >> 2, qcol = (lid & 3) * 2;
#pragma unroll
    for (int i = 0; i < 4; i++) {
        int m0g = mt * 128 + wm0 + i * 16 + qrow;
#pragma unroll
        for (int j = 0; j < 8; j++) {
            int n = nt * 256 + wn0 + j * 8 + qcol;
            if (m0g < NNODES) {
                size_t idx = ((size_t)s * NNODES + m0g) * NFEAT + n;
                *(float2*)(out + idx) = make_float2(acc[i][j][0], acc[i][j][1]);
            }
            if (m0g + 8 < NNODES) {
                size_t idx = ((size_t)s * NNODES + m0g + 8) * NFEAT + n;
                *(float2*)(out + idx) = make_float2(acc[i][j][2], acc[i][j][3]);
            }
        }
    }
}

// ---------------- launch ----------------
extern "C" void kernel_launch(void* const* d_in, const int* in_sizes, int n_in,
                              void* d_out, int out_size) {
    const float* x      = (const float*)d_in[0];
    const int*   ei     = (const int*)d_in[1];
    const float* scales = (const float*)d_in[2];
    float* out = (float*)d_out;

    float *pM, *pTa, *pTb, *pTc, *pW;
    cudaGetSymbolAddress((void**)&pM,  g_M);
    cudaGetSymbolAddress((void**)&pTa, g_Ta);
    cudaGetSymbolAddress((void**)&pTb, g_Tb);
    cudaGetSymbolAddress((void**)&pTc, g_Tc);
    cudaGetSymbolAddress((void**)&pW,  g_W);

    static int smem_set = 0;
    if (!smem_set) {
        cudaFuncSetAttribute(k_bigmma, cudaFuncAttributeMaxDynamicSharedMemorySize,
                             DSMEM_TOTAL);
        smem_set = 1;
    }

    const size_t NPNP = (size_t)NP * NP;

    k_zero<<<(NP * NP + 255) / 256, 256>>>();
    k_degree<<<(NEDGE + 255) / 256, 256>>>(ei);
    k_dinv<<<(NP + 255) / 256, 256>>>();
    k_adj<<<(NEDGE + 255) / 256, 256>>>(ei);
    k_diag<<<(NNODES + 255) / 256, 256>>>();
    k_gersh<<<1, 512>>>();
    k_coef<<<1, 32>>>(scales);
    k_scaleM_initT<<<(NP * NP + 255) / 256, 256>>>();

    dim3 gx(256, 16);
    k_convX<<<gx, 256>>>(x);

    // Chebyshev (deg 6) builds W(0.25) in slot 3
    float* T[3] = {pTa, pTb, pTc};
    int pp = 0, pv = 1, ot = 2;
    dim3 gs(8, 8);
    for (int k = 2; k <= CHEB_DEG; k++) {
        k_small<0><<<gs, 256>>>(pM, T[pv], T[pp], T[ot], pW + 3 * NPNP, k);
        int tmp = pp; pp = pv; pv = ot; ot = tmp;
    }

    // Squaring ladder: 0.25 -> 0.5 -> 1 -> 2 -> 4 (slots 3 -> 0 -> 1 -> 2 -> 3)
    k_small<1><<<gs, 256>>>(pW + 3 * NPNP, pW + 3 * NPNP, pW, pW + 0 * NPNP, pW, 0);
    k_small<1><<<gs, 256>>>(pW + 0 * NPNP, pW + 0 * NPNP, pW, pW + 1 * NPNP, pW, 0);
    k_small<1><<<gs, 256>>>(pW + 1 * NPNP, pW + 1 * NPNP, pW, pW + 2 * NPNP, pW, 0);
    k_small<1><<<gs, 256>>>(pW + 2 * NPNP, pW + 2 * NPNP, pW, pW + 3 * NPNP, pW, 0);

    k_convW<<<(NSCALE * NP * NP + 255) / 256, 256>>>();

    // big HMMA GEMM: blockIdx.x = mt + 4*s (16), blockIdx.y = n tile of 256 (128)
    dim3 gb(16, 128);
    k_bigmma<<<gb, 256, DSMEM_TOTAL>>>(out);
}

// round 6
// speedup vs baseline: 4.3669x; 1.9230x over previous
#include <cuda_runtime.h>
#include <cuda_fp16.h>
#include <math.h>
#include <stdint.h>

#define NNODES 500
#define NP     512
#define NFEAT  32768
#define NEDGE  16000
#define NSCALE 4
#define CHEB_DEG 6
#define NCOEF (CHEB_DEG + 1)
#define DCTN 128

// ---------------- device scratch (static, allocation-free) ----------------
__device__ float g_M [NP * NP];
__device__ float g_Ta[NP * NP];
__device__ float g_Tb[NP * NP];
__device__ float g_Tc[NP * NP];
__device__ float g_W [NSCALE * NP * NP];   // slots: 0.5, 1, 2, 4 (slot3 temp=0.25)
__device__ float g_deg [NP];
__device__ float g_dinv[NP];
__device__ float g_c0h[2];
__device__ float g_coef[NCOEF];

// Packed, pre-swizzled (SW128) fp16 operand tiles for the HMMA big GEMM.
// A (W): [scale][m_tile(4)][k_chunk(8)] tiles of 128m x 64k (16KB each)
// B (xT): [n_tile(256)][k_chunk(8)] tiles of 128n x 64k (16KB each)
__device__ __half g_Ah[NSCALE * 4 * 8 * 8192];
__device__ __half g_Bh[256 * 8 * 8192];

// ---------------- packed f32x2 helpers ----------------
__device__ __forceinline__ void fma2(unsigned long long &d,
                                     unsigned long long a,
                                     unsigned long long b) {
    asm("fma.rn.f32x2 %0, %1, %2, %0;" : "+l"(d) : "l"(a), "l"(b));
}
__device__ __forceinline__ unsigned long long splat2(float a) {
    unsigned long long r;
    unsigned int ai = __float_as_uint(a);
    asm("mov.b64 %0, {%1, %1};" : "=l"(r) : "r"(ai));
    return r;
}
__device__ __forceinline__ float2 unpack2(unsigned long long v) {
    unsigned int lo, hi;
    asm("mov.b64 {%0, %1}, %2;" : "=r"(lo), "=r"(hi) : "l"(v));
    float2 f;
    f.x = __uint_as_float(lo);
    f.y = __uint_as_float(hi);
    return f;
}

// ---------------- graph / Laplacian build ----------------
__global__ void k_zero() {
    int i = blockIdx.x * blockDim.x + threadIdx.x;
    if (i < NP * NP) g_M[i] = 0.f;
    if (i < NP) g_deg[i] = 0.f;
}

__global__ void k_degree(const int* __restrict__ ei) {
    int e = blockIdx.x * blockDim.x + threadIdx.x;
    if (e < NEDGE) atomicAdd(&g_deg[ei[NEDGE + e]], 1.0f);
}

__global__ void k_dinv() {
    int i = blockIdx.x * blockDim.x + threadIdx.x;
    if (i < NP) g_dinv[i] = (i < NNODES) ? rsqrtf(fmaxf(g_deg[i], 1.0f)) : 0.f;
}

__global__ void k_adj(const int* __restrict__ ei) {
    int e = blockIdx.x * blockDim.x + threadIdx.x;
    if (e < NEDGE) {
        int s = ei[e], d = ei[NEDGE + e];
        float v = -g_dinv[s] * g_dinv[d];
        g_M[s * NP + d] = v;
        g_M[d * NP + s] = v;
    }
}

__global__ void k_diag() {
    int i = blockIdx.x * blockDim.x + threadIdx.x;
    if (i < NNODES) g_M[i * NP + i] += 1.0f;
}

__global__ void k_gersh() {
    __shared__ float slo[512], shi[512];
    int i = threadIdx.x;
    float c = g_M[i * NP + i];
    float r = 0.f;
    const float4* row = (const float4*)(g_M + i * NP);
#pragma unroll 4
    for (int j = 0; j < NP / 4; j++) {
        float4 v = row[j];
        r += fabsf(v.x) + fabsf(v.y) + fabsf(v.z) + fabsf(v.w);
    }
    r -= fabsf(c);
    slo[i] = c - r;
    shi[i] = c + r;
    __syncthreads();
    for (int s = 256; s > 0; s >>= 1) {
        if (i < s) {
            slo[i] = fminf(slo[i], slo[i + s]);
            shi[i] = fmaxf(shi[i], shi[i + s]);
        }
        __syncthreads();
    }
    if (i == 0) {
        float lo = slo[0], hi = shi[0];
        float c0 = 0.5f * (hi + lo);
        float h  = 0.5f * (hi - lo);
        h = fmaxf(h, 1e-4f) * 1.0001f;
        g_c0h[0] = c0;
        g_c0h[1] = h;
    }
}

// Chebyshev coefs of exp(-(s0/2)(c0 + h t)) on [-1,1] (for W(0.25) when s0=0.5)
// Parallel DCT: one block per coefficient k, one thread per quadrature node j.
__global__ void k_coef(const float* __restrict__ scales) {
    __shared__ double red[DCTN];
    int k = blockIdx.x;
    int j = threadIdx.x;
    const double PI = 3.14159265358979323846;
    double s0 = 0.5 * (double)scales[0];
    double c0 = (double)g_c0h[0];
    double h  = (double)g_c0h[1];
    double th = PI * (j + 0.5) / (double)DCTN;
    red[j] = exp(-s0 * (c0 + h * cos(th))) * cos((double)k * th);
    __syncthreads();
    for (int s = DCTN / 2; s > 0; s >>= 1) {
        if (j < s) red[j] += red[j + s];
        __syncthreads();
    }
    if (j == 0)
        g_coef[k] = (float)(red[0] * ((k == 0) ? 1.0 : 2.0) / (double)DCTN);
}

// M = (L - c0 I)/h; T0 = I, T1 = M; W(0.25) accumulator (slot 3) = c0 I + c1 M
__global__ void k_scaleM_initT() {
    int i = blockIdx.x * blockDim.x + threadIdx.x;
    if (i < NP * NP) {
        int r = i >> 9, c = i & (NP - 1);
        float c0 = g_c0h[0], h = g_c0h[1];
        float diag = (r == c) ? 1.f : 0.f;
        float m = (g_M[i] - c0 * diag) / h;
        g_M[i]  = m;
        g_Ta[i] = diag;
        g_Tb[i] = m;
        g_W[3 * NP * NP + i] = g_coef[0] * diag + g_coef[1] * m;
    }
}

// ---------------- small 512x512x512 SGEMM (Chebyshev chain + squaring) ----
template <int MODE>
__global__ void __launch_bounds__(256) k_small(const float* __restrict__ A,
                                               const float* __restrict__ B,
                                               const float* __restrict__ Q,
                                               float* __restrict__ D,
                                               float* __restrict__ Wacc,
                                               int kc) {
    __shared__ __align__(16) float As[32][68];
    __shared__ __align__(16) float Bs[32][64];
    int t = threadIdx.x;
    int m0 = blockIdx.y * 64, n0 = blockIdx.x * 64;
    unsigned long long acc2[4][2] = {};

    for (int kt = 0; kt < NP; kt += 32) {
#pragma unroll
        for (int l = 0; l < 2; l++) {
            int f = t + l * 256;
            int row = f >> 3, kq = f & 7;
            float4 v = *(const float4*)(A + (size_t)(m0 + row) * NP + kt + kq * 4);
            As[kq * 4 + 0][row] = v.x;
            As[kq * 4 + 1][row] = v.y;
            As[kq * 4 + 2][row] = v.z;
            As[kq * 4 + 3][row] = v.w;
        }
#pragma unroll
        for (int l = 0; l < 2; l++) {
            int f = t + l * 256;
            int row = f >> 4, nq = f & 15;
            *(float4*)&Bs[row][nq * 4] =
                *(const float4*)(B + (size_t)(kt + row) * NP + n0 + nq * 4);
        }
        __syncthreads();
        int tm = (t >> 4) * 4, tn = (t & 15) * 4;
#pragma unroll
        for (int kk = 0; kk < 32; kk++) {
            float4 a = *(const float4*)&As[kk][tm];
            ulonglong2 b = *(const ulonglong2*)&Bs[kk][tn];
            float av[4] = {a.x, a.y, a.z, a.w};
#pragma unroll
            for (int r = 0; r < 4; r++) {
                unsigned long long ap = splat2(av[r]);
                fma2(acc2[r][0], ap, b.x);
                fma2(acc2[r][1], ap, b.y);
            }
        }
        __syncthreads();
    }

    int tm = (t >> 4) * 4, tn = (t & 15) * 4;
    float ck = (MODE == 0) ? g_coef[kc] : 0.f;
#pragma unroll
    for (int r = 0; r < 4; r++) {
        float2 p0 = unpack2(acc2[r][0]);
        float2 p1 = unpack2(acc2[r][1]);
        float vals[4] = {p0.x, p0.y, p1.x, p1.y};
#pragma unroll
        for (int c = 0; c < 4; c++) {
            int idx = (m0 + tm + r) * NP + (n0 + tn + c);
            float v = vals[c];
            if (MODE == 0) {
                v = 2.f * v - Q[idx];
                D[idx] = v;
                Wacc[idx] += ck * v;
            } else {
                D[idx] = v;
            }
        }
    }
}

// ---------------- fp16 conversion + tile packing ----------------
__global__ void k_convW() {
    int i = blockIdx.x * blockDim.x + threadIdx.x;
    if (i >= NSCALE * NP * NP) return;
    int s = i >> 18;
    int m = (i >> 9) & 511;
    int k = i & 511;
    float v = g_W[i];
    int tile = ((s * 4 + (m >> 7)) * 8) + (k >> 6);
    int off = (m & 127) * 128 + (k & 63) * 2;
    off ^= (off >> 3) & 0x70;
    g_Ah[tile * 8192 + (off >> 1)] = __float2half(v);
}

__global__ void __launch_bounds__(256) k_convX(const float* __restrict__ x) {
    __shared__ float t[32][132];
    int nt = blockIdx.x;          // 0..255 (n tile of 128)
    int kb = blockIdx.y;          // 0..15  (32 k-rows each)
    int tid = threadIdx.x;

#pragma unroll
    for (int it = 0; it < 4; it++) {
        int f = tid + it * 256;
        int row = f >> 5, c4 = f & 31;
        int kg = kb * 32 + row;
        float4 v = make_float4(0.f, 0.f, 0.f, 0.f);
        if (kg < NNODES)
            v = *(const float4*)(x + (size_t)kg * NFEAT + nt * 128 + c4 * 4);
        t[row][c4 * 4 + 0] = v.x;
        t[row][c4 * 4 + 1] = v.y;
        t[row][c4 * 4 + 2] = v.z;
        t[row][c4 * 4 + 3] = v.w;
    }
    __syncthreads();

    size_t tile_bytes = (size_t)(nt * 8 + (kb >> 1)) * 16384;
    int halfk = (kb & 1) * 32;
    char* bh = (char*)g_Bh + tile_bytes;

#pragma unroll
    for (int it = 0; it < 2; it++) {
        int j = tid + it * 256;
        int n = j >> 2, q = j & 3;
        __align__(16) __half hs[8];
#pragma unroll
        for (int e = 0; e < 8; e++)
            hs[e] = __float2half(t[q * 8 + e][n]);
        int off = n * 128 + (halfk + q * 8) * 2;
        off ^= (off >> 3) & 0x70;
        *(uint4*)(bh + off) = *(const uint4*)hs;
    }
}

// ---------------- HMMA helpers ----------------
__device__ __forceinline__ void ldmx4(uint32_t* r, uint32_t addr) {
    asm volatile("ldmatrix.sync.aligned.m8n8.x4.shared.b16 {%0,%1,%2,%3}, [%4];"
                 : "=r"(r[0]), "=r"(r[1]), "=r"(r[2]), "=r"(r[3]) : "r"(addr));
}
__device__ __forceinline__ void mma16816(float* c, const uint32_t* a,
                                         const uint32_t* b) {
    asm volatile(
        "mma.sync.aligned.m16n8k16.row.col.f32.f16.f16.f32 "
        "{%0,%1,%2,%3}, {%4,%5,%6,%7}, {%8,%9}, {%0,%1,%2,%3};"
        : "+f"(c[0]), "+f"(c[1]), "+f"(c[2]), "+f"(c[3])
        : "r"(a[0]), "r"(a[1]), "r"(a[2]), "r"(a[3]), "r"(b[0]), "r"(b[1]));
}
__device__ __forceinline__ void cpasync16(uint32_t dst, const void* src) {
    asm volatile("cp.async.cg.shared.global [%0], [%1], 16;"
                 :: "r"(dst), "l"(src) : "memory");
}

// ---------------- big GEMM: out[s] = W_s @ x via HMMA fp16 ----------------
// CTA tile 128m x 256n, K chunks of 64, 8 warps as 2m x 4n (warp tile 64x64)
#define STAGE_BYTES 49152
#define DSMEM_TOTAL (2 * STAGE_BYTES)

__global__ void __launch_bounds__(256, 1) k_bigmma(float* __restrict__ out) {
    extern __shared__ __align__(1024) char smem[];
    uint32_t sb = (uint32_t)__cvta_generic_to_shared(smem);
    int tid = threadIdx.x, wid = tid >> 5, lid = tid & 31;
    int mt = blockIdx.x & 3, s = blockIdx.x >> 2, nt = blockIdx.y;
    int wm0 = (wid >> 2) * 64;    // 2 warp rows (m)
    int wn0 = (wid & 3) * 64;     // 4 warp cols (n)

    const char* pAh = (const char*)(g_Ah + ((size_t)((s * 4 + mt) * 8)) * 8192);

    float acc[4][8][4] = {};

    auto issue = [&](int c, int buf) {
        uint32_t dst = sb + buf * STAGE_BYTES;
        size_t aoff = (size_t)c * 16384;
#pragma unroll
        for (int it = 0; it < 4; it++) {
            uint32_t o = (uint32_t)(tid + it * 256) * 16;
            cpasync16(dst + o, pAh + aoff + o);
        }
#pragma unroll
        for (int it = 0; it < 8; it++) {
            int line = tid + it * 256;           // 0..2047
            int t0 = line >> 10;                 // which of the 2 B tiles
            uint32_t o = (uint32_t)(line & 1023) * 16;
            size_t src = ((size_t)((nt * 2 + t0) * 8 + c)) * 16384 + o;
            cpasync16(dst + 16384 + (uint32_t)line * 16, (const char*)g_Bh + src);
        }
    };

    issue(0, 0);
    asm volatile("cp.async.commit_group;");
    issue(1, 1);
    asm volatile("cp.async.commit_group;");

    for (int c = 0; c < 8; c++) {
        asm volatile("cp.async.wait_group 1;");
        __syncthreads();

        uint32_t base = sb + (c & 1) * STAGE_BYTES;
        uint32_t sAh = base, sBh = base + 16384;

#pragma unroll
        for (int kk = 0; kk < 4; kk++) {
            uint32_t ah[4][4], bh[4][4];
#pragma unroll
            for (int i = 0; i < 4; i++) {
                uint32_t off = (uint32_t)(wm0 + i * 16 + (lid & 15)) * 128 +
                               kk * 32 + (lid >> 4) * 16;
                off ^= (off >> 3) & 0x70;
                ldmx4(ah[i], sAh + off);
            }
#pragma unroll
            for (int g = 0; g < 4; g++) {
                int nl = wn0 + g * 16 + ((lid >> 4) & 1) * 8 + (lid & 7);
                uint32_t off = (uint32_t)(nl & 127) * 128 +
                               kk * 32 + ((lid >> 3) & 1) * 16;
                off ^= (off >> 3) & 0x70;
                uint32_t toff = (uint32_t)(nl >> 7) * 16384;
                ldmx4(bh[g], sBh + toff + off);
            }
#pragma unroll
            for (int i = 0; i < 4; i++) {
#pragma unroll
                for (int j = 0; j < 8; j++) {
                    int g = j >> 1, h = (j & 1) * 2;
                    mma16816(acc[i][j], ah[i], &bh[g][h]);
                }
            }
        }
        __syncthreads();
        if (c + 2 < 8) issue(c + 2, c & 1);
        asm volatile("cp.async.commit_group;");
    }

    // epilogue
    int qrow = lid >> 2, qcol = (lid & 3) * 2;
#pragma unroll
    for (int i = 0; i < 4; i++) {
        int m0g = mt * 128 + wm0 + i * 16 + qrow;
#pragma unroll
        for (int j = 0; j < 8; j++) {
            int n = nt * 256 + wn0 + j * 8 + qcol;
            if (m0g < NNODES) {
                size_t idx = ((size_t)s * NNODES + m0g) * NFEAT + n;
                *(float2*)(out + idx) = make_float2(acc[i][j][0], acc[i][j][1]);
            }
            if (m0g + 8 < NNODES) {
                size_t idx = ((size_t)s * NNODES + m0g + 8) * NFEAT + n;
                *(float2*)(out + idx) = make_float2(acc[i][j][2], acc[i][j][3]);
            }
        }
    }
}

// ---------------- launch ----------------
extern "C" void kernel_launch(void* const* d_in, const int* in_sizes, int n_in,
                              void* d_out, int out_size) {
    const float* x      = (const float*)d_in[0];
    const int*   ei     = (const int*)d_in[1];
    const float* scales = (const float*)d_in[2];
    float* out = (float*)d_out;

    float *pM, *pTa, *pTb, *pTc, *pW;
    cudaGetSymbolAddress((void**)&pM,  g_M);
    cudaGetSymbolAddress((void**)&pTa, g_Ta);
    cudaGetSymbolAddress((void**)&pTb, g_Tb);
    cudaGetSymbolAddress((void**)&pTc, g_Tc);
    cudaGetSymbolAddress((void**)&pW,  g_W);

    static int smem_set = 0;
    if (!smem_set) {
        cudaFuncSetAttribute(k_bigmma, cudaFuncAttributeMaxDynamicSharedMemorySize,
                             DSMEM_TOTAL);
        smem_set = 1;
    }

    const size_t NPNP = (size_t)NP * NP;

    k_zero<<<(NP * NP + 255) / 256, 256>>>();
    k_degree<<<(NEDGE + 255) / 256, 256>>>(ei);
    k_dinv<<<(NP + 255) / 256, 256>>>();
    k_adj<<<(NEDGE + 255) / 256, 256>>>(ei);
    k_diag<<<(NNODES + 255) / 256, 256>>>();
    k_gersh<<<1, 512>>>();
    k_coef<<<NCOEF, DCTN>>>(scales);
    k_scaleM_initT<<<(NP * NP + 255) / 256, 256>>>();

    dim3 gx(256, 16);
    k_convX<<<gx, 256>>>(x);

    // Chebyshev (deg 6) builds W(0.25) in slot 3
    float* T[3] = {pTa, pTb, pTc};
    int pp = 0, pv = 1, ot = 2;
    dim3 gs(8, 8);
    for (int k = 2; k <= CHEB_DEG; k++) {
        k_small<0><<<gs, 256>>>(pM, T[pv], T[pp], T[ot], pW + 3 * NPNP, k);
        int tmp = pp; pp = pv; pv = ot; ot = tmp;
    }

    // Squaring ladder: 0.25 -> 0.5 -> 1 -> 2 -> 4 (slots 3 -> 0 -> 1 -> 2 -> 3)
    k_small<1><<<gs, 256>>>(pW + 3 * NPNP, pW + 3 * NPNP, pW, pW + 0 * NPNP, pW, 0);
    k_small<1><<<gs, 256>>>(pW + 0 * NPNP, pW + 0 * NPNP, pW, pW + 1 * NPNP, pW, 0);
    k_small<1><<<gs, 256>>>(pW + 1 * NPNP, pW + 1 * NPNP, pW, pW + 2 * NPNP, pW, 0);
    k_small<1><<<gs, 256>>>(pW + 2 * NPNP, pW + 2 * NPNP, pW, pW + 3 * NPNP, pW, 0);

    k_convW<<<(NSCALE * NP * NP + 255) / 256, 256>>>();

    // big HMMA GEMM: blockIdx.x = mt + 4*s (16), blockIdx.y = n tile of 256 (128)
    dim3 gb(16, 128);
    k_bigmma<<<gb, 256, DSMEM_TOTAL>>>(out);
}

// round 7
// speedup vs baseline: 4.9269x; 1.1282x over previous
#include <cuda_runtime.h>
#include <cuda_fp16.h>
#include <math.h>
#include <stdint.h>

#define NNODES 500
#define NP     512
#define NFEAT  32768
#define NEDGE  16000
#define NSCALE 4
#define NCOEF 7
#define DCTN 128

// ---------------- device scratch (static, allocation-free) ----------------
__device__ float g_M [NP * NP];            // M = (L - c0 I)/h  (persists)
__device__ float g_Ta[NP * NP];            // T2
__device__ float g_Tb[NP * NP];            // T3
__device__ float g_Tc[NP * NP];            // T4
__device__ float g_Td[NP * NP];            // W(0.25)
__device__ float g_W [NSCALE * NP * NP];   // T5,T6 then W(0.5),W(1),W(2),W(4)
__device__ float g_deg [NP];
__device__ float g_c0h[2];
__device__ float g_coef[NCOEF];

// Packed, pre-swizzled (SW128) fp16 operand tiles for the HMMA big GEMM.
// A (W): [scale][m_tile(4)][k_chunk(8)] tiles of 128m x 64k (16KB each)
// B (xT): [n_tile(256)][k_chunk(8)] tiles of 128n x 64k (16KB each)
__device__ __half g_Ah[NSCALE * 4 * 8 * 8192];
__device__ __half g_Bh[256 * 8 * 8192];

// ---------------- packed f32x2 helpers ----------------
__device__ __forceinline__ void fma2(unsigned long long &d,
                                     unsigned long long a,
                                     unsigned long long b) {
    asm("fma.rn.f32x2 %0, %1, %2, %0;" : "+l"(d) : "l"(a), "l"(b));
}
__device__ __forceinline__ unsigned long long splat2(float a) {
    unsigned long long r;
    unsigned int ai = __float_as_uint(a);
    asm("mov.b64 %0, {%1, %1};" : "=l"(r) : "r"(ai));
    return r;
}
__device__ __forceinline__ float2 unpack2(unsigned long long v) {
    unsigned int lo, hi;
    asm("mov.b64 {%0, %1}, %2;" : "=r"(lo), "=r"(hi) : "l"(v));
    float2 f;
    f.x = __uint_as_float(lo);
    f.y = __uint_as_float(hi);
    return f;
}

// ---------------- graph / Laplacian build ----------------
__global__ void k_zero() {
    int i = blockIdx.x * blockDim.x + threadIdx.x;
    if (i < NP * NP) g_M[i] = 0.f;
    if (i < NP) g_deg[i] = 0.f;
}

__global__ void k_degree(const int* __restrict__ ei) {
    int e = blockIdx.x * blockDim.x + threadIdx.x;
    if (e < NEDGE) atomicAdd(&g_deg[ei[NEDGE + e]], 1.0f);
}

// adj with inline d^{-1/2}: M[s][d] = M[d][s] = -dinv(s)*dinv(d)
__global__ void k_adj(const int* __restrict__ ei) {
    int e = blockIdx.x * blockDim.x + threadIdx.x;
    if (e < NEDGE) {
        int s = ei[e], d = ei[NEDGE + e];
        float v = -rsqrtf(fmaxf(g_deg[s], 1.0f)) * rsqrtf(fmaxf(g_deg[d], 1.0f));
        g_M[s * NP + d] = v;
        g_M[d * NP + s] = v;
    }
}

// Gershgorin + add identity diag in one pass
__global__ void k_gersh() {
    __shared__ float slo[512], shi[512];
    int i = threadIdx.x;
    float cold = g_M[i * NP + i];
    float r = 0.f;
    const float4* row = (const float4*)(g_M + i * NP);
#pragma unroll 4
    for (int j = 0; j < NP / 4; j++) {
        float4 v = row[j];
        r += fabsf(v.x) + fabsf(v.y) + fabsf(v.z) + fabsf(v.w);
    }
    r -= fabsf(cold);
    float c = cold + ((i < NNODES) ? 1.f : 0.f);
    g_M[i * NP + i] = c;          // Laplacian diag
    slo[i] = c - r;
    shi[i] = c + r;
    __syncthreads();
    for (int s = 256; s > 0; s >>= 1) {
        if (i < s) {
            slo[i] = fminf(slo[i], slo[i + s]);
            shi[i] = fmaxf(shi[i], shi[i + s]);
        }
        __syncthreads();
    }
    if (i == 0) {
        float lo = slo[0], hi = shi[0];
        float c0 = 0.5f * (hi + lo);
        float h  = 0.5f * (hi - lo);
        h = fmaxf(h, 1e-4f) * 1.0001f;
        g_c0h[0] = c0;
        g_c0h[1] = h;
    }
}

// Chebyshev coefs of exp(-(s0/2)(c0 + h t)) on [-1,1]; parallel DCT
__global__ void k_coef(const float* __restrict__ scales) {
    __shared__ double red[DCTN];
    int k = blockIdx.x;
    int j = threadIdx.x;
    const double PI = 3.14159265358979323846;
    double s0 = 0.5 * (double)scales[0];
    double c0 = (double)g_c0h[0];
    double h  = (double)g_c0h[1];
    double th = PI * (j + 0.5) / (double)DCTN;
    red[j] = exp(-s0 * (c0 + h * cos(th))) * cos((double)k * th);
    __syncthreads();
    for (int s = DCTN / 2; s > 0; s >>= 1) {
        if (j < s) red[j] += red[j + s];
        __syncthreads();
    }
    if (j == 0)
        g_coef[k] = (float)(red[0] * ((k == 0) ? 1.0 : 2.0) / (double)DCTN);
}

// M = (L - c0 I)/h in place
__global__ void k_scaleM() {
    int i = blockIdx.x * blockDim.x + threadIdx.x;
    if (i < NP * NP) {
        int r = i >> 9, c = i & (NP - 1);
        float c0 = g_c0h[0], h = g_c0h[1];
        float diag = (r == c) ? 1.f : 0.f;
        g_M[i] = (g_M[i] - c0 * diag) / h;
    }
}

// ---------------- shared 64x64-tile fp32 GEMM core (FFMA2) ----------------
__device__ __forceinline__ void tile_mm(const float* __restrict__ A,
                                        const float* __restrict__ B,
                                        int m0, int n0, int t,
                                        float As[32][68], float Bs[32][64],
                                        unsigned long long acc2[4][2]) {
    for (int kt = 0; kt < NP; kt += 32) {
#pragma unroll
        for (int l = 0; l < 2; l++) {
            int f = t + l * 256;
            int row = f >> 3, kq = f & 7;
            float4 v = *(const float4*)(A + (size_t)(m0 + row) * NP + kt + kq * 4);
            As[kq * 4 + 0][row] = v.x;
            As[kq * 4 + 1][row] = v.y;
            As[kq * 4 + 2][row] = v.z;
            As[kq * 4 + 3][row] = v.w;
        }
#pragma unroll
        for (int l = 0; l < 2; l++) {
            int f = t + l * 256;
            int row = f >> 4, nq = f & 15;
            *(float4*)&Bs[row][nq * 4] =
                *(const float4*)(B + (size_t)(kt + row) * NP + n0 + nq * 4);
        }
        __syncthreads();
        int tm = (t >> 4) * 4, tn = (t & 15) * 4;
#pragma unroll
        for (int kk = 0; kk < 32; kk++) {
            float4 a = *(const float4*)&As[kk][tm];
            ulonglong2 b = *(const ulonglong2*)&Bs[kk][tn];
            float av[4] = {a.x, a.y, a.z, a.w};
#pragma unroll
            for (int r = 0; r < 4; r++) {
                unsigned long long ap = splat2(av[r]);
                fma2(acc2[r][0], ap, b.x);
                fma2(acc2[r][1], ap, b.y);
            }
        }
        __syncthreads();
    }
}

// Chebyshev product step: D = 2*A*B - (qid ? I : Q), batched over z
__global__ void __launch_bounds__(256) k_cheb2(
    const float* A0, const float* B0, const float* Q0, float* D0, int id0,
    const float* A1, const float* B1, const float* Q1, float* D1, int id1) {
    __shared__ __align__(16) float As[32][68];
    __shared__ __align__(16) float Bs[32][64];
    int t = threadIdx.x;
    int m0 = blockIdx.y * 64, n0 = blockIdx.x * 64;
    const float *A, *B, *Q;
    float* D;
    int qid;
    if (blockIdx.z == 0) { A = A0; B = B0; Q = Q0; D = D0; qid = id0; }
    else                 { A = A1; B = B1; Q = Q1; D = D1; qid = id1; }

    unsigned long long acc2[4][2] = {};
    tile_mm(A, B, m0, n0, t, As, Bs, acc2);

    int tm = (t >> 4) * 4, tn = (t & 15) * 4;
#pragma unroll
    for (int r = 0; r < 4; r++) {
        float2 p0 = unpack2(acc2[r][0]);
        float2 p1 = unpack2(acc2[r][1]);
        float vals[4] = {p0.x, p0.y, p1.x, p1.y};
#pragma unroll
        for (int c = 0; c < 4; c++) {
            int m = m0 + tm + r, n = n0 + tn + c;
            int idx = m * NP + n;
            float q = qid ? ((m == n) ? 1.f : 0.f) : Q[idx];
            D[idx] = 2.f * vals[c] - q;
        }
    }
}

// Squaring: D = A*A, epilogue also packs fp16 SW128 tiles into g_Ah[slot]
__global__ void __launch_bounds__(256) k_sq(const float* A, float* D, int slot) {
    __shared__ __align__(16) float As[32][68];
    __shared__ __align__(16) float Bs[32][64];
    int t = threadIdx.x;
    int m0 = blockIdx.y * 64, n0 = blockIdx.x * 64;

    unsigned long long acc2[4][2] = {};
    tile_mm(A, A, m0, n0, t, As, Bs, acc2);

    int tm = (t >> 4) * 4, tn = (t & 15) * 4;
#pragma unroll
    for (int r = 0; r < 4; r++) {
        float2 p0 = unpack2(acc2[r][0]);
        float2 p1 = unpack2(acc2[r][1]);
        float vals[4] = {p0.x, p0.y, p1.x, p1.y};
        int m = m0 + tm + r;
#pragma unroll
        for (int c = 0; c < 4; c++) {
            int k = n0 + tn + c;
            float v = vals[c];
            D[m * NP + k] = v;
            int tile = ((slot * 4 + (m >> 7)) * 8) + (k >> 6);
            int off = (m & 127) * 128 + (k & 63) * 2;
            off ^= (off >> 3) & 0x70;
            g_Ah[tile * 8192 + (off >> 1)] = __float2half(v);
        }
    }
}

// W(0.25) = c0 I + c1 M + c2 T2 + c3 T3 + c4 T4 + c5 T5 + c6 T6
__global__ void k_sum() {
    int i = blockIdx.x * blockDim.x + threadIdx.x;
    if (i >= NP * NP) return;
    int r = i >> 9, c = i & (NP - 1);
    float v = g_coef[0] * ((r == c) ? 1.f : 0.f)
            + g_coef[1] * g_M[i]
            + g_coef[2] * g_Ta[i]
            + g_coef[3] * g_Tb[i]
            + g_coef[4] * g_Tc[i]
            + g_coef[5] * g_W[i]
            + g_coef[6] * g_W[NP * NP + i];
    g_Td[i] = v;
}

// ---------------- x transpose -> fp16 SW128 tiles ----------------
__global__ void __launch_bounds__(256) k_convX(const float* __restrict__ x) {
    __shared__ float t[32][132];
    int nt = blockIdx.x;          // 0..255 (n tile of 128)
    int kb = blockIdx.y;          // 0..15  (32 k-rows each)
    int tid = threadIdx.x;

#pragma unroll
    for (int it = 0; it < 4; it++) {
        int f = tid + it * 256;
        int row = f >> 5, c4 = f & 31;
        int kg = kb * 32 + row;
        float4 v = make_float4(0.f, 0.f, 0.f, 0.f);
        if (kg < NNODES)
            v = *(const float4*)(x + (size_t)kg * NFEAT + nt * 128 + c4 * 4);
        t[row][c4 * 4 + 0] = v.x;
        t[row][c4 * 4 + 1] = v.y;
        t[row][c4 * 4 + 2] = v.z;
        t[row][c4 * 4 + 3] = v.w;
    }
    __syncthreads();

    size_t tile_bytes = (size_t)(nt * 8 + (kb >> 1)) * 16384;
    int halfk = (kb & 1) * 32;
    char* bh = (char*)g_Bh + tile_bytes;

#pragma unroll
    for (int it = 0; it < 2; it++) {
        int j = tid + it * 256;
        int n = j >> 2, q = j & 3;
        __align__(16) __half hs[8];
#pragma unroll
        for (int e = 0; e < 8; e++)
            hs[e] = __float2half(t[q * 8 + e][n]);
        int off = n * 128 + (halfk + q * 8) * 2;
        off ^= (off >> 3) & 0x70;
        *(uint4*)(bh + off) = *(const uint4*)hs;
    }
}

// ---------------- HMMA helpers ----------------
__device__ __forceinline__ void ldmx4(uint32_t* r, uint32_t addr) {
    asm volatile("ldmatrix.sync.aligned.m8n8.x4.shared.b16 {%0,%1,%2,%3}, [%4];"
                 : "=r"(r[0]), "=r"(r[1]), "=r"(r[2]), "=r"(r[3]) : "r"(addr));
}
__device__ __forceinline__ void mma16816(float* c, const uint32_t* a,
                                         const uint32_t* b) {
    asm volatile(
        "mma.sync.aligned.m16n8k16.row.col.f32.f16.f16.f32 "
        "{%0,%1,%2,%3}, {%4,%5,%6,%7}, {%8,%9}, {%0,%1,%2,%3};"
        : "+f"(c[0]), "+f"(c[1]), "+f"(c[2]), "+f"(c[3])
        : "r"(a[0]), "r"(a[1]), "r"(a[2]), "r"(a[3]), "r"(b[0]), "r"(b[1]));
}
__device__ __forceinline__ void cpasync16(uint32_t dst, const void* src) {
    asm volatile("cp.async.cg.shared.global [%0], [%1], 16;"
                 :: "r"(dst), "l"(src) : "memory");
}

// ---------------- big GEMM: out[s] = W_s @ x via HMMA fp16 ----------------
// CTA tile 128m x 256n, K chunks of 64, 8 warps as 2m x 4n (warp tile 64x64)
#define STAGE_BYTES 49152
#define DSMEM_TOTAL (2 * STAGE_BYTES)

__global__ void __launch_bounds__(256, 1) k_bigmma(float* __restrict__ out) {
    extern __shared__ __align__(1024) char smem[];
    uint32_t sb = (uint32_t)__cvta_generic_to_shared(smem);
    int tid = threadIdx.x, wid = tid >> 5, lid = tid & 31;
    int mt = blockIdx.x & 3, s = blockIdx.x >> 2, nt = blockIdx.y;
    int wm0 = (wid >> 2) * 64;    // 2 warp rows (m)
    int wn0 = (wid & 3) * 64;     // 4 warp cols (n)

    const char* pAh = (const char*)(g_Ah + ((size_t)((s * 4 + mt) * 8)) * 8192);

    float acc[4][8][4] = {};

    auto issue = [&](int c, int buf) {
        uint32_t dst = sb + buf * STAGE_BYTES;
        size_t aoff = (size_t)c * 16384;
#pragma unroll
        for (int it = 0; it < 4; it++) {
            uint32_t o = (uint32_t)(tid + it * 256) * 16;
            cpasync16(dst + o, pAh + aoff + o);
        }
#pragma unroll
        for (int it = 0; it < 8; it++) {
            int line = tid + it * 256;           // 0..2047
            int t0 = line >> 10;                 // which of the 2 B tiles
            uint32_t o = (uint32_t)(line & 1023) * 16;
            size_t src = ((size_t)((nt * 2 + t0) * 8 + c)) * 16384 + o;
            cpasync16(dst + 16384 + (uint32_t)line * 16, (const char*)g_Bh + src);
        }
    };

    issue(0, 0);
    asm volatile("cp.async.commit_group;");
    issue(1, 1);
    asm volatile("cp.async.commit_group;");

    for (int c = 0; c < 8; c++) {
        asm volatile("cp.async.wait_group 1;");
        __syncthreads();

        uint32_t base = sb + (c & 1) * STAGE_BYTES;
        uint32_t sAh = base, sBh = base + 16384;

#pragma unroll
        for (int kk = 0; kk < 4; kk++) {
            uint32_t ah[4][4], bh[4][4];
#pragma unroll
            for (int i = 0; i < 4; i++) {
                uint32_t off = (uint32_t)(wm0 + i * 16 + (lid & 15)) * 128 +
                               kk * 32 + (lid >> 4) * 16;
                off ^= (off >> 3) & 0x70;
                ldmx4(ah[i], sAh + off);
            }
#pragma unroll
            for (int g = 0; g < 4; g++) {
                int nl = wn0 + g * 16 + ((lid >> 4) & 1) * 8 + (lid & 7);
                uint32_t off = (uint32_t)(nl & 127) * 128 +
                               kk * 32 + ((lid >> 3) & 1) * 16;
                off ^= (off >> 3) & 0x70;
                uint32_t toff = (uint32_t)(nl >> 7) * 16384;
                ldmx4(bh[g], sBh + toff + off);
            }
#pragma unroll
            for (int i = 0; i < 4; i++) {
#pragma unroll
                for (int j = 0; j < 8; j++) {
                    int g = j >> 1, h = (j & 1) * 2;
                    mma16816(acc[i][j], ah[i], &bh[g][h]);
                }
            }
        }
        __syncthreads();
        if (c + 2 < 8) issue(c + 2, c & 1);
        asm volatile("cp.async.commit_group;");
    }

    // epilogue
    int qrow = lid >> 2, qcol = (lid & 3) * 2;
#pragma unroll
    for (int i = 0; i < 4; i++) {
        int m0g = mt * 128 + wm0 + i * 16 + qrow;
#pragma unroll
        for (int j = 0; j < 8; j++) {
            int n = nt * 256 + wn0 + j * 8 + qcol;
            if (m0g < NNODES) {
                size_t idx = ((size_t)s * NNODES + m0g) * NFEAT + n;
                *(float2*)(out + idx) = make_float2(acc[i][j][0], acc[i][j][1]);
            }
            if (m0g + 8 < NNODES) {
                size_t idx = ((size_t)s * NNODES + m0g + 8) * NFEAT + n;
                *(float2*)(out + idx) = make_float2(acc[i][j][2], acc[i][j][3]);
            }
        }
    }
}

// ---------------- launch ----------------
extern "C" void kernel_launch(void* const* d_in, const int* in_sizes, int n_in,
                              void* d_out, int out_size) {
    const float* x      = (const float*)d_in[0];
    const int*   ei     = (const int*)d_in[1];
    const float* scales = (const float*)d_in[2];
    float* out = (float*)d_out;

    float *pM, *pTa, *pTb, *pTc, *pTd, *pW;
    cudaGetSymbolAddress((void**)&pM,  g_M);
    cudaGetSymbolAddress((void**)&pTa, g_Ta);
    cudaGetSymbolAddress((void**)&pTb, g_Tb);
    cudaGetSymbolAddress((void**)&pTc, g_Tc);
    cudaGetSymbolAddress((void**)&pTd, g_Td);
    cudaGetSymbolAddress((void**)&pW,  g_W);

    static int smem_set = 0;
    if (!smem_set) {
        cudaFuncSetAttribute(k_bigmma, cudaFuncAttributeMaxDynamicSharedMemorySize,
                             DSMEM_TOTAL);
        smem_set = 1;
    }

    const size_t NPNP = (size_t)NP * NP;
    float* pW0 = pW;
    float* pW1 = pW + NPNP;
    float* pW2 = pW + 2 * NPNP;
    float* pW3 = pW + 3 * NPNP;

    // build: zero, degree, adj(+dinv), gersh(+diag), coef, scaleM
    k_zero<<<(NP * NP + 255) / 256, 256>>>();
    k_degree<<<(NEDGE + 255) / 256, 256>>>(ei);
    k_adj<<<(NEDGE + 255) / 256, 256>>>(ei);
    k_gersh<<<1, 512>>>();
    k_coef<<<NCOEF, DCTN>>>(scales);
    k_scaleM<<<(NP * NP + 255) / 256, 256>>>();

    // x transpose + fp16 pack (independent)
    dim3 gx(256, 16);
    k_convX<<<gx, 256>>>(x);

    // parallel Chebyshev: T2; {T3,T4}; {T5,T6}
    dim3 g1(8, 8, 1), g2(8, 8, 2);
    // T2 = 2 M M - I  -> Ta   (single GEMM; use z-batch kernel with same args)
    k_cheb2<<<g1, 256>>>(pM, pM, pM, pTa, 1,  pM, pM, pM, pTa, 1);
    // T3 = 2 M T2 - M -> Tb ; T4 = 2 T2 T2 - I -> Tc
    k_cheb2<<<g2, 256>>>(pM, pTa, pM, pTb, 0,  pTa, pTa, pM, pTc, 1);
    // T5 = 2 T2 T3 - M -> W0 ; T6 = 2 T3 T3 - I -> W1
    k_cheb2<<<g2, 256>>>(pTa, pTb, pM, pW0, 0,  pTb, pTb, pM, pW1, 1);
    // W(0.25) = sum c_k T_k -> Td
    k_sum<<<(NP * NP + 255) / 256, 256>>>();

    // squaring ladder with fused fp16 packing: 0.25->0.5->1->2->4
    k_sq<<<g1, 256>>>(pTd, pW0, 0);
    k_sq<<<g1, 256>>>(pW0, pW1, 1);
    k_sq<<<g1, 256>>>(pW1, pW2, 2);
    k_sq<<<g1, 256>>>(pW2, pW3, 3);

    // big HMMA GEMM: blockIdx.x = mt + 4*s (16), blockIdx.y = n tile of 256 (128)
    dim3 gb(16, 128);
    k_bigmma<<<gb, 256, DSMEM_TOTAL>>>(out);
}

// round 8
// speedup vs baseline: 5.2864x; 1.0730x over previous
#include <cuda_runtime.h>
#include <cuda_fp16.h>
#include <math.h>
#include <stdint.h>

#define NNODES 500
#define NP     512
#define NFEAT  32768
#define NEDGE  16000
#define NSCALE 4
#define NCOEF 7
#define DCTN 128

// ---------------- device scratch (static, allocation-free) ----------------
__device__ float g_M [NP * NP];            // M = (L - c0 I)/h  (persists)
__device__ float g_Ta[NP * NP];            // T2
__device__ float g_Tb[NP * NP];            // T3
__device__ float g_Tc[NP * NP];            // T4
__device__ float g_Td[NP * NP];            // W(0.25)
__device__ float g_W [NSCALE * NP * NP];   // T5,T6 then W(0.5),W(1),W(2),W(4)
__device__ float g_deg [NP];
__device__ float g_rlo[NP];
__device__ float g_rhi[NP];
__device__ float g_c0h[2];
__device__ float g_coef[NCOEF];

// Packed, pre-swizzled (SW128) fp16 operand tiles for the HMMA big GEMM.
__device__ __half g_Ah[NSCALE * 4 * 8 * 8192];
__device__ __half g_Bh[256 * 8 * 8192];

// ---------------- packed f32x2 helpers ----------------
__device__ __forceinline__ void fma2(unsigned long long &d,
                                     unsigned long long a,
                                     unsigned long long b) {
    asm("fma.rn.f32x2 %0, %1, %2, %0;" : "+l"(d) : "l"(a), "l"(b));
}
__device__ __forceinline__ unsigned long long splat2(float a) {
    unsigned long long r;
    unsigned int ai = __float_as_uint(a);
    asm("mov.b64 %0, {%1, %1};" : "=l"(r) : "r"(ai));
    return r;
}
__device__ __forceinline__ float2 unpack2(unsigned long long v) {
    unsigned int lo, hi;
    asm("mov.b64 {%0, %1}, %2;" : "=r"(lo), "=r"(hi) : "l"(v));
    float2 f;
    f.x = __uint_as_float(lo);
    f.y = __uint_as_float(hi);
    return f;
}

// ---------------- graph / Laplacian build ----------------
__global__ void k_zero() {
    int i = blockIdx.x * blockDim.x + threadIdx.x;
    if (i < NP * NP) g_M[i] = 0.f;
    if (i < NP) g_deg[i] = 0.f;
}

__global__ void k_degree(const int* __restrict__ ei) {
    int e = blockIdx.x * blockDim.x + threadIdx.x;
    if (e < NEDGE) atomicAdd(&g_deg[ei[NEDGE + e]], 1.0f);
}

__global__ void k_adj(const int* __restrict__ ei) {
    int e = blockIdx.x * blockDim.x + threadIdx.x;
    if (e < NEDGE) {
        int s = ei[e], d = ei[NEDGE + e];
        float v = -rsqrtf(fmaxf(g_deg[s], 1.0f)) * rsqrtf(fmaxf(g_deg[d], 1.0f));
        g_M[s * NP + d] = v;
        g_M[d * NP + s] = v;
    }
}

// Per-row Gershgorin: one block per row (128 threads), diag += 1 folded in
__global__ void __launch_bounds__(128) k_rows() {
    __shared__ float red[128];
    int i = blockIdx.x;
    int t = threadIdx.x;
    const float4* row = (const float4*)(g_M + i * NP);
    float r = 0.f;
    float4 v = row[t];
    r = fabsf(v.x) + fabsf(v.y) + fabsf(v.z) + fabsf(v.w);
    red[t] = r;
    __syncthreads();
    for (int s = 64; s > 0; s >>= 1) {
        if (t < s) red[t] += red[t + s];
        __syncthreads();
    }
    if (t == 0) {
        float cold = g_M[i * NP + i];
        float rr = red[0] - fabsf(cold);
        float c = cold + ((i < NNODES) ? 1.f : 0.f);
        g_M[i * NP + i] = c;
        g_rlo[i] = c - rr;
        g_rhi[i] = c + rr;
    }
}

__global__ void k_gfin() {
    __shared__ float slo[512], shi[512];
    int i = threadIdx.x;
    slo[i] = g_rlo[i];
    shi[i] = g_rhi[i];
    __syncthreads();
    for (int s = 256; s > 0; s >>= 1) {
        if (i < s) {
            slo[i] = fminf(slo[i], slo[i + s]);
            shi[i] = fmaxf(shi[i], shi[i + s]);
        }
        __syncthreads();
    }
    if (i == 0) {
        float lo = slo[0], hi = shi[0];
        float c0 = 0.5f * (hi + lo);
        float h  = 0.5f * (hi - lo);
        h = fmaxf(h, 1e-4f) * 1.0001f;
        g_c0h[0] = c0;
        g_c0h[1] = h;
    }
}

// Chebyshev coefs of exp(-(s0/2)(c0 + h t)) on [-1,1]; parallel DCT
__global__ void k_coef(const float* __restrict__ scales) {
    __shared__ double red[DCTN];
    int k = blockIdx.x;
    int j = threadIdx.x;
    const double PI = 3.14159265358979323846;
    double s0 = 0.5 * (double)scales[0];
    double c0 = (double)g_c0h[0];
    double h  = (double)g_c0h[1];
    double th = PI * (j + 0.5) / (double)DCTN;
    red[j] = exp(-s0 * (c0 + h * cos(th))) * cos((double)k * th);
    __syncthreads();
    for (int s = DCTN / 2; s > 0; s >>= 1) {
        if (j < s) red[j] += red[j + s];
        __syncthreads();
    }
    if (j == 0)
        g_coef[k] = (float)(red[0] * ((k == 0) ? 1.0 : 2.0) / (double)DCTN);
}

// M = (L - c0 I)/h in place
__global__ void k_scaleM() {
    int i = blockIdx.x * blockDim.x + threadIdx.x;
    if (i < NP * NP) {
        int r = i >> 9, c = i & (NP - 1);
        float c0 = g_c0h[0], h = g_c0h[1];
        float diag = (r == c) ? 1.f : 0.f;
        g_M[i] = (g_M[i] - c0 * diag) / h;
    }
}

// ---------------- shared 64x64-tile fp32 GEMM core (FFMA2) ----------------
__device__ __forceinline__ void tile_mm(const float* __restrict__ A,
                                        const float* __restrict__ B,
                                        int m0, int n0, int t,
                                        float As[32][68], float Bs[32][64],
                                        unsigned long long acc2[4][2]) {
    for (int kt = 0; kt < NP; kt += 32) {
#pragma unroll
        for (int l = 0; l < 2; l++) {
            int f = t + l * 256;
            int row = f >> 3, kq = f & 7;
            float4 v = *(const float4*)(A + (size_t)(m0 + row) * NP + kt + kq * 4);
            As[kq * 4 + 0][row] = v.x;
            As[kq * 4 + 1][row] = v.y;
            As[kq * 4 + 2][row] = v.z;
            As[kq * 4 + 3][row] = v.w;
        }
#pragma unroll
        for (int l = 0; l < 2; l++) {
            int f = t + l * 256;
            int row = f >> 4, nq = f & 15;
            *(float4*)&Bs[row][nq * 4] =
                *(const float4*)(B + (size_t)(kt + row) * NP + n0 + nq * 4);
        }
        __syncthreads();
        int tm = (t >> 4) * 4, tn = (t & 15) * 4;
#pragma unroll
        for (int kk = 0; kk < 32; kk++) {
            float4 a = *(const float4*)&As[kk][tm];
            ulonglong2 b = *(const ulonglong2*)&Bs[kk][tn];
            float av[4] = {a.x, a.y, a.z, a.w};
#pragma unroll
            for (int r = 0; r < 4; r++) {
                unsigned long long ap = splat2(av[r]);
                fma2(acc2[r][0], ap, b.x);
                fma2(acc2[r][1], ap, b.y);
            }
        }
        __syncthreads();
    }
}

// Chebyshev product step: D = 2*A*B - (qid ? I : Q), batched over z
__global__ void __launch_bounds__(256) k_cheb2(
    const float* A0, const float* B0, const float* Q0, float* D0, int id0,
    const float* A1, const float* B1, const float* Q1, float* D1, int id1) {
    __shared__ __align__(16) float As[32][68];
    __shared__ __align__(16) float Bs[32][64];
    int t = threadIdx.x;
    int m0 = blockIdx.y * 64, n0 = blockIdx.x * 64;
    const float *A, *B, *Q;
    float* D;
    int qid;
    if (blockIdx.z == 0) { A = A0; B = B0; Q = Q0; D = D0; qid = id0; }
    else                 { A = A1; B = B1; Q = Q1; D = D1; qid = id1; }

    unsigned long long acc2[4][2] = {};
    tile_mm(A, B, m0, n0, t, As, Bs, acc2);

    int tm = (t >> 4) * 4, tn = (t & 15) * 4;
#pragma unroll
    for (int r = 0; r < 4; r++) {
        float2 p0 = unpack2(acc2[r][0]);
        float2 p1 = unpack2(acc2[r][1]);
        float vals[4] = {p0.x, p0.y, p1.x, p1.y};
#pragma unroll
        for (int c = 0; c < 4; c++) {
            int m = m0 + tm + r, n = n0 + tn + c;
            int idx = m * NP + n;
            float q = qid ? ((m == n) ? 1.f : 0.f) : Q[idx];
            D[idx] = 2.f * vals[c] - q;
        }
    }
}

// Squaring: D = A*A, epilogue also packs fp16 SW128 tiles into g_Ah[slot]
__global__ void __launch_bounds__(256) k_sq(const float* A, float* D, int slot) {
    __shared__ __align__(16) float As[32][68];
    __shared__ __align__(16) float Bs[32][64];
    int t = threadIdx.x;
    int m0 = blockIdx.y * 64, n0 = blockIdx.x * 64;

    unsigned long long acc2[4][2] = {};
    tile_mm(A, A, m0, n0, t, As, Bs, acc2);

    int tm = (t >> 4) * 4, tn = (t & 15) * 4;
#pragma unroll
    for (int r = 0; r < 4; r++) {
        float2 p0 = unpack2(acc2[r][0]);
        float2 p1 = unpack2(acc2[r][1]);
        float vals[4] = {p0.x, p0.y, p1.x, p1.y};
        int m = m0 + tm + r;
#pragma unroll
        for (int c = 0; c < 4; c++) {
            int k = n0 + tn + c;
            float v = vals[c];
            D[m * NP + k] = v;
            int tile = ((slot * 4 + (m >> 7)) * 8) + (k >> 6);
            int off = (m & 127) * 128 + (k & 63) * 2;
            off ^= (off >> 3) & 0x70;
            g_Ah[tile * 8192 + (off >> 1)] = __float2half(v);
        }
    }
}

// W(0.25) = c0 I + c1 M + c2 T2 + c3 T3 + c4 T4 + c5 T5 + c6 T6
__global__ void k_sum() {
    int i = blockIdx.x * blockDim.x + threadIdx.x;
    if (i >= NP * NP) return;
    int r = i >> 9, c = i & (NP - 1);
    float v = g_coef[0] * ((r == c) ? 1.f : 0.f)
            + g_coef[1] * g_M[i]
            + g_coef[2] * g_Ta[i]
            + g_coef[3] * g_Tb[i]
            + g_coef[4] * g_Tc[i]
            + g_coef[5] * g_W[i]
            + g_coef[6] * g_W[NP * NP + i];
    g_Td[i] = v;
}

// ---------------- x transpose -> fp16 SW128 tiles ----------------
__global__ void __launch_bounds__(256) k_convX(const float* __restrict__ x) {
    __shared__ float t[32][132];
    int nt = blockIdx.x;
    int kb = blockIdx.y;
    int tid = threadIdx.x;

#pragma unroll
    for (int it = 0; it < 4; it++) {
        int f = tid + it * 256;
        int row = f >> 5, c4 = f & 31;
        int kg = kb * 32 + row;
        float4 v = make_float4(0.f, 0.f, 0.f, 0.f);
        if (kg < NNODES)
            v = *(const float4*)(x + (size_t)kg * NFEAT + nt * 128 + c4 * 4);
        t[row][c4 * 4 + 0] = v.x;
        t[row][c4 * 4 + 1] = v.y;
        t[row][c4 * 4 + 2] = v.z;
        t[row][c4 * 4 + 3] = v.w;
    }
    __syncthreads();

    size_t tile_bytes = (size_t)(nt * 8 + (kb >> 1)) * 16384;
    int halfk = (kb & 1) * 32;
    char* bh = (char*)g_Bh + tile_bytes;

#pragma unroll
    for (int it = 0; it < 2; it++) {
        int j = tid + it * 256;
        int n = j >> 2, q = j & 3;
        __align__(16) __half hs[8];
#pragma unroll
        for (int e = 0; e < 8; e++)
            hs[e] = __float2half(t[q * 8 + e][n]);
        int off = n * 128 + (halfk + q * 8) * 2;
        off ^= (off >> 3) & 0x70;
        *(uint4*)(bh + off) = *(const uint4*)hs;
    }
}

// ---------------- HMMA helpers ----------------
__device__ __forceinline__ void ldmx4(uint32_t* r, uint32_t addr) {
    asm volatile("ldmatrix.sync.aligned.m8n8.x4.shared.b16 {%0,%1,%2,%3}, [%4];"
                 : "=r"(r[0]), "=r"(r[1]), "=r"(r[2]), "=r"(r[3]) : "r"(addr));
}
__device__ __forceinline__ void mma16816(float* c, const uint32_t* a,
                                         const uint32_t* b) {
    asm volatile(
        "mma.sync.aligned.m16n8k16.row.col.f32.f16.f16.f32 "
        "{%0,%1,%2,%3}, {%4,%5,%6,%7}, {%8,%9}, {%0,%1,%2,%3};"
        : "+f"(c[0]), "+f"(c[1]), "+f"(c[2]), "+f"(c[3])
        : "r"(a[0]), "r"(a[1]), "r"(a[2]), "r"(a[3]), "r"(b[0]), "r"(b[1]));
}
__device__ __forceinline__ void cpasync16(uint32_t dst, const void* src) {
    asm volatile("cp.async.cg.shared.global [%0], [%1], 16;"
                 :: "r"(dst), "l"(src) : "memory");
}

// ---------------- big GEMM: out[s] = W_s @ x via HMMA fp16 ----------------
// CTA tile 128m x 256n, K chunks of 64, 4-stage cp.async pipeline
#define STAGE_BYTES 49152
#define NSTAGE 4
#define DSMEM_TOTAL (NSTAGE * STAGE_BYTES)

__global__ void __launch_bounds__(256, 1) k_bigmma(float* __restrict__ out) {
    extern __shared__ __align__(1024) char smem[];
    uint32_t sb = (uint32_t)__cvta_generic_to_shared(smem);
    int tid = threadIdx.x, wid = tid >> 5, lid = tid & 31;
    int mt = blockIdx.x & 3, s = blockIdx.x >> 2, nt = blockIdx.y;
    int wm0 = (wid >> 2) * 64;
    int wn0 = (wid & 3) * 64;

    const char* pAh = (const char*)(g_Ah + ((size_t)((s * 4 + mt) * 8)) * 8192);

    float acc[4][8][4] = {};

    auto issue = [&](int c) {
        uint32_t dst = sb + (c & (NSTAGE - 1)) * STAGE_BYTES;
        size_t aoff = (size_t)c * 16384;
#pragma unroll
        for (int it = 0; it < 4; it++) {
            uint32_t o = (uint32_t)(tid + it * 256) * 16;
            cpasync16(dst + o, pAh + aoff + o);
        }
#pragma unroll
        for (int it = 0; it < 8; it++) {
            int line = tid + it * 256;
            int t0 = line >> 10;
            uint32_t o = (uint32_t)(line & 1023) * 16;
            size_t src = ((size_t)((nt * 2 + t0) * 8 + c)) * 16384 + o;
            cpasync16(dst + 16384 + (uint32_t)line * 16, (const char*)g_Bh + src);
        }
        asm volatile("cp.async.commit_group;");
    };

    issue(0);
    issue(1);
    issue(2);

    for (int c = 0; c < 8; c++) {
        asm volatile("cp.async.wait_group 2;");
        __syncthreads();

        uint32_t base = sb + (c & (NSTAGE - 1)) * STAGE_BYTES;
        uint32_t sAh = base, sBh = base + 16384;

#pragma unroll
        for (int kk = 0; kk < 4; kk++) {
            uint32_t ah[4][4], bh[4][4];
#pragma unroll
            for (int i = 0; i < 4; i++) {
                uint32_t off = (uint32_t)(wm0 + i * 16 + (lid & 15)) * 128 +
                               kk * 32 + (lid >> 4) * 16;
                off ^= (off >> 3) & 0x70;
                ldmx4(ah[i], sAh + off);
            }
#pragma unroll
            for (int g = 0; g < 4; g++) {
                int nl = wn0 + g * 16 + ((lid >> 4) & 1) * 8 + (lid & 7);
                uint32_t off = (uint32_t)(nl & 127) * 128 +
                               kk * 32 + ((lid >> 3) & 1) * 16;
                off ^= (off >> 3) & 0x70;
                uint32_t toff = (uint32_t)(nl >> 7) * 16384;
                ldmx4(bh[g], sBh + toff + off);
            }
#pragma unroll
            for (int i = 0; i < 4; i++) {
#pragma unroll
                for (int j = 0; j < 8; j++) {
                    int g = j >> 1, h = (j & 1) * 2;
                    mma16816(acc[i][j], ah[i], &bh[g][h]);
                }
            }
        }
        __syncthreads();
        if (c + 3 < 8) issue(c + 3);
        else asm volatile("cp.async.commit_group;");
    }

    // epilogue
    int qrow = lid >> 2, qcol = (lid & 3) * 2;
#pragma unroll
    for (int i = 0; i < 4; i++) {
        int m0g = mt * 128 + wm0 + i * 16 + qrow;
#pragma unroll
        for (int j = 0; j < 8; j++) {
            int n = nt * 256 + wn0 + j * 8 + qcol;
            if (m0g < NNODES) {
                size_t idx = ((size_t)s * NNODES + m0g) * NFEAT + n;
                *(float2*)(out + idx) = make_float2(acc[i][j][0], acc[i][j][1]);
            }
            if (m0g + 8 < NNODES) {
                size_t idx = ((size_t)s * NNODES + m0g + 8) * NFEAT + n;
                *(float2*)(out + idx) = make_float2(acc[i][j][2], acc[i][j][3]);
            }
        }
    }
}

// ---------------- launch ----------------
extern "C" void kernel_launch(void* const* d_in, const int* in_sizes, int n_in,
                              void* d_out, int out_size) {
    const float* x      = (const float*)d_in[0];
    const int*   ei     = (const int*)d_in[1];
    const float* scales = (const float*)d_in[2];
    float* out = (float*)d_out;

    float *pM, *pTa, *pTb, *pTc, *pTd, *pW;
    cudaGetSymbolAddress((void**)&pM,  g_M);
    cudaGetSymbolAddress((void**)&pTa, g_Ta);
    cudaGetSymbolAddress((void**)&pTb, g_Tb);
    cudaGetSymbolAddress((void**)&pTc, g_Tc);
    cudaGetSymbolAddress((void**)&pTd, g_Td);
    cudaGetSymbolAddress((void**)&pW,  g_W);

    static int smem_set = 0;
    if (!smem_set) {
        cudaFuncSetAttribute(k_bigmma, cudaFuncAttributeMaxDynamicSharedMemorySize,
                             DSMEM_TOTAL);
        smem_set = 1;
    }

    const size_t NPNP = (size_t)NP * NP;
    float* pW0 = pW;
    float* pW1 = pW + NPNP;
    float* pW2 = pW + 2 * NPNP;
    float* pW3 = pW + 3 * NPNP;

    // build
    k_zero<<<(NP * NP + 255) / 256, 256>>>();
    k_degree<<<(NEDGE + 255) / 256, 256>>>(ei);
    k_adj<<<(NEDGE + 255) / 256, 256>>>(ei);
    k_rows<<<NP, 128>>>();
    k_gfin<<<1, 512>>>();
    k_coef<<<NCOEF, DCTN>>>(scales);
    k_scaleM<<<(NP * NP + 255) / 256, 256>>>();

    // x transpose + fp16 pack (independent)
    dim3 gx(256, 16);
    k_convX<<<gx, 256>>>(x);

    // parallel Chebyshev: T2; {T3,T4}; {T5,T6}
    dim3 g1(8, 8, 1), g2(8, 8, 2);
    k_cheb2<<<g1, 256>>>(pM, pM, pM, pTa, 1,  pM, pM, pM, pTa, 1);
    k_cheb2<<<g2, 256>>>(pM, pTa, pM, pTb, 0,  pTa, pTa, pM, pTc, 1);
    k_cheb2<<<g2, 256>>>(pTa, pTb, pM, pW0, 0,  pTb, pTb, pM, pW1, 1);
    k_sum<<<(NP * NP + 255) / 256, 256>>>();

    // squaring ladder with fused fp16 packing: 0.25->0.5->1->2->4
    k_sq<<<g1, 256>>>(pTd, pW0, 0);
    k_sq<<<g1, 256>>>(pW0, pW1, 1);
    k_sq<<<g1, 256>>>(pW1, pW2, 2);
    k_sq<<<g1, 256>>>(pW2, pW3, 3);

    // big HMMA GEMM
    dim3 gb(16, 128);
    k_bigmma<<<gb, 256, DSMEM_TOTAL>>>(out);
}

// round 10
// speedup vs baseline: 5.5513x; 1.0501x over previous
#include <cuda_runtime.h>
#include <cuda_fp16.h>
#include <math.h>
#include <stdint.h>

#define NNODES 500
#define NP     512
#define NFEAT  32768
#define NEDGE  16000
#define NSCALE 4
#define NCOEF 9
#define DCTN 128

// ---------------- device scratch (static, allocation-free) ----------------
__device__ float g_M [NP * NP];            // M = (L - c0 I)/h  (persists)
__device__ float g_Ta[NP * NP];            // T2, later W(1)
__device__ float g_Tb[NP * NP];            // T3, later W(2)
__device__ float g_Tc[NP * NP];            // T4, later W(4)
__device__ float g_Td[NP * NP];            // W(0.5)
__device__ float g_W [NSCALE * NP * NP];   // T5..T8
__device__ float g_deg [NP];
__device__ float g_rlo[NP];
__device__ float g_rhi[NP];
__device__ float g_c0h[2];
__device__ float g_coef[NCOEF];

// Packed, pre-swizzled (SW128) fp16 operand tiles for the HMMA big GEMM.
__device__ __half g_Ah[NSCALE * 4 * 8 * 8192];
__device__ __half g_Bh[256 * 8 * 8192];

// ---------------- packed f32x2 helpers ----------------
__device__ __forceinline__ void fma2(unsigned long long &d,
                                     unsigned long long a,
                                     unsigned long long b) {
    asm("fma.rn.f32x2 %0, %1, %2, %0;" : "+l"(d) : "l"(a), "l"(b));
}
__device__ __forceinline__ unsigned long long splat2(float a) {
    unsigned long long r;
    unsigned int ai = __float_as_uint(a);
    asm("mov.b64 %0, {%1, %1};" : "=l"(r) : "r"(ai));
    return r;
}
__device__ __forceinline__ float2 unpack2(unsigned long long v) {
    unsigned int lo, hi;
    asm("mov.b64 {%0, %1}, %2;" : "=r"(lo), "=r"(hi) : "l"(v));
    float2 f;
    f.x = __uint_as_float(lo);
    f.y = __uint_as_float(hi);
    return f;
}

// pack one fp32 value into the SW128 fp16 A-tile layout for scale slot
__device__ __forceinline__ void packA(int slot, int m, int k, float v) {
    int tile = ((slot * 4 + (m >> 7)) * 8) + (k >> 6);
    int off = (m & 127) * 128 + (k & 63) * 2;
    off ^= (off >> 3) & 0x70;
    g_Ah[tile * 8192 + (off >> 1)] = __float2half(v);
}

// ---------------- graph / Laplacian build ----------------
__global__ void k_zero() {
    int i = blockIdx.x * blockDim.x + threadIdx.x;
    if (i < NP * NP) g_M[i] = 0.f;
    if (i < NP) g_deg[i] = 0.f;
}

__global__ void k_degree(const int* __restrict__ ei) {
    int e = blockIdx.x * blockDim.x + threadIdx.x;
    if (e < NEDGE) atomicAdd(&g_deg[ei[NEDGE + e]], 1.0f);
}

__global__ void k_adj(const int* __restrict__ ei) {
    int e = blockIdx.x * blockDim.x + threadIdx.x;
    if (e < NEDGE) {
        int s = ei[e], d = ei[NEDGE + e];
        float v = -rsqrtf(fmaxf(g_deg[s], 1.0f)) * rsqrtf(fmaxf(g_deg[d], 1.0f));
        g_M[s * NP + d] = v;
        g_M[d * NP + s] = v;
    }
}

// Per-row Gershgorin: one block per row, diag += 1 folded in
__global__ void __launch_bounds__(128) k_rows() {
    __shared__ float red[128];
    int i = blockIdx.x;
    int t = threadIdx.x;
    const float4* row = (const float4*)(g_M + i * NP);
    float4 v = row[t];
    red[t] = fabsf(v.x) + fabsf(v.y) + fabsf(v.z) + fabsf(v.w);
    __syncthreads();
    for (int s = 64; s > 0; s >>= 1) {
        if (t < s) red[t] += red[t + s];
        __syncthreads();
    }
    if (t == 0) {
        float cold = g_M[i * NP + i];
        float rr = red[0] - fabsf(cold);
        float c = cold + ((i < NNODES) ? 1.f : 0.f);
        g_M[i * NP + i] = c;
        g_rlo[i] = c - rr;
        g_rhi[i] = c + rr;
    }
}

// Chebyshev coefs of exp(-s0(c0 + h t)); each block reduces bounds itself.
__global__ void __launch_bounds__(DCTN) k_coef(const float* __restrict__ scales) {
    __shared__ float blo[DCTN], bhi[DCTN];
    __shared__ double red[DCTN];
    int j = threadIdx.x;
    int k = blockIdx.x;
    float lo = 1e30f, hi = -1e30f;
    for (int t = j; t < NP; t += DCTN) {
        lo = fminf(lo, g_rlo[t]);
        hi = fmaxf(hi, g_rhi[t]);
    }
    blo[j] = lo; bhi[j] = hi;
    __syncthreads();
    for (int s = DCTN / 2; s > 0; s >>= 1) {
        if (j < s) {
            blo[j] = fminf(blo[j], blo[j + s]);
            bhi[j] = fmaxf(bhi[j], bhi[j + s]);
        }
        __syncthreads();
    }
    float c0f = 0.5f * (bhi[0] + blo[0]);
    float hf  = fmaxf(0.5f * (bhi[0] - blo[0]), 1e-4f) * 1.0001f;
    if (k == 0 && j == 0) {
        g_c0h[0] = c0f;
        g_c0h[1] = hf;
    }
    const double PI = 3.14159265358979323846;
    double s0 = (double)scales[0];
    double c0 = (double)c0f;
    double h  = (double)hf;
    double th = PI * (j + 0.5) / (double)DCTN;
    red[j] = exp(-s0 * (c0 + h * cos(th))) * cos((double)k * th);
    __syncthreads();
    for (int s = DCTN / 2; s > 0; s >>= 1) {
        if (j < s) red[j] += red[j + s];
        __syncthreads();
    }
    if (j == 0)
        g_coef[k] = (float)(red[0] * ((k == 0) ? 1.0 : 2.0) / (double)DCTN);
}

// M = (L - c0 I)/h in place
__global__ void k_scaleM() {
    int i = blockIdx.x * blockDim.x + threadIdx.x;
    if (i < NP * NP) {
        int r = i >> 9, c = i & (NP - 1);
        float c0 = g_c0h[0], h = g_c0h[1];
        float diag = (r == c) ? 1.f : 0.f;
        g_M[i] = (g_M[i] - c0 * diag) / h;
    }
}

// ---------------- shared 64x64-tile fp32 GEMM core (FFMA2) ----------------
__device__ __forceinline__ void tile_mm(const float* __restrict__ A,
                                        const float* __restrict__ B,
                                        int m0, int n0, int t,
                                        float As[32][68], float Bs[32][64],
                                        unsigned long long acc2[4][2]) {
    for (int kt = 0; kt < NP; kt += 32) {
#pragma unroll
        for (int l = 0; l < 2; l++) {
            int f = t + l * 256;
            int row = f >> 3, kq = f & 7;
            float4 v = *(const float4*)(A + (size_t)(m0 + row) * NP + kt + kq * 4);
            As[kq * 4 + 0][row] = v.x;
            As[kq * 4 + 1][row] = v.y;
            As[kq * 4 + 2][row] = v.z;
            As[kq * 4 + 3][row] = v.w;
        }
#pragma unroll
        for (int l = 0; l < 2; l++) {
            int f = t + l * 256;
            int row = f >> 4, nq = f & 15;
            *(float4*)&Bs[row][nq * 4] =
                *(const float4*)(B + (size_t)(kt + row) * NP + n0 + nq * 4);
        }
        __syncthreads();
        int tm = (t >> 4) * 4, tn = (t & 15) * 4;
#pragma unroll
        for (int kk = 0; kk < 32; kk++) {
            float4 a = *(const float4*)&As[kk][tm];
            ulonglong2 b = *(const ulonglong2*)&Bs[kk][tn];
            float av[4] = {a.x, a.y, a.z, a.w};
#pragma unroll
            for (int r = 0; r < 4; r++) {
                unsigned long long ap = splat2(av[r]);
                fma2(acc2[r][0], ap, b.x);
                fma2(acc2[r][1], ap, b.y);
            }
        }
        __syncthreads();
    }
}

// Chebyshev product step, z-batched up to 4: D = 2*A*B - (qid ? I : Q)
__global__ void __launch_bounds__(256) k_cheb(
    const float* A0, const float* B0, const float* Q0, float* D0, int id0,
    const float* A1, const float* B1, const float* Q1, float* D1, int id1,
    const float* A2, const float* B2, const float* Q2, float* D2, int id2,
    const float* A3, const float* B3, const float* Q3, float* D3, int id3) {
    __shared__ __align__(16) float As[32][68];
    __shared__ __align__(16) float Bs[32][64];
    int t = threadIdx.x;
    int m0 = blockIdx.y * 64, n0 = blockIdx.x * 64;
    const float *A, *B, *Q;
    float* D;
    int qid;
    switch (blockIdx.z) {
        case 0:  A = A0; B = B0; Q = Q0; D = D0; qid = id0; break;
        case 1:  A = A1; B = B1; Q = Q1; D = D1; qid = id1; break;
        case 2:  A = A2; B = B2; Q = Q2; D = D2; qid = id2; break;
        default: A = A3; B = B3; Q = Q3; D = D3; qid = id3; break;
    }

    unsigned long long acc2[4][2] = {};
    tile_mm(A, B, m0, n0, t, As, Bs, acc2);

    int tm = (t >> 4) * 4, tn = (t & 15) * 4;
#pragma unroll
    for (int r = 0; r < 4; r++) {
        float2 p0 = unpack2(acc2[r][0]);
        float2 p1 = unpack2(acc2[r][1]);
        float vals[4] = {p0.x, p0.y, p1.x, p1.y};
#pragma unroll
        for (int c = 0; c < 4; c++) {
            int m = m0 + tm + r, n = n0 + tn + c;
            int idx = m * NP + n;
            float q = qid ? ((m == n) ? 1.f : 0.f) : Q[idx];
            D[idx] = 2.f * vals[c] - q;
        }
    }
}

// Squaring: D = A*A, epilogue also packs fp16 SW128 tiles into g_Ah[slot]
__global__ void __launch_bounds__(256) k_sq(const float* A, float* D, int slot) {
    __shared__ __align__(16) float As[32][68];
    __shared__ __align__(16) float Bs[32][64];
    int t = threadIdx.x;
    int m0 = blockIdx.y * 64, n0 = blockIdx.x * 64;

    unsigned long long acc2[4][2] = {};
    tile_mm(A, A, m0, n0, t, As, Bs, acc2);

    int tm = (t >> 4) * 4, tn = (t & 15) * 4;
#pragma unroll
    for (int r = 0; r < 4; r++) {
        float2 p0 = unpack2(acc2[r][0]);
        float2 p1 = unpack2(acc2[r][1]);
        float vals[4] = {p0.x, p0.y, p1.x, p1.y};
        int m = m0 + tm + r;
#pragma unroll
        for (int c = 0; c < 4; c++) {
            int k = n0 + tn + c;
            float v = vals[c];
            D[m * NP + k] = v;
            packA(slot, m, k, v);
        }
    }
}

// W(0.5) = c0 I + c1 M + c2 T2 + ... + c8 T8 ; also packs fp16 slot 0
__global__ void k_sum() {
    int i = blockIdx.x * blockDim.x + threadIdx.x;
    if (i >= NP * NP) return;
    int r = i >> 9, c = i & (NP - 1);
    float v = g_coef[0] * ((r == c) ? 1.f : 0.f)
            + g_coef[1] * g_M[i]
            + g_coef[2] * g_Ta[i]
            + g_coef[3] * g_Tb[i]
            + g_coef[4] * g_Tc[i]
            + g_coef[5] * g_W[i]
            + g_coef[6] * g_W[NP * NP + i]
            + g_coef[7] * g_W[2 * NP * NP + i]
            + g_coef[8] * g_W[3 * NP * NP + i];
    g_Td[i] = v;
    packA(0, r, c, v);
}

// ---------------- x transpose -> fp16 SW128 tiles ----------------
__global__ void __launch_bounds__(256) k_convX(const float* __restrict__ x) {
    __shared__ float t[32][132];
    int nt = blockIdx.x;
    int kb = blockIdx.y;
    int tid = threadIdx.x;

#pragma unroll
    for (int it = 0; it < 4; it++) {
        int f = tid + it * 256;
        int row = f >> 5, c4 = f & 31;
        int kg = kb * 32 + row;
        float4 v = make_float4(0.f, 0.f, 0.f, 0.f);
        if (kg < NNODES)
            v = *(const float4*)(x + (size_t)kg * NFEAT + nt * 128 + c4 * 4);
        t[row][c4 * 4 + 0] = v.x;
        t[row][c4 * 4 + 1] = v.y;
        t[row][c4 * 4 + 2] = v.z;
        t[row][c4 * 4 + 3] = v.w;
    }
    __syncthreads();

    size_t tile_bytes = (size_t)(nt * 8 + (kb >> 1)) * 16384;
    int halfk = (kb & 1) * 32;
    char* bh = (char*)g_Bh + tile_bytes;

#pragma unroll
    for (int it = 0; it < 2; it++) {
        int j = tid + it * 256;
        int n = j >> 2, q = j & 3;
        __align__(16) __half hs[8];
#pragma unroll
        for (int e = 0; e < 8; e++)
            hs[e] = __float2half(t[q * 8 + e][n]);
        int off = n * 128 + (halfk + q * 8) * 2;
        off ^= (off >> 3) & 0x70;
        *(uint4*)(bh + off) = *(const uint4*)hs;
    }
}

// ---------------- HMMA helpers ----------------
__device__ __forceinline__ void ldmx4(uint32_t* r, uint32_t addr) {
    asm volatile("ldmatrix.sync.aligned.m8n8.x4.shared.b16 {%0,%1,%2,%3}, [%4];"
                 : "=r"(r[0]), "=r"(r[1]), "=r"(r[2]), "=r"(r[3]) : "r"(addr));
}
__device__ __forceinline__ void mma16816(float* c, const uint32_t* a,
                                         const uint32_t* b) {
    asm volatile(
        "mma.sync.aligned.m16n8k16.row.col.f32.f16.f16.f32 "
        "{%0,%1,%2,%3}, {%4,%5,%6,%7}, {%8,%9}, {%0,%1,%2,%3};"
        : "+f"(c[0]), "+f"(c[1]), "+f"(c[2]), "+f"(c[3])
        : "r"(a[0]), "r"(a[1]), "r"(a[2]), "r"(a[3]), "r"(b[0]), "r"(b[1]));
}
__device__ __forceinline__ void cpasync16(uint32_t dst, const void* src) {
    asm volatile("cp.async.cg.shared.global [%0], [%1], 16;"
                 :: "r"(dst), "l"(src) : "memory");
}

// ---------------- big GEMM: out[s] = W_s @ x via HMMA fp16 ----------------
#define STAGE_BYTES 49152
#define NSTAGE 4
#define DSMEM_TOTAL (NSTAGE * STAGE_BYTES)

__global__ void __launch_bounds__(256, 1) k_bigmma(float* __restrict__ out) {
    extern __shared__ __align__(1024) char smem[];
    uint32_t sb = (uint32_t)__cvta_generic_to_shared(smem);
    int tid = threadIdx.x, wid = tid >> 5, lid = tid & 31;
    int mt = blockIdx.x & 3, s = blockIdx.x >> 2, nt = blockIdx.y;
    int wm0 = (wid >> 2) * 64;
    int wn0 = (wid & 3) * 64;

    const char* pAh = (const char*)(g_Ah + ((size_t)((s * 4 + mt) * 8)) * 8192);

    float acc[4][8][4] = {};

    auto issue = [&](int c) {
        uint32_t dst = sb + (c & (NSTAGE - 1)) * STAGE_BYTES;
        size_t aoff = (size_t)c * 16384;
#pragma unroll
        for (int it = 0; it < 4; it++) {
            uint32_t o = (uint32_t)(tid + it * 256) * 16;
            cpasync16(dst + o, pAh + aoff + o);
        }
#pragma unroll
        for (int it = 0; it < 8; it++) {
            int line = tid + it * 256;
            int t0 = line >> 10;
            uint32_t o = (uint32_t)(line & 1023) * 16;
            size_t src = ((size_t)((nt * 2 + t0) * 8 + c)) * 16384 + o;
            cpasync16(dst + 16384 + (uint32_t)line * 16, (const char*)g_Bh + src);
        }
        asm volatile("cp.async.commit_group;");
    };

    issue(0);
    issue(1);
    issue(2);

    for (int c = 0; c < 8; c++) {
        asm volatile("cp.async.wait_group 2;");
        __syncthreads();

        uint32_t base = sb + (c & (NSTAGE - 1)) * STAGE_BYTES;
        uint32_t sAh = base, sBh = base + 16384;

#pragma unroll
        for (int kk = 0; kk < 4; kk++) {
            uint32_t ah[4][4], bh[4][4];
#pragma unroll
            for (int i = 0; i < 4; i++) {
                uint32_t off = (uint32_t)(wm0 + i * 16 + (lid & 15)) * 128 +
                               kk * 32 + (lid >> 4) * 16;
                off ^= (off >> 3) & 0x70;
                ldmx4(ah[i], sAh + off);
            }
#pragma unroll
            for (int g = 0; g < 4; g++) {
                int nl = wn0 + g * 16 + ((lid >> 4) & 1) * 8 + (lid & 7);
                uint32_t off = (uint32_t)(nl & 127) * 128 +
                               kk * 32 + ((lid >> 3) & 1) * 16;
                off ^= (off >> 3) & 0x70;
                uint32_t toff = (uint32_t)(nl >> 7) * 16384;
                ldmx4(bh[g], sBh + toff + off);
            }
#pragma unroll
            for (int i = 0; i < 4; i++) {
#pragma unroll
                for (int j = 0; j < 8; j++) {
                    int g = j >> 1, h = (j & 1) * 2;
                    mma16816(acc[i][j], ah[i], &bh[g][h]);
                }
            }
        }
        // NSTAGE=4: stage (c+3)%4 was consumed at chunk c-1, already ordered
        // by this chunk's top barrier — no second __syncthreads needed.
        if (c + 3 < 8) issue(c + 3);
        else asm volatile("cp.async.commit_group;");
    }

    // epilogue
    int qrow = lid >> 2, qcol = (lid & 3) * 2;
#pragma unroll
    for (int i = 0; i < 4; i++) {
        int m0g = mt * 128 + wm0 + i * 16 + qrow;
#pragma unroll
        for (int j = 0; j < 8; j++) {
            int n = nt * 256 + wn0 + j * 8 + qcol;
            if (m0g < NNODES) {
                size_t idx = ((size_t)s * NNODES + m0g) * NFEAT + n;
                *(float2*)(out + idx) = make_float2(acc[i][j][0], acc[i][j][1]);
            }
            if (m0g + 8 < NNODES) {
                size_t idx = ((size_t)s * NNODES + m0g + 8) * NFEAT + n;
                *(float2*)(out + idx) = make_float2(acc[i][j][2], acc[i][j][3]);
            }
        }
    }
}

// ---------------- launch (single stream — graph-capture safe) ----------------
extern "C" void kernel_launch(void* const* d_in, const int* in_sizes, int n_in,
                              void* d_out, int out_size) {
    const float* x      = (const float*)d_in[0];
    const int*   ei     = (const int*)d_in[1];
    const float* scales = (const float*)d_in[2];
    float* out = (float*)d_out;

    float *pM, *pTa, *pTb, *pTc, *pTd, *pW;
    cudaGetSymbolAddress((void**)&pM,  g_M);
    cudaGetSymbolAddress((void**)&pTa, g_Ta);
    cudaGetSymbolAddress((void**)&pTb, g_Tb);
    cudaGetSymbolAddress((void**)&pTc, g_Tc);
    cudaGetSymbolAddress((void**)&pTd, g_Td);
    cudaGetSymbolAddress((void**)&pW,  g_W);

    static int smem_set = 0;
    if (!smem_set) {
        cudaFuncSetAttribute(k_bigmma, cudaFuncAttributeMaxDynamicSharedMemorySize,
                             DSMEM_TOTAL);
        smem_set = 1;
    }

    const size_t NPNP = (size_t)NP * NP;
    float* pW0 = pW;
    float* pW1 = pW + NPNP;
    float* pW2 = pW + 2 * NPNP;
    float* pW3 = pW + 3 * NPNP;

    // build
    k_zero<<<(NP * NP + 255) / 256, 256>>>();
    k_degree<<<(NEDGE + 255) / 256, 256>>>(ei);
    k_adj<<<(NEDGE + 255) / 256, 256>>>(ei);
    k_rows<<<NP, 128>>>();
    k_coef<<<NCOEF, DCTN>>>(scales);
    k_scaleM<<<(NP * NP + 255) / 256, 256>>>();

    // x transpose + fp16 pack (inline; fills idle SMs alongside chain waves)
    dim3 gx(256, 16);
    k_convX<<<gx, 256>>>(x);

    // parallel Chebyshev (deg 8, base s=0.5): T2; {T3,T4}; {T5,T6,T7,T8}
    dim3 g1(8, 8, 1), g2(8, 8, 2), g4(8, 8, 4);
    k_cheb<<<g1, 256>>>(pM, pM, pM, pTa, 1,
                        pM, pM, pM, pTa, 1,
                        pM, pM, pM, pTa, 1,
                        pM, pM, pM, pTa, 1);
    k_cheb<<<g2, 256>>>(pM, pTa, pM, pTb, 0,      // T3 = 2 M T2 - M
                        pTa, pTa, pM, pTc, 1,     // T4 = 2 T2^2 - I
                        pM, pM, pM, pTa, 1,
                        pM, pM, pM, pTa, 1);
    k_cheb<<<g4, 256>>>(pTa, pTb, pM, pW0, 0,     // T5 = 2 T2 T3 - M
                        pTb, pTb, pM, pW1, 1,     // T6 = 2 T3^2 - I
                        pTb, pTc, pM, pW2, 0,     // T7 = 2 T3 T4 - M
                        pTc, pTc, pM, pW3, 1);    // T8 = 2 T4^2 - I
    // W(0.5) = sum c_k T_k -> Td, packs fp16 slot 0
    k_sum<<<(NP * NP + 255) / 256, 256>>>();

    // squaring ladder: 0.5 -> 1 -> 2 -> 4 (slots 1,2,3)
    k_sq<<<g1, 256>>>(pTd, pTa, 1);
    k_sq<<<g1, 256>>>(pTa, pTb, 2);
    k_sq<<<g1, 256>>>(pTb, pTc, 3);

    // big HMMA GEMM
    dim3 gb(16, 128);
    k_bigmma<<<gb, 256, DSMEM_TOTAL>>>(out);
}

// round 11
// speedup vs baseline: 6.2659x; 1.1287x over previous
#include <cuda_runtime.h>
#include <cuda_fp16.h>
#include <math.h>
#include <stdint.h>

#define NNODES 500
#define NP     512
#define NFEAT  32768
#define NEDGE  16000
#define NSCALE 4
#define NCOEF 9
#define DCTN 128

// ---------------- device scratch (static, allocation-free) ----------------
__device__ float g_M [NP * NP];            // M = (L - c0 I)/h  (persists)
__device__ float g_Ta[NP * NP];            // T2
__device__ float g_Tb[NP * NP];            // T3
__device__ float g_Tc[NP * NP];            // T4
__device__ float g_W [NSCALE * NP * NP];   // T5..T8
__device__ float g_deg [NP];
__device__ float g_rlo[NP];
__device__ float g_rhi[NP];
__device__ float g_c0h[2];
__device__ float g_coef[NCOEF];

// Packed, pre-swizzled (SW128) fp16 operand tiles.
// A (W hi/lo): [scale][m_tile(4)][k_chunk(8)] tiles of 128m x 64k (16KB each)
// B (xT hi):   [n_tile(256)][k_chunk(8)] tiles of 128n x 64k (16KB each)
__device__ __half g_Ah[NSCALE * 4 * 8 * 8192];
__device__ __half g_Al[NSCALE * 4 * 8 * 8192];
__device__ __half g_Bh[256 * 8 * 8192];

// ---------------- packed f32x2 helpers ----------------
__device__ __forceinline__ void fma2(unsigned long long &d,
                                     unsigned long long a,
                                     unsigned long long b) {
    asm("fma.rn.f32x2 %0, %1, %2, %0;" : "+l"(d) : "l"(a), "l"(b));
}
__device__ __forceinline__ unsigned long long splat2(float a) {
    unsigned long long r;
    unsigned int ai = __float_as_uint(a);
    asm("mov.b64 %0, {%1, %1};" : "=l"(r) : "r"(ai));
    return r;
}
__device__ __forceinline__ float2 unpack2(unsigned long long v) {
    unsigned int lo, hi;
    asm("mov.b64 {%0, %1}, %2;" : "=r"(lo), "=r"(hi) : "l"(v));
    float2 f;
    f.x = __uint_as_float(lo);
    f.y = __uint_as_float(hi);
    return f;
}

// pack one fp32 value into the SW128 fp16 hi/lo A-tile layout for scale slot
__device__ __forceinline__ void packA2(int slot, int m, int k, float v) {
    int tile = ((slot * 4 + (m >> 7)) * 8) + (k >> 6);
    int off = (m & 127) * 128 + (k & 63) * 2;
    off ^= (off >> 3) & 0x70;
    int idx = tile * 8192 + (off >> 1);
    __half h = __float2half(v);
    g_Ah[idx] = h;
    g_Al[idx] = __float2half(v - __half2float(h));
}

// ---------------- graph / Laplacian build ----------------
__global__ void k_zero() {
    int i = blockIdx.x * blockDim.x + threadIdx.x;
    if (i < NP * NP) g_M[i] = 0.f;
    if (i < NP) g_deg[i] = 0.f;
}

__global__ void k_degree(const int* __restrict__ ei) {
    int e = blockIdx.x * blockDim.x + threadIdx.x;
    if (e < NEDGE) atomicAdd(&g_deg[ei[NEDGE + e]], 1.0f);
}

__global__ void k_adj(const int* __restrict__ ei) {
    int e = blockIdx.x * blockDim.x + threadIdx.x;
    if (e < NEDGE) {
        int s = ei[e], d = ei[NEDGE + e];
        float v = -rsqrtf(fmaxf(g_deg[s], 1.0f)) * rsqrtf(fmaxf(g_deg[d], 1.0f));
        g_M[s * NP + d] = v;
        g_M[d * NP + s] = v;
    }
}

// Per-row Gershgorin: one block per row, diag += 1 folded in
__global__ void __launch_bounds__(128) k_rows() {
    __shared__ float red[128];
    int i = blockIdx.x;
    int t = threadIdx.x;
    const float4* row = (const float4*)(g_M + i * NP);
    float4 v = row[t];
    red[t] = fabsf(v.x) + fabsf(v.y) + fabsf(v.z) + fabsf(v.w);
    __syncthreads();
    for (int s = 64; s > 0; s >>= 1) {
        if (t < s) red[t] += red[t + s];
        __syncthreads();
    }
    if (t == 0) {
        float cold = g_M[i * NP + i];
        float rr = red[0] - fabsf(cold);
        float c = cold + ((i < NNODES) ? 1.f : 0.f);
        g_M[i * NP + i] = c;
        g_rlo[i] = c - rr;
        g_rhi[i] = c + rr;
    }
}

// Chebyshev coefs of exp(-s0(c0 + h t)); each block reduces bounds itself.
__global__ void __launch_bounds__(DCTN) k_coef(const float* __restrict__ scales) {
    __shared__ float blo[DCTN], bhi[DCTN];
    __shared__ double red[DCTN];
    int j = threadIdx.x;
    int k = blockIdx.x;
    float lo = 1e30f, hi = -1e30f;
    for (int t = j; t < NP; t += DCTN) {
        lo = fminf(lo, g_rlo[t]);
        hi = fmaxf(hi, g_rhi[t]);
    }
    blo[j] = lo; bhi[j] = hi;
    __syncthreads();
    for (int s = DCTN / 2; s > 0; s >>= 1) {
        if (j < s) {
            blo[j] = fminf(blo[j], blo[j + s]);
            bhi[j] = fmaxf(bhi[j], bhi[j + s]);
        }
        __syncthreads();
    }
    float c0f = 0.5f * (bhi[0] + blo[0]);
    float hf  = fmaxf(0.5f * (bhi[0] - blo[0]), 1e-4f) * 1.0001f;
    if (k == 0 && j == 0) {
        g_c0h[0] = c0f;
        g_c0h[1] = hf;
    }
    const double PI = 3.14159265358979323846;
    double s0 = (double)scales[0];
    double c0 = (double)c0f;
    double h  = (double)hf;
    double th = PI * (j + 0.5) / (double)DCTN;
    red[j] = exp(-s0 * (c0 + h * cos(th))) * cos((double)k * th);
    __syncthreads();
    for (int s = DCTN / 2; s > 0; s >>= 1) {
        if (j < s) red[j] += red[j + s];
        __syncthreads();
    }
    if (j == 0)
        g_coef[k] = (float)(red[0] * ((k == 0) ? 1.0 : 2.0) / (double)DCTN);
}

// M = (L - c0 I)/h in place
__global__ void k_scaleM() {
    int i = blockIdx.x * blockDim.x + threadIdx.x;
    if (i < NP * NP) {
        int r = i >> 9, c = i & (NP - 1);
        float c0 = g_c0h[0], h = g_c0h[1];
        float diag = (r == c) ? 1.f : 0.f;
        g_M[i] = (g_M[i] - c0 * diag) / h;
    }
}

// ---------------- shared 64x64-tile fp32 GEMM core (FFMA2) ----------------
__device__ __forceinline__ void tile_mm(const float* __restrict__ A,
                                        const float* __restrict__ B,
                                        int m0, int n0, int t,
                                        float As[32][68], float Bs[32][64],
                                        unsigned long long acc2[4][2]) {
    for (int kt = 0; kt < NP; kt += 32) {
#pragma unroll
        for (int l = 0; l < 2; l++) {
            int f = t + l * 256;
            int row = f >> 3, kq = f & 7;
            float4 v = *(const float4*)(A + (size_t)(m0 + row) * NP + kt + kq * 4);
            As[kq * 4 + 0][row] = v.x;
            As[kq * 4 + 1][row] = v.y;
            As[kq * 4 + 2][row] = v.z;
            As[kq * 4 + 3][row] = v.w;
        }
#pragma unroll
        for (int l = 0; l < 2; l++) {
            int f = t + l * 256;
            int row = f >> 4, nq = f & 15;
            *(float4*)&Bs[row][nq * 4] =
                *(const float4*)(B + (size_t)(kt + row) * NP + n0 + nq * 4);
        }
        __syncthreads();
        int tm = (t >> 4) * 4, tn = (t & 15) * 4;
#pragma unroll
        for (int kk = 0; kk < 32; kk++) {
            float4 a = *(const float4*)&As[kk][tm];
            ulonglong2 b = *(const ulonglong2*)&Bs[kk][tn];
            float av[4] = {a.x, a.y, a.z, a.w};
#pragma unroll
            for (int r = 0; r < 4; r++) {
                unsigned long long ap = splat2(av[r]);
                fma2(acc2[r][0], ap, b.x);
                fma2(acc2[r][1], ap, b.y);
            }
        }
        __syncthreads();
    }
}

// Chebyshev product step, z-batched up to 4: D = 2*A*B - (qid ? I : Q)
__global__ void __launch_bounds__(256) k_cheb(
    const float* A0, const float* B0, const float* Q0, float* D0, int id0,
    const float* A1, const float* B1, const float* Q1, float* D1, int id1,
    const float* A2, const float* B2, const float* Q2, float* D2, int id2,
    const float* A3, const float* B3, const float* Q3, float* D3, int id3) {
    __shared__ __align__(16) float As[32][68];
    __shared__ __align__(16) float Bs[32][64];
    int t = threadIdx.x;
    int m0 = blockIdx.y * 64, n0 = blockIdx.x * 64;
    const float *A, *B, *Q;
    float* D;
    int qid;
    switch (blockIdx.z) {
        case 0:  A = A0; B = B0; Q = Q0; D = D0; qid = id0; break;
        case 1:  A = A1; B = B1; Q = Q1; D = D1; qid = id1; break;
        case 2:  A = A2; B = B2; Q = Q2; D = D2; qid = id2; break;
        default: A = A3; B = B3; Q = Q3; D = D3; qid = id3; break;
    }

    unsigned long long acc2[4][2] = {};
    tile_mm(A, B, m0, n0, t, As, Bs, acc2);

    int tm = (t >> 4) * 4, tn = (t & 15) * 4;
#pragma unroll
    for (int r = 0; r < 4; r++) {
        float2 p0 = unpack2(acc2[r][0]);
        float2 p1 = unpack2(acc2[r][1]);
        float vals[4] = {p0.x, p0.y, p1.x, p1.y};
#pragma unroll
        for (int c = 0; c < 4; c++) {
            int m = m0 + tm + r, n = n0 + tn + c;
            int idx = m * NP + n;
            float q = qid ? ((m == n) ? 1.f : 0.f) : Q[idx];
            D[idx] = 2.f * vals[c] - q;
        }
    }
}

// W(0.5) = c0 I + c1 M + ... + c8 T8 ; packs fp16 hi/lo slot 0 (no fp32 out)
__global__ void k_sum() {
    int i = blockIdx.x * blockDim.x + threadIdx.x;
    if (i >= NP * NP) return;
    int r = i >> 9, c = i & (NP - 1);
    float v = g_coef[0] * ((r == c) ? 1.f : 0.f)
            + g_coef[1] * g_M[i]
            + g_coef[2] * g_Ta[i]
            + g_coef[3] * g_Tb[i]
            + g_coef[4] * g_Tc[i]
            + g_coef[5] * g_W[i]
            + g_coef[6] * g_W[NP * NP + i]
            + g_coef[7] * g_W[2 * NP * NP + i]
            + g_coef[8] * g_W[3 * NP * NP + i];
    packA2(0, r, c, v);
}

// ---------------- x transpose -> fp16 SW128 tiles ----------------
__global__ void __launch_bounds__(256) k_convX(const float* __restrict__ x) {
    __shared__ float t[32][132];
    int nt = blockIdx.x;
    int kb = blockIdx.y;
    int tid = threadIdx.x;

#pragma unroll
    for (int it = 0; it < 4; it++) {
        int f = tid + it * 256;
        int row = f >> 5, c4 = f & 31;
        int kg = kb * 32 + row;
        float4 v = make_float4(0.f, 0.f, 0.f, 0.f);
        if (kg < NNODES)
            v = *(const float4*)(x + (size_t)kg * NFEAT + nt * 128 + c4 * 4);
        t[row][c4 * 4 + 0] = v.x;
        t[row][c4 * 4 + 1] = v.y;
        t[row][c4 * 4 + 2] = v.z;
        t[row][c4 * 4 + 3] = v.w;
    }
    __syncthreads();

    size_t tile_bytes = (size_t)(nt * 8 + (kb >> 1)) * 16384;
    int halfk = (kb & 1) * 32;
    char* bh = (char*)g_Bh + tile_bytes;

#pragma unroll
    for (int it = 0; it < 2; it++) {
        int j = tid + it * 256;
        int n = j >> 2, q = j & 3;
        __align__(16) __half hs[8];
#pragma unroll
        for (int e = 0; e < 8; e++)
            hs[e] = __float2half(t[q * 8 + e][n]);
        int off = n * 128 + (halfk + q * 8) * 2;
        off ^= (off >> 3) & 0x70;
        *(uint4*)(bh + off) = *(const uint4*)hs;
    }
}

// ---------------- HMMA helpers ----------------
__device__ __forceinline__ void ldmx4(uint32_t* r, uint32_t addr) {
    asm volatile("ldmatrix.sync.aligned.m8n8.x4.shared.b16 {%0,%1,%2,%3}, [%4];"
                 : "=r"(r[0]), "=r"(r[1]), "=r"(r[2]), "=r"(r[3]) : "r"(addr));
}
__device__ __forceinline__ void mma16816(float* c, const uint32_t* a,
                                         const uint32_t* b) {
    asm volatile(
        "mma.sync.aligned.m16n8k16.row.col.f32.f16.f16.f32 "
        "{%0,%1,%2,%3}, {%4,%5,%6,%7}, {%8,%9}, {%0,%1,%2,%3};"
        : "+f"(c[0]), "+f"(c[1]), "+f"(c[2]), "+f"(c[3])
        : "r"(a[0]), "r"(a[1]), "r"(a[2]), "r"(a[3]), "r"(b[0]), "r"(b[1]));
}
__device__ __forceinline__ void cpasync16(uint32_t dst, const void* src) {
    asm volatile("cp.async.cg.shared.global [%0], [%1], 16;"
                 :: "r"(dst), "l"(src) : "memory");
}

// ---------------- HMMA squaring: slot so = (slot si)^2 ----------------
// Reads packed hi/lo tiles, computes 3-term (Ah Bh + Ah Bl + Al Bh), writes
// packed hi/lo tiles of the result. W symmetric -> B rows = A rows of W.
#define SQ_STAGE  32768
#define SQ_NSTAGE 4
#define SQ_SMEM   (SQ_NSTAGE * SQ_STAGE)

__global__ void __launch_bounds__(256, 1) k_sqmma(int si, int so) {
    extern __shared__ __align__(1024) char smem[];
    uint32_t sb = (uint32_t)__cvta_generic_to_shared(smem);
    int tid = threadIdx.x, wid = tid >> 5, lid = tid & 31;
    int m0 = blockIdx.y * 64, n0 = blockIdx.x * 64;
    int wm = wid >> 2, wn = wid & 3;   // 2m x 4n warps, warp tile 32m x 16n

    const char* Ahb = (const char*)g_Ah;
    const char* Alb = (const char*)g_Al;

    float acc[2][2][4] = {};

    auto issue = [&](int c) {
        uint32_t dst = sb + (c & (SQ_NSTAGE - 1)) * SQ_STAGE;
        size_t baseA = ((size_t)((si * 4 + (m0 >> 7)) * 8 + c)) * 16384 +
                       (size_t)(m0 & 127) * 128;
        size_t baseB = ((size_t)((si * 4 + (n0 >> 7)) * 8 + c)) * 16384 +
                       (size_t)(n0 & 127) * 128;
#pragma unroll
        for (int it = 0; it < 8; it++) {
            int line = tid + it * 256;          // 2048 lines of 16B
            int reg = line >> 9;                // 0:Ah 1:Al 2:Bh 3:Bl
            uint32_t o = (uint32_t)(line & 511) * 16;
            const char* src;
            if (reg == 0)      src = Ahb + baseA + o;
            else if (reg == 1) src = Alb + baseA + o;
            else if (reg == 2) src = Ahb + baseB + o;
            else               src = Alb + baseB + o;
            cpasync16(dst + (uint32_t)line * 16, src);
        }
        asm volatile("cp.async.commit_group;");
    };

    issue(0);
    issue(1);
    issue(2);

    for (int c = 0; c < 8; c++) {
        asm volatile("cp.async.wait_group 2;");
        __syncthreads();

        uint32_t base = sb + (c & (SQ_NSTAGE - 1)) * SQ_STAGE;
        uint32_t sAh = base, sAl = base + 8192;
        uint32_t sBh = base + 16384, sBl = base + 24576;

#pragma unroll
        for (int kk = 0; kk < 4; kk++) {
            uint32_t ah[2][4], al[2][4], bh[4], bl[4];
#pragma unroll
            for (int i = 0; i < 2; i++) {
                uint32_t off = (uint32_t)(wm * 32 + i * 16 + (lid & 15)) * 128 +
                               kk * 32 + (lid >> 4) * 16;
                off ^= (off >> 3) & 0x70;
                ldmx4(ah[i], sAh + off);
                ldmx4(al[i], sAl + off);
            }
            {
                int nl = wn * 16 + ((lid >> 4) & 1) * 8 + (lid & 7);
                uint32_t off = (uint32_t)nl * 128 +
                               kk * 32 + ((lid >> 3) & 1) * 16;
                off ^= (off >> 3) & 0x70;
                ldmx4(bh, sBh + off);
                ldmx4(bl, sBl + off);
            }
#pragma unroll
            for (int i = 0; i < 2; i++) {
#pragma unroll
                for (int j = 0; j < 2; j++) {
                    mma16816(acc[i][j], ah[i], &bh[j * 2]);
                    mma16816(acc[i][j], ah[i], &bl[j * 2]);
                    mma16816(acc[i][j], al[i], &bh[j * 2]);
                }
            }
        }
        if (c + 3 < 8) issue(c + 3);
        else asm volatile("cp.async.commit_group;");
    }

    // epilogue: pack result hi/lo into slot so
    int qrow = lid >> 2, qcol = (lid & 3) * 2;
#pragma unroll
    for (int i = 0; i < 2; i++) {
#pragma unroll
        for (int j = 0; j < 2; j++) {
            int m = m0 + wm * 32 + i * 16 + qrow;
            int n = n0 + wn * 16 + j * 8 + qcol;
            packA2(so, m,     n,     acc[i][j][0]);
            packA2(so, m,     n + 1, acc[i][j][1]);
            packA2(so, m + 8, n,     acc[i][j][2]);
            packA2(so, m + 8, n + 1, acc[i][j][3]);
        }
    }
}

// ---------------- big GEMM: out[s] = W_s @ x via HMMA fp16 ----------------
#define STAGE_BYTES 49152
#define NSTAGE 4
#define DSMEM_TOTAL (NSTAGE * STAGE_BYTES)

__global__ void __launch_bounds__(256, 1) k_bigmma(float* __restrict__ out) {
    extern __shared__ __align__(1024) char smem[];
    uint32_t sb = (uint32_t)__cvta_generic_to_shared(smem);
    int tid = threadIdx.x, wid = tid >> 5, lid = tid & 31;
    int mt = blockIdx.x & 3, s = blockIdx.x >> 2, nt = blockIdx.y;
    int wm0 = (wid >> 2) * 64;
    int wn0 = (wid & 3) * 64;

    const char* pAh = (const char*)(g_Ah + ((size_t)((s * 4 + mt) * 8)) * 8192);

    float acc[4][8][4] = {};

    auto issue = [&](int c) {
        uint32_t dst = sb + (c & (NSTAGE - 1)) * STAGE_BYTES;
        size_t aoff = (size_t)c * 16384;
#pragma unroll
        for (int it = 0; it < 4; it++) {
            uint32_t o = (uint32_t)(tid + it * 256) * 16;
            cpasync16(dst + o, pAh + aoff + o);
        }
#pragma unroll
        for (int it = 0; it < 8; it++) {
            int line = tid + it * 256;
            int t0 = line >> 10;
            uint32_t o = (uint32_t)(line & 1023) * 16;
            size_t src = ((size_t)((nt * 2 + t0) * 8 + c)) * 16384 + o;
            cpasync16(dst + 16384 + (uint32_t)line * 16, (const char*)g_Bh + src);
        }
        asm volatile("cp.async.commit_group;");
    };

    issue(0);
    issue(1);
    issue(2);

    for (int c = 0; c < 8; c++) {
        asm volatile("cp.async.wait_group 2;");
        __syncthreads();

        uint32_t base = sb + (c & (NSTAGE - 1)) * STAGE_BYTES;
        uint32_t sAh = base, sBh = base + 16384;

#pragma unroll
        for (int kk = 0; kk < 4; kk++) {
            uint32_t ah[4][4], bh[4][4];
#pragma unroll
            for (int i = 0; i < 4; i++) {
                uint32_t off = (uint32_t)(wm0 + i * 16 + (lid & 15)) * 128 +
                               kk * 32 + (lid >> 4) * 16;
                off ^= (off >> 3) & 0x70;
                ldmx4(ah[i], sAh + off);
            }
#pragma unroll
            for (int g = 0; g < 4; g++) {
                int nl = wn0 + g * 16 + ((lid >> 4) & 1) * 8 + (lid & 7);
                uint32_t off = (uint32_t)(nl & 127) * 128 +
                               kk * 32 + ((lid >> 3) & 1) * 16;
                off ^= (off >> 3) & 0x70;
                uint32_t toff = (uint32_t)(nl >> 7) * 16384;
                ldmx4(bh[g], sBh + toff + off);
            }
#pragma unroll
            for (int i = 0; i < 4; i++) {
#pragma unroll
                for (int j = 0; j < 8; j++) {
                    int g = j >> 1, h = (j & 1) * 2;
                    mma16816(acc[i][j], ah[i], &bh[g][h]);
                }
            }
        }
        if (c + 3 < 8) issue(c + 3);
        else asm volatile("cp.async.commit_group;");
    }

    // epilogue
    int qrow = lid >> 2, qcol = (lid & 3) * 2;
#pragma unroll
    for (int i = 0; i < 4; i++) {
        int m0g = mt * 128 + wm0 + i * 16 + qrow;
#pragma unroll
        for (int j = 0; j < 8; j++) {
            int n = nt * 256 + wn0 + j * 8 + qcol;
            if (m0g < NNODES) {
                size_t idx = ((size_t)s * NNODES + m0g) * NFEAT + n;
                *(float2*)(out + idx) = make_float2(acc[i][j][0], acc[i][j][1]);
            }
            if (m0g + 8 < NNODES) {
                size_t idx = ((size_t)s * NNODES + m0g + 8) * NFEAT + n;
                *(float2*)(out + idx) = make_float2(acc[i][j][2], acc[i][j][3]);
            }
        }
    }
}

// ---------------- launch (single stream — graph-capture safe) ----------------
extern "C" void kernel_launch(void* const* d_in, const int* in_sizes, int n_in,
                              void* d_out, int out_size) {
    const float* x      = (const float*)d_in[0];
    const int*   ei     = (const int*)d_in[1];
    const float* scales = (const float*)d_in[2];
    float* out = (float*)d_out;

    float *pM, *pTa, *pTb, *pTc, *pW;
    cudaGetSymbolAddress((void**)&pM,  g_M);
    cudaGetSymbolAddress((void**)&pTa, g_Ta);
    cudaGetSymbolAddress((void**)&pTb, g_Tb);
    cudaGetSymbolAddress((void**)&pTc, g_Tc);
    cudaGetSymbolAddress((void**)&pW,  g_W);

    static int smem_set = 0;
    if (!smem_set) {
        cudaFuncSetAttribute(k_bigmma, cudaFuncAttributeMaxDynamicSharedMemorySize,
                             DSMEM_TOTAL);
        cudaFuncSetAttribute(k_sqmma, cudaFuncAttributeMaxDynamicSharedMemorySize,
                             SQ_SMEM);
        smem_set = 1;
    }

    const size_t NPNP = (size_t)NP * NP;
    float* pW0 = pW;
    float* pW1 = pW + NPNP;
    float* pW2 = pW + 2 * NPNP;
    float* pW3 = pW + 3 * NPNP;

    // build
    k_zero<<<(NP * NP + 255) / 256, 256>>>();
    k_degree<<<(NEDGE + 255) / 256, 256>>>(ei);
    k_adj<<<(NEDGE + 255) / 256, 256>>>(ei);
    k_rows<<<NP, 128>>>();
    k_coef<<<NCOEF, DCTN>>>(scales);
    k_scaleM<<<(NP * NP + 255) / 256, 256>>>();

    // x transpose + fp16 pack
    dim3 gx(256, 16);
    k_convX<<<gx, 256>>>(x);

    // parallel Chebyshev (deg 8, base s=0.5): T2; {T3,T4}; {T5,T6,T7,T8}
    dim3 g1(8, 8, 1), g2(8, 8, 2), g4(8, 8, 4), gsq(8, 8);
    k_cheb<<<g1, 256>>>(pM, pM, pM, pTa, 1,
                        pM, pM, pM, pTa, 1,
                        pM, pM, pM, pTa, 1,
                        pM, pM, pM, pTa, 1);
    k_cheb<<<g2, 256>>>(pM, pTa, pM, pTb, 0,      // T3 = 2 M T2 - M
                        pTa, pTa, pM, pTc, 1,     // T4 = 2 T2^2 - I
                        pM, pM, pM, pTa, 1,
                        pM, pM, pM, pTa, 1);
    k_cheb<<<g4, 256>>>(pTa, pTb, pM, pW0, 0,     // T5 = 2 T2 T3 - M
                        pTb, pTb, pM, pW1, 1,     // T6 = 2 T3^2 - I
                        pTb, pTc, pM, pW2, 0,     // T7 = 2 T3 T4 - M
                        pTc, pTc, pM, pW3, 1);    // T8 = 2 T4^2 - I
    // W(0.5) = sum c_k T_k -> packed hi/lo slot 0
    k_sum<<<(NP * NP + 255) / 256, 256>>>();

    // HMMA squaring ladder on packed tiles: 0.5 -> 1 -> 2 -> 4
    k_sqmma<<<gsq, 256, SQ_SMEM>>>(0, 1);
    k_sqmma<<<gsq, 256, SQ_SMEM>>>(1, 2);
    k_sqmma<<<gsq, 256, SQ_SMEM>>>(2, 3);

    // big HMMA GEMM
    dim3 gb(16, 128);
    k_bigmma<<<gb, 256, DSMEM_TOTAL>>>(out);
}

// round 12
// speedup vs baseline: 6.7837x; 1.0826x over previous
#include <cuda_runtime.h>
#include <cuda_fp16.h>
#include <math.h>
#include <stdint.h>

#define NNODES 500
#define NP     512
#define NFEAT  32768
#define NEDGE  16000
#define NSCALE 4
#define NCOEF 9
#define DCTN 128

// ---------------- device scratch (static, allocation-free) ----------------
__device__ float g_M [NP * NP];            // M = (L - c0 I)/h  (persists)
__device__ float g_Ta[NP * NP];            // T2
__device__ float g_Tb[NP * NP];            // T3
__device__ float g_Tc[NP * NP];            // T4
__device__ float g_W [NSCALE * NP * NP];   // T5..T8
__device__ float g_deg [NP];
__device__ float g_rlo[NP];
__device__ float g_rhi[NP];
__device__ float g_c0h[2];
__device__ float g_coef[NCOEF];

// Packed, pre-swizzled (SW128) fp16 operand tiles.
// A (W hi/lo): [scale][m_tile(4)][k_chunk(8)] tiles of 128m x 64k (16KB each)
// B (xT hi):   [n_tile(256)][k_chunk(8)] tiles of 128n x 64k (16KB each)
__device__ __half g_Ah[NSCALE * 4 * 8 * 8192];
__device__ __half g_Al[NSCALE * 4 * 8 * 8192];
__device__ __half g_Bh[256 * 8 * 8192];

// ---------------- packed f32x2 helpers ----------------
__device__ __forceinline__ void fma2(unsigned long long &d,
                                     unsigned long long a,
                                     unsigned long long b) {
    asm("fma.rn.f32x2 %0, %1, %2, %0;" : "+l"(d) : "l"(a), "l"(b));
}
__device__ __forceinline__ unsigned long long splat2(float a) {
    unsigned long long r;
    unsigned int ai = __float_as_uint(a);
    asm("mov.b64 %0, {%1, %1};" : "=l"(r) : "r"(ai));
    return r;
}
__device__ __forceinline__ float2 unpack2(unsigned long long v) {
    unsigned int lo, hi;
    asm("mov.b64 {%0, %1}, %2;" : "=r"(lo), "=r"(hi) : "l"(v));
    float2 f;
    f.x = __uint_as_float(lo);
    f.y = __uint_as_float(hi);
    return f;
}

// pack one fp32 value into the SW128 fp16 hi/lo A-tile layout for scale slot
__device__ __forceinline__ void packA2(int slot, int m, int k, float v) {
    int tile = ((slot * 4 + (m >> 7)) * 8) + (k >> 6);
    int off = (m & 127) * 128 + (k & 63) * 2;
    off ^= (off >> 3) & 0x70;
    int idx = tile * 8192 + (off >> 1);
    __half h = __float2half(v);
    g_Ah[idx] = h;
    g_Al[idx] = __float2half(v - __half2float(h));
}

// ---------------- graph / Laplacian build ----------------
__global__ void k_zero() {
    int i = blockIdx.x * blockDim.x + threadIdx.x;
    if (i < NP * NP) g_M[i] = 0.f;
    if (i < NP) g_deg[i] = 0.f;
}

__global__ void k_degree(const int* __restrict__ ei) {
    int e = blockIdx.x * blockDim.x + threadIdx.x;
    if (e < NEDGE) atomicAdd(&g_deg[ei[NEDGE + e]], 1.0f);
}

__global__ void k_adj(const int* __restrict__ ei) {
    int e = blockIdx.x * blockDim.x + threadIdx.x;
    if (e < NEDGE) {
        int s = ei[e], d = ei[NEDGE + e];
        float v = -rsqrtf(fmaxf(g_deg[s], 1.0f)) * rsqrtf(fmaxf(g_deg[d], 1.0f));
        g_M[s * NP + d] = v;
        g_M[d * NP + s] = v;
    }
}

// Per-row Gershgorin: one block per row, diag += 1 folded in
__global__ void __launch_bounds__(128) k_rows() {
    __shared__ float red[128];
    int i = blockIdx.x;
    int t = threadIdx.x;
    const float4* row = (const float4*)(g_M + i * NP);
    float4 v = row[t];
    red[t] = fabsf(v.x) + fabsf(v.y) + fabsf(v.z) + fabsf(v.w);
    __syncthreads();
    for (int s = 64; s > 0; s >>= 1) {
        if (t < s) red[t] += red[t + s];
        __syncthreads();
    }
    if (t == 0) {
        float cold = g_M[i * NP + i];
        float rr = red[0] - fabsf(cold);
        float c = cold + ((i < NNODES) ? 1.f : 0.f);
        g_M[i * NP + i] = c;
        g_rlo[i] = c - rr;
        g_rhi[i] = c + rr;
    }
}

// Chebyshev coefs of exp(-s0(c0 + h t)); each block reduces bounds itself.
__global__ void __launch_bounds__(DCTN) k_coef(const float* __restrict__ scales) {
    __shared__ float blo[DCTN], bhi[DCTN];
    __shared__ double red[DCTN];
    int j = threadIdx.x;
    int k = blockIdx.x;
    float lo = 1e30f, hi = -1e30f;
    for (int t = j; t < NP; t += DCTN) {
        lo = fminf(lo, g_rlo[t]);
        hi = fmaxf(hi, g_rhi[t]);
    }
    blo[j] = lo; bhi[j] = hi;
    __syncthreads();
    for (int s = DCTN / 2; s > 0; s >>= 1) {
        if (j < s) {
            blo[j] = fminf(blo[j], blo[j + s]);
            bhi[j] = fmaxf(bhi[j], bhi[j + s]);
        }
        __syncthreads();
    }
    float c0f = 0.5f * (bhi[0] + blo[0]);
    float hf  = fmaxf(0.5f * (bhi[0] - blo[0]), 1e-4f) * 1.0001f;
    if (k == 0 && j == 0) {
        g_c0h[0] = c0f;
        g_c0h[1] = hf;
    }
    const double PI = 3.14159265358979323846;
    double s0 = (double)scales[0];
    double c0 = (double)c0f;
    double h  = (double)hf;
    double th = PI * (j + 0.5) / (double)DCTN;
    red[j] = exp(-s0 * (c0 + h * cos(th))) * cos((double)k * th);
    __syncthreads();
    for (int s = DCTN / 2; s > 0; s >>= 1) {
        if (j < s) red[j] += red[j + s];
        __syncthreads();
    }
    if (j == 0)
        g_coef[k] = (float)(red[0] * ((k == 0) ? 1.0 : 2.0) / (double)DCTN);
}

// M = (L - c0 I)/h in place
__global__ void k_scaleM() {
    int i = blockIdx.x * blockDim.x + threadIdx.x;
    if (i < NP * NP) {
        int r = i >> 9, c = i & (NP - 1);
        float c0 = g_c0h[0], h = g_c0h[1];
        float diag = (r == c) ? 1.f : 0.f;
        g_M[i] = (g_M[i] - c0 * diag) / h;
    }
}

// ---------------- shared 64x64-tile fp32 GEMM core (FFMA2) ----------------
__device__ __forceinline__ void tile_mm(const float* __restrict__ A,
                                        const float* __restrict__ B,
                                        int m0, int n0, int t,
                                        float As[32][68], float Bs[32][64],
                                        unsigned long long acc2[4][2]) {
    for (int kt = 0; kt < NP; kt += 32) {
#pragma unroll
        for (int l = 0; l < 2; l++) {
            int f = t + l * 256;
            int row = f >> 3, kq = f & 7;
            float4 v = *(const float4*)(A + (size_t)(m0 + row) * NP + kt + kq * 4);
            As[kq * 4 + 0][row] = v.x;
            As[kq * 4 + 1][row] = v.y;
            As[kq * 4 + 2][row] = v.z;
            As[kq * 4 + 3][row] = v.w;
        }
#pragma unroll
        for (int l = 0; l < 2; l++) {
            int f = t + l * 256;
            int row = f >> 4, nq = f & 15;
            *(float4*)&Bs[row][nq * 4] =
                *(const float4*)(B + (size_t)(kt + row) * NP + n0 + nq * 4);
        }
        __syncthreads();
        int tm = (t >> 4) * 4, tn = (t & 15) * 4;
#pragma unroll
        for (int kk = 0; kk < 32; kk++) {
            float4 a = *(const float4*)&As[kk][tm];
            ulonglong2 b = *(const ulonglong2*)&Bs[kk][tn];
            float av[4] = {a.x, a.y, a.z, a.w};
#pragma unroll
            for (int r = 0; r < 4; r++) {
                unsigned long long ap = splat2(av[r]);
                fma2(acc2[r][0], ap, b.x);
                fma2(acc2[r][1], ap, b.y);
            }
        }
        __syncthreads();
    }
}

// Chebyshev product step, z-batched up to 4: D = 2*A*B - (qid ? I : Q)
__global__ void __launch_bounds__(256) k_cheb(
    const float* A0, const float* B0, const float* Q0, float* D0, int id0,
    const float* A1, const float* B1, const float* Q1, float* D1, int id1,
    const float* A2, const float* B2, const float* Q2, float* D2, int id2,
    const float* A3, const float* B3, const float* Q3, float* D3, int id3) {
    __shared__ __align__(16) float As[32][68];
    __shared__ __align__(16) float Bs[32][64];
    int t = threadIdx.x;
    int m0 = blockIdx.y * 64, n0 = blockIdx.x * 64;
    const float *A, *B, *Q;
    float* D;
    int qid;
    switch (blockIdx.z) {
        case 0:  A = A0; B = B0; Q = Q0; D = D0; qid = id0; break;
        case 1:  A = A1; B = B1; Q = Q1; D = D1; qid = id1; break;
        case 2:  A = A2; B = B2; Q = Q2; D = D2; qid = id2; break;
        default: A = A3; B = B3; Q = Q3; D = D3; qid = id3; break;
    }

    unsigned long long acc2[4][2] = {};
    tile_mm(A, B, m0, n0, t, As, Bs, acc2);

    int tm = (t >> 4) * 4, tn = (t & 15) * 4;
#pragma unroll
    for (int r = 0; r < 4; r++) {
        float2 p0 = unpack2(acc2[r][0]);
        float2 p1 = unpack2(acc2[r][1]);
        float vals[4] = {p0.x, p0.y, p1.x, p1.y};
#pragma unroll
        for (int c = 0; c < 4; c++) {
            int m = m0 + tm + r, n = n0 + tn + c;
            int idx = m * NP + n;
            float q = qid ? ((m == n) ? 1.f : 0.f) : Q[idx];
            D[idx] = 2.f * vals[c] - q;
        }
    }
}

// W(0.5) = c0 I + c1 M + ... + c8 T8 ; packs fp16 hi/lo slot 0 (no fp32 out)
__global__ void k_sum() {
    int i = blockIdx.x * blockDim.x + threadIdx.x;
    if (i >= NP * NP) return;
    int r = i >> 9, c = i & (NP - 1);
    float v = g_coef[0] * ((r == c) ? 1.f : 0.f)
            + g_coef[1] * g_M[i]
            + g_coef[2] * g_Ta[i]
            + g_coef[3] * g_Tb[i]
            + g_coef[4] * g_Tc[i]
            + g_coef[5] * g_W[i]
            + g_coef[6] * g_W[NP * NP + i]
            + g_coef[7] * g_W[2 * NP * NP + i]
            + g_coef[8] * g_W[3 * NP * NP + i];
    packA2(0, r, c, v);
}

// ---------------- x transpose -> fp16 SW128 tiles ----------------
__global__ void __launch_bounds__(256) k_convX(const float* __restrict__ x) {
    __shared__ float t[32][132];
    int nt = blockIdx.x;
    int kb = blockIdx.y;
    int tid = threadIdx.x;

#pragma unroll
    for (int it = 0; it < 4; it++) {
        int f = tid + it * 256;
        int row = f >> 5, c4 = f & 31;
        int kg = kb * 32 + row;
        float4 v = make_float4(0.f, 0.f, 0.f, 0.f);
        if (kg < NNODES)
            v = *(const float4*)(x + (size_t)kg * NFEAT + nt * 128 + c4 * 4);
        t[row][c4 * 4 + 0] = v.x;
        t[row][c4 * 4 + 1] = v.y;
        t[row][c4 * 4 + 2] = v.z;
        t[row][c4 * 4 + 3] = v.w;
    }
    __syncthreads();

    size_t tile_bytes = (size_t)(nt * 8 + (kb >> 1)) * 16384;
    int halfk = (kb & 1) * 32;
    char* bh = (char*)g_Bh + tile_bytes;

#pragma unroll
    for (int it = 0; it < 2; it++) {
        int j = tid + it * 256;
        int n = j >> 2, q = j & 3;
        __align__(16) __half hs[8];
#pragma unroll
        for (int e = 0; e < 8; e++)
            hs[e] = __float2half(t[q * 8 + e][n]);
        int off = n * 128 + (halfk + q * 8) * 2;
        off ^= (off >> 3) & 0x70;
        *(uint4*)(bh + off) = *(const uint4*)hs;
    }
}

// ---------------- HMMA helpers ----------------
__device__ __forceinline__ void ldmx4(uint32_t* r, uint32_t addr) {
    asm volatile("ldmatrix.sync.aligned.m8n8.x4.shared.b16 {%0,%1,%2,%3}, [%4];"
                 : "=r"(r[0]), "=r"(r[1]), "=r"(r[2]), "=r"(r[3]) : "r"(addr));
}
__device__ __forceinline__ void mma16816(float* c, const uint32_t* a,
                                         const uint32_t* b) {
    asm volatile(
        "mma.sync.aligned.m16n8k16.row.col.f32.f16.f16.f32 "
        "{%0,%1,%2,%3}, {%4,%5,%6,%7}, {%8,%9}, {%0,%1,%2,%3};"
        : "+f"(c[0]), "+f"(c[1]), "+f"(c[2]), "+f"(c[3])
        : "r"(a[0]), "r"(a[1]), "r"(a[2]), "r"(a[3]), "r"(b[0]), "r"(b[1]));
}
__device__ __forceinline__ void cpasync16(uint32_t dst, const void* src) {
    asm volatile("cp.async.cg.shared.global [%0], [%1], 16;"
                 :: "r"(dst), "l"(src) : "memory");
}

// ---------------- HMMA squaring: slot so = (slot si)^2 ----------------
#define SQ_STAGE  32768
#define SQ_NSTAGE 4
#define SQ_SMEM   (SQ_NSTAGE * SQ_STAGE)

__global__ void __launch_bounds__(256, 1) k_sqmma(int si, int so) {
    extern __shared__ __align__(1024) char smem[];
    uint32_t sb = (uint32_t)__cvta_generic_to_shared(smem);
    int tid = threadIdx.x, wid = tid >> 5, lid = tid & 31;
    int m0 = blockIdx.y * 64, n0 = blockIdx.x * 64;
    int wm = wid >> 2, wn = wid & 3;   // 2m x 4n warps, warp tile 32m x 16n

    const char* Ahb = (const char*)g_Ah;
    const char* Alb = (const char*)g_Al;

    float acc[2][2][4] = {};

    auto issue = [&](int c) {
        uint32_t dst = sb + (c & (SQ_NSTAGE - 1)) * SQ_STAGE;
        size_t baseA = ((size_t)((si * 4 + (m0 >> 7)) * 8 + c)) * 16384 +
                       (size_t)(m0 & 127) * 128;
        size_t baseB = ((size_t)((si * 4 + (n0 >> 7)) * 8 + c)) * 16384 +
                       (size_t)(n0 & 127) * 128;
#pragma unroll
        for (int it = 0; it < 8; it++) {
            int line = tid + it * 256;          // 2048 lines of 16B
            int reg = line >> 9;                // 0:Ah 1:Al 2:Bh 3:Bl
            uint32_t o = (uint32_t)(line & 511) * 16;
            const char* src;
            if (reg == 0)      src = Ahb + baseA + o;
            else if (reg == 1) src = Alb + baseA + o;
            else if (reg == 2) src = Ahb + baseB + o;
            else               src = Alb + baseB + o;
            cpasync16(dst + (uint32_t)line * 16, src);
        }
        asm volatile("cp.async.commit_group;");
    };

    issue(0);
    issue(1);
    issue(2);

    for (int c = 0; c < 8; c++) {
        asm volatile("cp.async.wait_group 2;");
        __syncthreads();

        uint32_t base = sb + (c & (SQ_NSTAGE - 1)) * SQ_STAGE;
        uint32_t sAh = base, sAl = base + 8192;
        uint32_t sBh = base + 16384, sBl = base + 24576;

#pragma unroll
        for (int kk = 0; kk < 4; kk++) {
            uint32_t ah[2][4], al[2][4], bh[4], bl[4];
#pragma unroll
            for (int i = 0; i < 2; i++) {
                uint32_t off = (uint32_t)(wm * 32 + i * 16 + (lid & 15)) * 128 +
                               kk * 32 + (lid >> 4) * 16;
                off ^= (off >> 3) & 0x70;
                ldmx4(ah[i], sAh + off);
                ldmx4(al[i], sAl + off);
            }
            {
                int nl = wn * 16 + ((lid >> 4) & 1) * 8 + (lid & 7);
                uint32_t off = (uint32_t)nl * 128 +
                               kk * 32 + ((lid >> 3) & 1) * 16;
                off ^= (off >> 3) & 0x70;
                ldmx4(bh, sBh + off);
                ldmx4(bl, sBl + off);
            }
#pragma unroll
            for (int i = 0; i < 2; i++) {
#pragma unroll
                for (int j = 0; j < 2; j++) {
                    mma16816(acc[i][j], ah[i], &bh[j * 2]);
                    mma16816(acc[i][j], ah[i], &bl[j * 2]);
                    mma16816(acc[i][j], al[i], &bh[j * 2]);
                }
            }
        }
        if (c + 3 < 8) issue(c + 3);
        else asm volatile("cp.async.commit_group;");
    }

    // epilogue: pack result hi/lo into slot so
    int qrow = lid >> 2, qcol = (lid & 3) * 2;
#pragma unroll
    for (int i = 0; i < 2; i++) {
#pragma unroll
        for (int j = 0; j < 2; j++) {
            int m = m0 + wm * 32 + i * 16 + qrow;
            int n = n0 + wn * 16 + j * 8 + qcol;
            packA2(so, m,     n,     acc[i][j][0]);
            packA2(so, m,     n + 1, acc[i][j][1]);
            packA2(so, m + 8, n,     acc[i][j][2]);
            packA2(so, m + 8, n + 1, acc[i][j][3]);
        }
    }
}

// ---------------- big GEMM: out[s] = W_s @ x via HMMA fp16 ----------------
// CTA tile 128m x 128n, 3-stage cp.async, 2 CTAs/SM (occupancy experiment)
#define STAGE_BYTES 32768
#define NSTAGE 3
#define DSMEM_TOTAL (NSTAGE * STAGE_BYTES)

__global__ void __launch_bounds__(256, 2) k_bigmma(float* __restrict__ out) {
    extern __shared__ __align__(1024) char smem[];
    uint32_t sb = (uint32_t)__cvta_generic_to_shared(smem);
    int tid = threadIdx.x, wid = tid >> 5, lid = tid & 31;
    int mt = blockIdx.x & 3, s = blockIdx.x >> 2, nt = blockIdx.y;
    int wm0 = (wid >> 2) * 64;    // 2 warp rows (m)
    int wn0 = (wid & 3) * 32;     // 4 warp cols (n)

    const char* pAh = (const char*)(g_Ah + ((size_t)((s * 4 + mt) * 8)) * 8192);

    float acc[4][4][4] = {};

    auto issue = [&](int c) {
        uint32_t dst = sb + (c % NSTAGE) * STAGE_BYTES;
        size_t aoff = (size_t)c * 16384;
        size_t boff = ((size_t)(nt * 8 + c)) * 16384;
#pragma unroll
        for (int it = 0; it < 4; it++) {
            uint32_t o = (uint32_t)(tid + it * 256) * 16;
            cpasync16(dst + o,         pAh + aoff + o);
            cpasync16(dst + 16384 + o, (const char*)g_Bh + boff + o);
        }
        asm volatile("cp.async.commit_group;");
    };

    issue(0);
    issue(1);

    for (int c = 0; c < 8; c++) {
        asm volatile("cp.async.wait_group 1;");
        __syncthreads();
        // stage (c+2)%3 was consumed at chunk c-1; barrier above orders it
        if (c + 2 < 8) issue(c + 2);
        else asm volatile("cp.async.commit_group;");

        uint32_t base = sb + (c % NSTAGE) * STAGE_BYTES;
        uint32_t sAh = base, sBh = base + 16384;

#pragma unroll
        for (int kk = 0; kk < 4; kk++) {
            uint32_t ah[4][4], bh[2][4];
#pragma unroll
            for (int i = 0; i < 4; i++) {
                uint32_t off = (uint32_t)(wm0 + i * 16 + (lid & 15)) * 128 +
                               kk * 32 + (lid >> 4) * 16;
                off ^= (off >> 3) & 0x70;
                ldmx4(ah[i], sAh + off);
            }
#pragma unroll
            for (int g = 0; g < 2; g++) {
                int nl = wn0 + g * 16 + ((lid >> 4) & 1) * 8 + (lid & 7);
                uint32_t off = (uint32_t)nl * 128 +
                               kk * 32 + ((lid >> 3) & 1) * 16;
                off ^= (off >> 3) & 0x70;
                ldmx4(bh[g], sBh + off);
            }
#pragma unroll
            for (int i = 0; i < 4; i++) {
#pragma unroll
                for (int j = 0; j < 4; j++) {
                    int g = j >> 1, h = (j & 1) * 2;
                    mma16816(acc[i][j], ah[i], &bh[g][h]);
                }
            }
        }
    }

    // epilogue
    int qrow = lid >> 2, qcol = (lid & 3) * 2;
#pragma unroll
    for (int i = 0; i < 4; i++) {
        int m0g = mt * 128 + wm0 + i * 16 + qrow;
#pragma unroll
        for (int j = 0; j < 4; j++) {
            int n = nt * 128 + wn0 + j * 8 + qcol;
            if (m0g < NNODES) {
                size_t idx = ((size_t)s * NNODES + m0g) * NFEAT + n;
                *(float2*)(out + idx) = make_float2(acc[i][j][0], acc[i][j][1]);
            }
            if (m0g + 8 < NNODES) {
                size_t idx = ((size_t)s * NNODES + m0g + 8) * NFEAT + n;
                *(float2*)(out + idx) = make_float2(acc[i][j][2], acc[i][j][3]);
            }
        }
    }
}

// ---------------- launch (single stream — graph-capture safe) ----------------
extern "C" void kernel_launch(void* const* d_in, const int* in_sizes, int n_in,
                              void* d_out, int out_size) {
    const float* x      = (const float*)d_in[0];
    const int*   ei     = (const int*)d_in[1];
    const float* scales = (const float*)d_in[2];
    float* out = (float*)d_out;

    float *pM, *pTa, *pTb, *pTc, *pW;
    cudaGetSymbolAddress((void**)&pM,  g_M);
    cudaGetSymbolAddress((void**)&pTa, g_Ta);
    cudaGetSymbolAddress((void**)&pTb, g_Tb);
    cudaGetSymbolAddress((void**)&pTc, g_Tc);
    cudaGetSymbolAddress((void**)&pW,  g_W);

    static int smem_set = 0;
    if (!smem_set) {
        cudaFuncSetAttribute(k_bigmma, cudaFuncAttributeMaxDynamicSharedMemorySize,
                             DSMEM_TOTAL);
        cudaFuncSetAttribute(k_sqmma, cudaFuncAttributeMaxDynamicSharedMemorySize,
                             SQ_SMEM);
        smem_set = 1;
    }

    const size_t NPNP = (size_t)NP * NP;
    float* pW0 = pW;
    float* pW1 = pW + NPNP;
    float* pW2 = pW + 2 * NPNP;
    float* pW3 = pW + 3 * NPNP;

    // build
    k_zero<<<(NP * NP + 255) / 256, 256>>>();
    k_degree<<<(NEDGE + 255) / 256, 256>>>(ei);
    k_adj<<<(NEDGE + 255) / 256, 256>>>(ei);
    k_rows<<<NP, 128>>>();
    k_coef<<<NCOEF, DCTN>>>(scales);
    k_scaleM<<<(NP * NP + 255) / 256, 256>>>();

    // x transpose + fp16 pack
    dim3 gx(256, 16);
    k_convX<<<gx, 256>>>(x);

    // parallel Chebyshev (deg 8, base s=0.5): T2; {T3,T4}; {T5,T6,T7,T8}
    dim3 g1(8, 8, 1), g2(8, 8, 2), g4(8, 8, 4), gsq(8, 8);
    k_cheb<<<g1, 256>>>(pM, pM, pM, pTa, 1,
                        pM, pM, pM, pTa, 1,
                        pM, pM, pM, pTa, 1,
                        pM, pM, pM, pTa, 1);
    k_cheb<<<g2, 256>>>(pM, pTa, pM, pTb, 0,      // T3 = 2 M T2 - M
                        pTa, pTa, pM, pTc, 1,     // T4 = 2 T2^2 - I
                        pM, pM, pM, pTa, 1,
                        pM, pM, pM, pTa, 1);
    k_cheb<<<g4, 256>>>(pTa, pTb, pM, pW0, 0,     // T5 = 2 T2 T3 - M
                        pTb, pTb, pM, pW1, 1,     // T6 = 2 T3^2 - I
                        pTb, pTc, pM, pW2, 0,     // T7 = 2 T3 T4 - M
                        pTc, pTc, pM, pW3, 1);    // T8 = 2 T4^2 - I
    // W(0.5) = sum c_k T_k -> packed hi/lo slot 0
    k_sum<<<(NP * NP + 255) / 256, 256>>>();

    // HMMA squaring ladder on packed tiles: 0.5 -> 1 -> 2 -> 4
    k_sqmma<<<gsq, 256, SQ_SMEM>>>(0, 1);
    k_sqmma<<<gsq, 256, SQ_SMEM>>>(1, 2);
    k_sqmma<<<gsq, 256, SQ_SMEM>>>(2, 3);

    // big HMMA GEMM: blockIdx.x = mt + 4*s (16), blockIdx.y = n tile of 128 (256)
    dim3 gb(16, 256);
    k_bigmma<<<gb, 256, DSMEM_TOTAL>>>(out);
}

// round 13
// speedup vs baseline: 7.9462x; 1.1714x over previous
#include <cuda_runtime.h>
#include <cuda_fp16.h>
#include <math.h>
#include <stdint.h>

#define NNODES 500
#define NP     512
#define NFEAT  32768
#define NEDGE  16000
#define NSCALE 4
#define NCOEF 9
#define DCTN 128

// ---------------- device scratch (static, allocation-free) ----------------
__device__ float g_M [NP * NP];            // M = (L - c0 I)/h  (persists)
__device__ float g_Ta[NP * NP];            // T2
__device__ float g_Tb[NP * NP];            // T3
__device__ float g_Tc[NP * NP];            // T4
__device__ float g_W [NSCALE * NP * NP];   // T5..T8
__device__ float g_deg [NP];
__device__ float g_rlo[NP];
__device__ float g_rhi[NP];
__device__ float g_c0h[2];
__device__ float g_coef[NCOEF];

// Packed, pre-swizzled (SW128) fp16 hi/lo operand tiles.
// slots 0..3: W(0.5),W(1),W(2),W(4); slots 4..7: M,T2,T3,T4
// slot layout: [slot][m_tile(4)][k_chunk(8)] tiles of 128m x 64k (16KB each)
#define NSLOT 8
__device__ __half g_Ah[NSLOT * 4 * 8 * 8192];
__device__ __half g_Al[NSLOT * 4 * 8 * 8192];
__device__ __half g_Bh[256 * 8 * 8192];

// pack one fp32 value into the SW128 fp16 hi/lo tile layout for a slot
__device__ __forceinline__ void packA2(int slot, int m, int k, float v) {
    int tile = ((slot * 4 + (m >> 7)) * 8) + (k >> 6);
    int off = (m & 127) * 128 + (k & 63) * 2;
    off ^= (off >> 3) & 0x70;
    int idx = tile * 8192 + (off >> 1);
    __half h = __float2half(v);
    g_Ah[idx] = h;
    g_Al[idx] = __float2half(v - __half2float(h));
}

// ---------------- graph / Laplacian build ----------------
__global__ void k_zero() {
    int i = blockIdx.x * blockDim.x + threadIdx.x;
    if (i < NP * NP) g_M[i] = 0.f;
    if (i < NP) g_deg[i] = 0.f;
}

__global__ void k_degree(const int* __restrict__ ei) {
    int e = blockIdx.x * blockDim.x + threadIdx.x;
    if (e < NEDGE) atomicAdd(&g_deg[ei[NEDGE + e]], 1.0f);
}

__global__ void k_adj(const int* __restrict__ ei) {
    int e = blockIdx.x * blockDim.x + threadIdx.x;
    if (e < NEDGE) {
        int s = ei[e], d = ei[NEDGE + e];
        float v = -rsqrtf(fmaxf(g_deg[s], 1.0f)) * rsqrtf(fmaxf(g_deg[d], 1.0f));
        g_M[s * NP + d] = v;
        g_M[d * NP + s] = v;
    }
}

// Per-row Gershgorin: one block per row, diag += 1 folded in
__global__ void __launch_bounds__(128) k_rows() {
    __shared__ float red[128];
    int i = blockIdx.x;
    int t = threadIdx.x;
    const float4* row = (const float4*)(g_M + i * NP);
    float4 v = row[t];
    red[t] = fabsf(v.x) + fabsf(v.y) + fabsf(v.z) + fabsf(v.w);
    __syncthreads();
    for (int s = 64; s > 0; s >>= 1) {
        if (t < s) red[t] += red[t + s];
        __syncthreads();
    }
    if (t == 0) {
        float cold = g_M[i * NP + i];
        float rr = red[0] - fabsf(cold);
        float c = cold + ((i < NNODES) ? 1.f : 0.f);
        g_M[i * NP + i] = c;
        g_rlo[i] = c - rr;
        g_rhi[i] = c + rr;
    }
}

// Chebyshev coefs of exp(-s0(c0 + h t)); each block reduces bounds itself.
__global__ void __launch_bounds__(DCTN) k_coef(const float* __restrict__ scales) {
    __shared__ float blo[DCTN], bhi[DCTN];
    __shared__ double red[DCTN];
    int j = threadIdx.x;
    int k = blockIdx.x;
    float lo = 1e30f, hi = -1e30f;
    for (int t = j; t < NP; t += DCTN) {
        lo = fminf(lo, g_rlo[t]);
        hi = fmaxf(hi, g_rhi[t]);
    }
    blo[j] = lo; bhi[j] = hi;
    __syncthreads();
    for (int s = DCTN / 2; s > 0; s >>= 1) {
        if (j < s) {
            blo[j] = fminf(blo[j], blo[j + s]);
            bhi[j] = fmaxf(bhi[j], bhi[j + s]);
        }
        __syncthreads();
    }
    float c0f = 0.5f * (bhi[0] + blo[0]);
    float hf  = fmaxf(0.5f * (bhi[0] - blo[0]), 1e-4f) * 1.0001f;
    if (k == 0 && j == 0) {
        g_c0h[0] = c0f;
        g_c0h[1] = hf;
    }
    const double PI = 3.14159265358979323846;
    double s0 = (double)scales[0];
    double c0 = (double)c0f;
    double h  = (double)hf;
    double th = PI * (j + 0.5) / (double)DCTN;
    red[j] = exp(-s0 * (c0 + h * cos(th))) * cos((double)k * th);
    __syncthreads();
    for (int s = DCTN / 2; s > 0; s >>= 1) {
        if (j < s) red[j] += red[j + s];
        __syncthreads();
    }
    if (j == 0)
        g_coef[k] = (float)(red[0] * ((k == 0) ? 1.0 : 2.0) / (double)DCTN);
}

// M = (L - c0 I)/h in place; also packs slot 4 (hi/lo)
__global__ void k_scaleM() {
    int i = blockIdx.x * blockDim.x + threadIdx.x;
    if (i < NP * NP) {
        int r = i >> 9, c = i & (NP - 1);
        float c0 = g_c0h[0], h = g_c0h[1];
        float diag = (r == c) ? 1.f : 0.f;
        float m = (g_M[i] - c0 * diag) / h;
        g_M[i] = m;
        packA2(4, r, c, m);
    }
}

// W(0.5) = c0 I + c1 M + ... + c8 T8 ; packs fp16 hi/lo slot 0 (no fp32 out)
__global__ void k_sum() {
    int i = blockIdx.x * blockDim.x + threadIdx.x;
    if (i >= NP * NP) return;
    int r = i >> 9, c = i & (NP - 1);
    float v = g_coef[0] * ((r == c) ? 1.f : 0.f)
            + g_coef[1] * g_M[i]
            + g_coef[2] * g_Ta[i]
            + g_coef[3] * g_Tb[i]
            + g_coef[4] * g_Tc[i]
            + g_coef[5] * g_W[i]
            + g_coef[6] * g_W[NP * NP + i]
            + g_coef[7] * g_W[2 * NP * NP + i]
            + g_coef[8] * g_W[3 * NP * NP + i];
    packA2(0, r, c, v);
}

// ---------------- x transpose -> fp16 SW128 tiles ----------------
__global__ void __launch_bounds__(256) k_convX(const float* __restrict__ x) {
    __shared__ float t[32][132];
    int nt = blockIdx.x;
    int kb = blockIdx.y;
    int tid = threadIdx.x;

#pragma unroll
    for (int it = 0; it < 4; it++) {
        int f = tid + it * 256;
        int row = f >> 5, c4 = f & 31;
        int kg = kb * 32 + row;
        float4 v = make_float4(0.f, 0.f, 0.f, 0.f);
        if (kg < NNODES)
            v = *(const float4*)(x + (size_t)kg * NFEAT + nt * 128 + c4 * 4);
        t[row][c4 * 4 + 0] = v.x;
        t[row][c4 * 4 + 1] = v.y;
        t[row][c4 * 4 + 2] = v.z;
        t[row][c4 * 4 + 3] = v.w;
    }
    __syncthreads();

    size_t tile_bytes = (size_t)(nt * 8 + (kb >> 1)) * 16384;
    int halfk = (kb & 1) * 32;
    char* bh = (char*)g_Bh + tile_bytes;

#pragma unroll
    for (int it = 0; it < 2; it++) {
        int j = tid + it * 256;
        int n = j >> 2, q = j & 3;
        __align__(16) __half hs[8];
#pragma unroll
        for (int e = 0; e < 8; e++)
            hs[e] = __float2half(t[q * 8 + e][n]);
        int off = n * 128 + (halfk + q * 8) * 2;
        off ^= (off >> 3) & 0x70;
        *(uint4*)(bh + off) = *(const uint4*)hs;
    }
}

// ---------------- HMMA helpers ----------------
__device__ __forceinline__ void ldmx4(uint32_t* r, uint32_t addr) {
    asm volatile("ldmatrix.sync.aligned.m8n8.x4.shared.b16 {%0,%1,%2,%3}, [%4];"
                 : "=r"(r[0]), "=r"(r[1]), "=r"(r[2]), "=r"(r[3]) : "r"(addr));
}
__device__ __forceinline__ void mma16816(float* c, const uint32_t* a,
                                         const uint32_t* b) {
    asm volatile(
        "mma.sync.aligned.m16n8k16.row.col.f32.f16.f16.f32 "
        "{%0,%1,%2,%3}, {%4,%5,%6,%7}, {%8,%9}, {%0,%1,%2,%3};"
        : "+f"(c[0]), "+f"(c[1]), "+f"(c[2]), "+f"(c[3])
        : "r"(a[0]), "r"(a[1]), "r"(a[2]), "r"(a[3]), "r"(b[0]), "r"(b[1]));
}
__device__ __forceinline__ void cpasync16(uint32_t dst, const void* src) {
    asm volatile("cp.async.cg.shared.global [%0], [%1], 16;"
                 :: "r"(dst), "l"(src) : "memory");
}

// ---------------- generalized 512x512 HMMA 3-term GEMM on packed slots ----
// mode 0: D = 2*A*B - (qid ? I : Q), fp32 write + optional pack to slot so
// mode 1: pack(so) = A*B (no fp32 write)
// A rows from slot sa, B rows from slot sb (all operands symmetric).
struct MMJob {
    int sa, sb;
    const float* Q;
    float* D;
    int qid;
    int so;     // -1 = no pack
    int mode;
};

#define SQ_STAGE  32768
#define SQ_NSTAGE 4
#define SQ_SMEM   (SQ_NSTAGE * SQ_STAGE)

__global__ void __launch_bounds__(256, 1) k_mm3(MMJob j0, MMJob j1,
                                                MMJob j2, MMJob j3) {
    MMJob J = (blockIdx.z == 0) ? j0 : (blockIdx.z == 1) ? j1
            : (blockIdx.z == 2) ? j2 : j3;

    extern __shared__ __align__(1024) char smem[];
    uint32_t sb = (uint32_t)__cvta_generic_to_shared(smem);
    int tid = threadIdx.x, wid = tid >> 5, lid = tid & 31;
    int m0 = blockIdx.y * 64, n0 = blockIdx.x * 64;
    int wm = wid >> 2, wn = wid & 3;   // 2m x 4n warps, warp tile 32m x 16n

    const char* Ahb = (const char*)g_Ah;
    const char* Alb = (const char*)g_Al;

    float acc[2][2][4] = {};

    auto issue = [&](int c) {
        uint32_t dst = sb + (c & (SQ_NSTAGE - 1)) * SQ_STAGE;
        size_t baseA = ((size_t)((J.sa * 4 + (m0 >> 7)) * 8 + c)) * 16384 +
                       (size_t)(m0 & 127) * 128;
        size_t baseB = ((size_t)((J.sb * 4 + (n0 >> 7)) * 8 + c)) * 16384 +
                       (size_t)(n0 & 127) * 128;
#pragma unroll
        for (int it = 0; it < 8; it++) {
            int line = tid + it * 256;          // 2048 lines of 16B
            int reg = line >> 9;                // 0:Ah 1:Al 2:Bh 3:Bl
            uint32_t o = (uint32_t)(line & 511) * 16;
            const char* src;
            if (reg == 0)      src = Ahb + baseA + o;
            else if (reg == 1) src = Alb + baseA + o;
            else if (reg == 2) src = Ahb + baseB + o;
            else               src = Alb + baseB + o;
            cpasync16(dst + (uint32_t)line * 16, src);
        }
        asm volatile("cp.async.commit_group;");
    };

    issue(0);
    issue(1);
    issue(2);

    for (int c = 0; c < 8; c++) {
        asm volatile("cp.async.wait_group 2;");
        __syncthreads();

        uint32_t base = sb + (c & (SQ_NSTAGE - 1)) * SQ_STAGE;
        uint32_t sAh = base, sAl = base + 8192;
        uint32_t sBh = base + 16384, sBl = base + 24576;

#pragma unroll
        for (int kk = 0; kk < 4; kk++) {
            uint32_t ah[2][4], al[2][4], bh[4], bl[4];
#pragma unroll
            for (int i = 0; i < 2; i++) {
                uint32_t off = (uint32_t)(wm * 32 + i * 16 + (lid & 15)) * 128 +
                               kk * 32 + (lid >> 4) * 16;
                off ^= (off >> 3) & 0x70;
                ldmx4(ah[i], sAh + off);
                ldmx4(al[i], sAl + off);
            }
            {
                int nl = wn * 16 + ((lid >> 4) & 1) * 8 + (lid & 7);
                uint32_t off = (uint32_t)nl * 128 +
                               kk * 32 + ((lid >> 3) & 1) * 16;
                off ^= (off >> 3) & 0x70;
                ldmx4(bh, sBh + off);
                ldmx4(bl, sBl + off);
            }
#pragma unroll
            for (int i = 0; i < 2; i++) {
#pragma unroll
                for (int j = 0; j < 2; j++) {
                    mma16816(acc[i][j], ah[i], &bh[j * 2]);
                    mma16816(acc[i][j], ah[i], &bl[j * 2]);
                    mma16816(acc[i][j], al[i], &bh[j * 2]);
                }
            }
        }
        if (c + 3 < 8) issue(c + 3);
        else asm volatile("cp.async.commit_group;");
    }

    // epilogue
    int qrow = lid >> 2, qcol = (lid & 3) * 2;
#pragma unroll
    for (int i = 0; i < 2; i++) {
#pragma unroll
        for (int j = 0; j < 2; j++) {
#pragma unroll
            for (int e = 0; e < 4; e++) {
                int m = m0 + wm * 32 + i * 16 + qrow + (e >> 1) * 8;
                int n = n0 + wn * 16 + j * 8 + qcol + (e & 1);
                float v = acc[i][j][e];
                if (J.mode == 0) {
                    int idx = m * NP + n;
                    float q = J.qid ? ((m == n) ? 1.f : 0.f) : J.Q[idx];
                    v = 2.f * v - q;
                    J.D[idx] = v;
                }
                if (J.so >= 0) packA2(J.so, m, n, v);
            }
        }
    }
}

// ---------------- big GEMM: out[s] = W_s @ x via HMMA fp16 ----------------
// CTA tile 128m x 128n, 3-stage cp.async, 2 CTAs/SM
#define STAGE_BYTES 32768
#define NSTAGE 3
#define DSMEM_TOTAL (NSTAGE * STAGE_BYTES)

__global__ void __launch_bounds__(256, 2) k_bigmma(float* __restrict__ out) {
    extern __shared__ __align__(1024) char smem[];
    uint32_t sb = (uint32_t)__cvta_generic_to_shared(smem);
    int tid = threadIdx.x, wid = tid >> 5, lid = tid & 31;
    int mt = blockIdx.x & 3, s = blockIdx.x >> 2, nt = blockIdx.y;
    int wm0 = (wid >> 2) * 64;    // 2 warp rows (m)
    int wn0 = (wid & 3) * 32;     // 4 warp cols (n)

    const char* pAh = (const char*)(g_Ah + ((size_t)((s * 4 + mt) * 8)) * 8192);

    float acc[4][4][4] = {};

    auto issue = [&](int c) {
        uint32_t dst = sb + (c % NSTAGE) * STAGE_BYTES;
        size_t aoff = (size_t)c * 16384;
        size_t boff = ((size_t)(nt * 8 + c)) * 16384;
#pragma unroll
        for (int it = 0; it < 4; it++) {
            uint32_t o = (uint32_t)(tid + it * 256) * 16;
            cpasync16(dst + o,         pAh + aoff + o);
            cpasync16(dst + 16384 + o, (const char*)g_Bh + boff + o);
        }
        asm volatile("cp.async.commit_group;");
    };

    issue(0);
    issue(1);

    for (int c = 0; c < 8; c++) {
        asm volatile("cp.async.wait_group 1;");
        __syncthreads();
        if (c + 2 < 8) issue(c + 2);
        else asm volatile("cp.async.commit_group;");

        uint32_t base = sb + (c % NSTAGE) * STAGE_BYTES;
        uint32_t sAh = base, sBh = base + 16384;

#pragma unroll
        for (int kk = 0; kk < 4; kk++) {
            uint32_t ah[4][4], bh[2][4];
#pragma unroll
            for (int i = 0; i < 4; i++) {
                uint32_t off = (uint32_t)(wm0 + i * 16 + (lid & 15)) * 128 +
                               kk * 32 + (lid >> 4) * 16;
                off ^= (off >> 3) & 0x70;
                ldmx4(ah[i], sAh + off);
            }
#pragma unroll
            for (int g = 0; g < 2; g++) {
                int nl = wn0 + g * 16 + ((lid >> 4) & 1) * 8 + (lid & 7);
                uint32_t off = (uint32_t)nl * 128 +
                               kk * 32 + ((lid >> 3) & 1) * 16;
                off ^= (off >> 3) & 0x70;
                ldmx4(bh[g], sBh + off);
            }
#pragma unroll
            for (int i = 0; i < 4; i++) {
#pragma unroll
                for (int j = 0; j < 4; j++) {
                    int g = j >> 1, h = (j & 1) * 2;
                    mma16816(acc[i][j], ah[i], &bh[g][h]);
                }
            }
        }
    }

    // epilogue
    int qrow = lid >> 2, qcol = (lid & 3) * 2;
#pragma unroll
    for (int i = 0; i < 4; i++) {
        int m0g = mt * 128 + wm0 + i * 16 + qrow;
#pragma unroll
        for (int j = 0; j < 4; j++) {
            int n = nt * 128 + wn0 + j * 8 + qcol;
            if (m0g < NNODES) {
                size_t idx = ((size_t)s * NNODES + m0g) * NFEAT + n;
                *(float2*)(out + idx) = make_float2(acc[i][j][0], acc[i][j][1]);
            }
            if (m0g + 8 < NNODES) {
                size_t idx = ((size_t)s * NNODES + m0g + 8) * NFEAT + n;
                *(float2*)(out + idx) = make_float2(acc[i][j][2], acc[i][j][3]);
            }
        }
    }
}

// ---------------- launch (single stream — graph-capture safe) ----------------
extern "C" void kernel_launch(void* const* d_in, const int* in_sizes, int n_in,
                              void* d_out, int out_size) {
    const float* x      = (const float*)d_in[0];
    const int*   ei     = (const int*)d_in[1];
    const float* scales = (const float*)d_in[2];
    float* out = (float*)d_out;

    float *pM, *pTa, *pTb, *pTc, *pW;
    cudaGetSymbolAddress((void**)&pM,  g_M);
    cudaGetSymbolAddress((void**)&pTa, g_Ta);
    cudaGetSymbolAddress((void**)&pTb, g_Tb);
    cudaGetSymbolAddress((void**)&pTc, g_Tc);
    cudaGetSymbolAddress((void**)&pW,  g_W);

    static int smem_set = 0;
    if (!smem_set) {
        cudaFuncSetAttribute(k_bigmma, cudaFuncAttributeMaxDynamicSharedMemorySize,
                             DSMEM_TOTAL);
        cudaFuncSetAttribute(k_mm3, cudaFuncAttributeMaxDynamicSharedMemorySize,
                             SQ_SMEM);
        smem_set = 1;
    }

    const size_t NPNP = (size_t)NP * NP;
    float* pW0 = pW;
    float* pW1 = pW + NPNP;
    float* pW2 = pW + 2 * NPNP;
    float* pW3 = pW + 3 * NPNP;

    // build
    k_zero<<<(NP * NP + 255) / 256, 256>>>();
    k_degree<<<(NEDGE + 255) / 256, 256>>>(ei);
    k_adj<<<(NEDGE + 255) / 256, 256>>>(ei);
    k_rows<<<NP, 128>>>();
    k_coef<<<NCOEF, DCTN>>>(scales);
    k_scaleM<<<(NP * NP + 255) / 256, 256>>>();   // packs slot 4

    // x transpose + fp16 pack
    dim3 gx(256, 16);
    k_convX<<<gx, 256>>>(x);

    // Chebyshev via HMMA on packed slots (4=M, 5=T2, 6=T3, 7=T4)
    dim3 gz1(8, 8, 1), gz2(8, 8, 2), gz4(8, 8, 4);
    MMJob JD = {0, 0, nullptr, nullptr, 0, -1, 1};  // dummy filler

    // wave 1: T2 = 2 M M - I  (fp32 Ta + pack slot 5)
    MMJob w1 = {4, 4, nullptr, pTa, 1, 5, 0};
    k_mm3<<<gz1, 256, SQ_SMEM>>>(w1, JD, JD, JD);

    // wave 2: T3 = 2 M T2 - M ; T4 = 2 T2 T2 - I
    MMJob w2a = {4, 5, pM, pTb, 0, 6, 0};
    MMJob w2b = {5, 5, nullptr, pTc, 1, 7, 0};
    k_mm3<<<gz2, 256, SQ_SMEM>>>(w2a, w2b, JD, JD);

    // wave 3: T5 = 2 T2 T3 - M ; T6 = 2 T3 T3 - I ; T7 = 2 T3 T4 - M ; T8 = 2 T4 T4 - I
    MMJob w3a = {5, 6, pM, pW0, 0, -1, 0};
    MMJob w3b = {6, 6, nullptr, pW1, 1, -1, 0};
    MMJob w3c = {6, 7, pM, pW2, 0, -1, 0};
    MMJob w3d = {7, 7, nullptr, pW3, 1, -1, 0};
    k_mm3<<<gz4, 256, SQ_SMEM>>>(w3a, w3b, w3c, w3d);

    // W(0.5) = sum c_k T_k -> packed hi/lo slot 0
    k_sum<<<(NP * NP + 255) / 256, 256>>>();

    // HMMA squaring ladder: 0.5 -> 1 -> 2 -> 4 (slots 0->1->2->3)
    MMJob q1 = {0, 0, nullptr, nullptr, 0, 1, 1};
    MMJob q2 = {1, 1, nullptr, nullptr, 0, 2, 1};
    MMJob q3 = {2, 2, nullptr, nullptr, 0, 3, 1};
    k_mm3<<<gz1, 256, SQ_SMEM>>>(q1, JD, JD, JD);
    k_mm3<<<gz1, 256, SQ_SMEM>>>(q2, JD, JD, JD);
    k_mm3<<<gz1, 256, SQ_SMEM>>>(q3, JD, JD, JD);

    // big HMMA GEMM: blockIdx.x = mt + 4*s (16), blockIdx.y = n tile of 128 (256)
    dim3 gb(16, 256);
    k_bigmma<<<gb, 256, DSMEM_TOTAL>>>(out);
}

// round 14
// speedup vs baseline: 8.1812x; 1.0296x over previous
#include <cuda_runtime.h>
#include <cuda_fp16.h>
#include <math.h>
#include <stdint.h>

#define NNODES 500
#define NP     512
#define NFEAT  32768
#define NEDGE  16000
#define NSCALE 4
#define NCOEF 9
#define DCTN 128

// ---------------- device scratch (static, allocation-free) ----------------
__device__ float g_M [NP * NP];            // M = (L - c0 I)/h  (persists)
__device__ float g_Ta[NP * NP];            // T2
__device__ float g_Tb[NP * NP];            // T3
__device__ float g_Tc[NP * NP];            // T4
__device__ float g_W [NSCALE * NP * NP];   // T5..T8
__device__ float g_deg [NP];
__device__ float g_rlo[NP];
__device__ float g_rhi[NP];
__device__ float g_c0h[2];
__device__ float g_coef[2 * NCOEF];        // set 0: s0 (W 0.5), set 1: 2*s0 (W 1)

// Packed, pre-swizzled (SW128) fp16 hi/lo operand tiles.
// slots 0..3: W(0.5),W(1),W(2),W(4); slots 4..7: M,T2,T3,T4
#define NSLOT 8
__device__ __half g_Ah[NSLOT * 4 * 8 * 8192];
__device__ __half g_Al[NSLOT * 4 * 8 * 8192];
__device__ __half g_Bh[256 * 8 * 8192];

// pack one fp32 value into the SW128 fp16 hi/lo tile layout for a slot
__device__ __forceinline__ void packA2(int slot, int m, int k, float v) {
    int tile = ((slot * 4 + (m >> 7)) * 8) + (k >> 6);
    int off = (m & 127) * 128 + (k & 63) * 2;
    off ^= (off >> 3) & 0x70;
    int idx = tile * 8192 + (off >> 1);
    __half h = __float2half(v);
    g_Ah[idx] = h;
    g_Al[idx] = __float2half(v - __half2float(h));
}

// ---------------- graph / Laplacian build ----------------
__global__ void k_zero() {
    int i = blockIdx.x * blockDim.x + threadIdx.x;
    if (i < NP * NP) g_M[i] = 0.f;
    if (i < NP) g_deg[i] = 0.f;
}

__global__ void k_degree(const int* __restrict__ ei) {
    int e = blockIdx.x * blockDim.x + threadIdx.x;
    if (e < NEDGE) atomicAdd(&g_deg[ei[NEDGE + e]], 1.0f);
}

__global__ void k_adj(const int* __restrict__ ei) {
    int e = blockIdx.x * blockDim.x + threadIdx.x;
    if (e < NEDGE) {
        int s = ei[e], d = ei[NEDGE + e];
        float v = -rsqrtf(fmaxf(g_deg[s], 1.0f)) * rsqrtf(fmaxf(g_deg[d], 1.0f));
        g_M[s * NP + d] = v;
        g_M[d * NP + s] = v;
    }
}

// Per-row Gershgorin: one block per row, diag += 1 folded in
__global__ void __launch_bounds__(128) k_rows() {
    __shared__ float red[128];
    int i = blockIdx.x;
    int t = threadIdx.x;
    const float4* row = (const float4*)(g_M + i * NP);
    float4 v = row[t];
    red[t] = fabsf(v.x) + fabsf(v.y) + fabsf(v.z) + fabsf(v.w);
    __syncthreads();
    for (int s = 64; s > 0; s >>= 1) {
        if (t < s) red[t] += red[t + s];
        __syncthreads();
    }
    if (t == 0) {
        float cold = g_M[i * NP + i];
        float rr = red[0] - fabsf(cold);
        float c = cold + ((i < NNODES) ? 1.f : 0.f);
        g_M[i * NP + i] = c;
        g_rlo[i] = c - rr;
        g_rhi[i] = c + rr;
    }
}

// Chebyshev coefs of exp(-s(c0 + h t)) for s in {s0, 2*s0}; grid (NCOEF, 2).
__global__ void __launch_bounds__(DCTN) k_coef(const float* __restrict__ scales) {
    __shared__ float blo[DCTN], bhi[DCTN];
    __shared__ double red[DCTN];
    int j = threadIdx.x;
    int k = blockIdx.x;
    int set = blockIdx.y;
    float lo = 1e30f, hi = -1e30f;
    for (int t = j; t < NP; t += DCTN) {
        lo = fminf(lo, g_rlo[t]);
        hi = fmaxf(hi, g_rhi[t]);
    }
    blo[j] = lo; bhi[j] = hi;
    __syncthreads();
    for (int s = DCTN / 2; s > 0; s >>= 1) {
        if (j < s) {
            blo[j] = fminf(blo[j], blo[j + s]);
            bhi[j] = fmaxf(bhi[j], bhi[j + s]);
        }
        __syncthreads();
    }
    float c0f = 0.5f * (bhi[0] + blo[0]);
    float hf  = fmaxf(0.5f * (bhi[0] - blo[0]), 1e-4f) * 1.0001f;
    if (k == 0 && set == 0 && j == 0) {
        g_c0h[0] = c0f;
        g_c0h[1] = hf;
    }
    const double PI = 3.14159265358979323846;
    double s0 = (double)scales[0] * (double)(set + 1);
    double c0 = (double)c0f;
    double h  = (double)hf;
    double th = PI * (j + 0.5) / (double)DCTN;
    red[j] = exp(-s0 * (c0 + h * cos(th))) * cos((double)k * th);
    __syncthreads();
    for (int s = DCTN / 2; s > 0; s >>= 1) {
        if (j < s) red[j] += red[j + s];
        __syncthreads();
    }
    if (j == 0)
        g_coef[set * NCOEF + k] =
            (float)(red[0] * ((k == 0) ? 1.0 : 2.0) / (double)DCTN);
}

// M = (L - c0 I)/h in place; also packs slot 4 (hi/lo)
__global__ void k_scaleM() {
    int i = blockIdx.x * blockDim.x + threadIdx.x;
    if (i < NP * NP) {
        int r = i >> 9, c = i & (NP - 1);
        float c0 = g_c0h[0], h = g_c0h[1];
        float diag = (r == c) ? 1.f : 0.f;
        float m = (g_M[i] - c0 * diag) / h;
        g_M[i] = m;
        packA2(4, r, c, m);
    }
}

// W(0.5)->slot0 and W(1)->slot1 from the same T basis (two coef sets)
__global__ void k_sum() {
    int i = blockIdx.x * blockDim.x + threadIdx.x;
    if (i >= NP * NP) return;
    int r = i >> 9, c = i & (NP - 1);
    float tv[NCOEF];
    tv[0] = (r == c) ? 1.f : 0.f;
    tv[1] = g_M[i];
    tv[2] = g_Ta[i];
    tv[3] = g_Tb[i];
    tv[4] = g_Tc[i];
    tv[5] = g_W[i];
    tv[6] = g_W[NP * NP + i];
    tv[7] = g_W[2 * NP * NP + i];
    tv[8] = g_W[3 * NP * NP + i];
    float v0 = 0.f, v1 = 0.f;
#pragma unroll
    for (int k = 0; k < NCOEF; k++) {
        v0 += g_coef[k] * tv[k];
        v1 += g_coef[NCOEF + k] * tv[k];
    }
    packA2(0, r, c, v0);
    packA2(1, r, c, v1);
}

// ---------------- x transpose -> fp16 SW128 tiles ----------------
__global__ void __launch_bounds__(256) k_convX(const float* __restrict__ x) {
    __shared__ float t[32][132];
    int nt = blockIdx.x;
    int kb = blockIdx.y;
    int tid = threadIdx.x;

#pragma unroll
    for (int it = 0; it < 4; it++) {
        int f = tid + it * 256;
        int row = f >> 5, c4 = f & 31;
        int kg = kb * 32 + row;
        float4 v = make_float4(0.f, 0.f, 0.f, 0.f);
        if (kg < NNODES)
            v = *(const float4*)(x + (size_t)kg * NFEAT + nt * 128 + c4 * 4);
        t[row][c4 * 4 + 0] = v.x;
        t[row][c4 * 4 + 1] = v.y;
        t[row][c4 * 4 + 2] = v.z;
        t[row][c4 * 4 + 3] = v.w;
    }
    __syncthreads();

    size_t tile_bytes = (size_t)(nt * 8 + (kb >> 1)) * 16384;
    int halfk = (kb & 1) * 32;
    char* bh = (char*)g_Bh + tile_bytes;

#pragma unroll
    for (int it = 0; it < 2; it++) {
        int j = tid + it * 256;
        int n = j >> 2, q = j & 3;
        __align__(16) __half hs[8];
#pragma unroll
        for (int e = 0; e < 8; e++)
            hs[e] = __float2half(t[q * 8 + e][n]);
        int off = n * 128 + (halfk + q * 8) * 2;
        off ^= (off >> 3) & 0x70;
        *(uint4*)(bh + off) = *(const uint4*)hs;
    }
}

// ---------------- HMMA helpers ----------------
__device__ __forceinline__ void ldmx4(uint32_t* r, uint32_t addr) {
    asm volatile("ldmatrix.sync.aligned.m8n8.x4.shared.b16 {%0,%1,%2,%3}, [%4];"
                 : "=r"(r[0]), "=r"(r[1]), "=r"(r[2]), "=r"(r[3]) : "r"(addr));
}
__device__ __forceinline__ void mma16816(float* c, const uint32_t* a,
                                         const uint32_t* b) {
    asm volatile(
        "mma.sync.aligned.m16n8k16.row.col.f32.f16.f16.f32 "
        "{%0,%1,%2,%3}, {%4,%5,%6,%7}, {%8,%9}, {%0,%1,%2,%3};"
        : "+f"(c[0]), "+f"(c[1]), "+f"(c[2]), "+f"(c[3])
        : "r"(a[0]), "r"(a[1]), "r"(a[2]), "r"(a[3]), "r"(b[0]), "r"(b[1]));
}
__device__ __forceinline__ void cpasync16(uint32_t dst, const void* src) {
    asm volatile("cp.async.cg.shared.global [%0], [%1], 16;"
                 :: "r"(dst), "l"(src) : "memory");
}

// ---------------- generalized 512x512 HMMA 3-term GEMM on packed slots ----
struct MMJob {
    int sa, sb;
    const float* Q;
    float* D;
    int qid;
    int so;     // -1 = no pack
    int mode;   // 0: D=2AB-Q (+pack), 1: pack = AB
};

#define SQ_STAGE  32768
#define SQ_NSTAGE 4
#define SQ_SMEM   (SQ_NSTAGE * SQ_STAGE)

__global__ void __launch_bounds__(256, 1) k_mm3(MMJob j0, MMJob j1,
                                                MMJob j2, MMJob j3) {
    MMJob J = (blockIdx.z == 0) ? j0 : (blockIdx.z == 1) ? j1
            : (blockIdx.z == 2) ? j2 : j3;

    extern __shared__ __align__(1024) char smem[];
    uint32_t sb = (uint32_t)__cvta_generic_to_shared(smem);
    int tid = threadIdx.x, wid = tid >> 5, lid = tid & 31;
    int m0 = blockIdx.y * 64, n0 = blockIdx.x * 64;
    int wm = wid >> 2, wn = wid & 3;   // 2m x 4n warps, warp tile 32m x 16n

    const char* Ahb = (const char*)g_Ah;
    const char* Alb = (const char*)g_Al;

    float acc[2][2][4] = {};

    auto issue = [&](int c) {
        uint32_t dst = sb + (c & (SQ_NSTAGE - 1)) * SQ_STAGE;
        size_t baseA = ((size_t)((J.sa * 4 + (m0 >> 7)) * 8 + c)) * 16384 +
                       (size_t)(m0 & 127) * 128;
        size_t baseB = ((size_t)((J.sb * 4 + (n0 >> 7)) * 8 + c)) * 16384 +
                       (size_t)(n0 & 127) * 128;
#pragma unroll
        for (int it = 0; it < 8; it++) {
            int line = tid + it * 256;
            int reg = line >> 9;                // 0:Ah 1:Al 2:Bh 3:Bl
            uint32_t o = (uint32_t)(line & 511) * 16;
            const char* src;
            if (reg == 0)      src = Ahb + baseA + o;
            else if (reg == 1) src = Alb + baseA + o;
            else if (reg == 2) src = Ahb + baseB + o;
            else               src = Alb + baseB + o;
            cpasync16(dst + (uint32_t)line * 16, src);
        }
        asm volatile("cp.async.commit_group;");
    };

    issue(0);
    issue(1);
    issue(2);

    for (int c = 0; c < 8; c++) {
        asm volatile("cp.async.wait_group 2;");
        __syncthreads();

        uint32_t base = sb + (c & (SQ_NSTAGE - 1)) * SQ_STAGE;
        uint32_t sAh = base, sAl = base + 8192;
        uint32_t sBh = base + 16384, sBl = base + 24576;

#pragma unroll
        for (int kk = 0; kk < 4; kk++) {
            uint32_t ah[2][4], al[2][4], bh[4], bl[4];
#pragma unroll
            for (int i = 0; i < 2; i++) {
                uint32_t off = (uint32_t)(wm * 32 + i * 16 + (lid & 15)) * 128 +
                               kk * 32 + (lid >> 4) * 16;
                off ^= (off >> 3) & 0x70;
                ldmx4(ah[i], sAh + off);
                ldmx4(al[i], sAl + off);
            }
            {
                int nl = wn * 16 + ((lid >> 4) & 1) * 8 + (lid & 7);
                uint32_t off = (uint32_t)nl * 128 +
                               kk * 32 + ((lid >> 3) & 1) * 16;
                off ^= (off >> 3) & 0x70;
                ldmx4(bh, sBh + off);
                ldmx4(bl, sBl + off);
            }
#pragma unroll
            for (int i = 0; i < 2; i++) {
#pragma unroll
                for (int j = 0; j < 2; j++) {
                    mma16816(acc[i][j], ah[i], &bh[j * 2]);
                    mma16816(acc[i][j], ah[i], &bl[j * 2]);
                    mma16816(acc[i][j], al[i], &bh[j * 2]);
                }
            }
        }
        if (c + 3 < 8) issue(c + 3);
        else asm volatile("cp.async.commit_group;");
    }

    // epilogue
    int qrow = lid >> 2, qcol = (lid & 3) * 2;
#pragma unroll
    for (int i = 0; i < 2; i++) {
#pragma unroll
        for (int j = 0; j < 2; j++) {
#pragma unroll
            for (int e = 0; e < 4; e++) {
                int m = m0 + wm * 32 + i * 16 + qrow + (e >> 1) * 8;
                int n = n0 + wn * 16 + j * 8 + qcol + (e & 1);
                float v = acc[i][j][e];
                if (J.mode == 0) {
                    int idx = m * NP + n;
                    float q = J.qid ? ((m == n) ? 1.f : 0.f) : J.Q[idx];
                    v = 2.f * v - q;
                    J.D[idx] = v;
                }
                if (J.so >= 0) packA2(J.so, m, n, v);
            }
        }
    }
}

// ---------------- big GEMM: out[s] = W_s @ x via HMMA fp16 ----------------
// CTA tile 128m x 128n, 3-stage cp.async, 2 CTAs/SM
#define STAGE_BYTES 32768
#define NSTAGE 3
#define DSMEM_TOTAL (NSTAGE * STAGE_BYTES)

__global__ void __launch_bounds__(256, 2) k_bigmma(float* __restrict__ out) {
    extern __shared__ __align__(1024) char smem[];
    uint32_t sb = (uint32_t)__cvta_generic_to_shared(smem);
    int tid = threadIdx.x, wid = tid >> 5, lid = tid & 31;
    int mt = blockIdx.x & 3, s = blockIdx.x >> 2, nt = blockIdx.y;
    int wm0 = (wid >> 2) * 64;
    int wn0 = (wid & 3) * 32;

    const char* pAh = (const char*)(g_Ah + ((size_t)((s * 4 + mt) * 8)) * 8192);

    float acc[4][4][4] = {};

    auto issue = [&](int c) {
        uint32_t dst = sb + (c % NSTAGE) * STAGE_BYTES;
        size_t aoff = (size_t)c * 16384;
        size_t boff = ((size_t)(nt * 8 + c)) * 16384;
#pragma unroll
        for (int it = 0; it < 4; it++) {
            uint32_t o = (uint32_t)(tid + it * 256) * 16;
            cpasync16(dst + o,         pAh + aoff + o);
            cpasync16(dst + 16384 + o, (const char*)g_Bh + boff + o);
        }
        asm volatile("cp.async.commit_group;");
    };

    issue(0);
    issue(1);

    for (int c = 0; c < 8; c++) {
        asm volatile("cp.async.wait_group 1;");
        __syncthreads();
        if (c + 2 < 8) issue(c + 2);
        else asm volatile("cp.async.commit_group;");

        uint32_t base = sb + (c % NSTAGE) * STAGE_BYTES;
        uint32_t sAh = base, sBh = base + 16384;

#pragma unroll
        for (int kk = 0; kk < 4; kk++) {
            uint32_t ah[4][4], bh[2][4];
#pragma unroll
            for (int i = 0; i < 4; i++) {
                uint32_t off = (uint32_t)(wm0 + i * 16 + (lid & 15)) * 128 +
                               kk * 32 + (lid >> 4) * 16;
                off ^= (off >> 3) & 0x70;
                ldmx4(ah[i], sAh + off);
            }
#pragma unroll
            for (int g = 0; g < 2; g++) {
                int nl = wn0 + g * 16 + ((lid >> 4) & 1) * 8 + (lid & 7);
                uint32_t off = (uint32_t)nl * 128 +
                               kk * 32 + ((lid >> 3) & 1) * 16;
                off ^= (off >> 3) & 0x70;
                ldmx4(bh[g], sBh + off);
            }
#pragma unroll
            for (int i = 0; i < 4; i++) {
#pragma unroll
                for (int j = 0; j < 4; j++) {
                    int g = j >> 1, h = (j & 1) * 2;
                    mma16816(acc[i][j], ah[i], &bh[g][h]);
                }
            }
        }
    }

    // epilogue
    int qrow = lid >> 2, qcol = (lid & 3) * 2;
#pragma unroll
    for (int i = 0; i < 4; i++) {
        int m0g = mt * 128 + wm0 + i * 16 + qrow;
#pragma unroll
        for (int j = 0; j < 4; j++) {
            int n = nt * 128 + wn0 + j * 8 + qcol;
            if (m0g < NNODES) {
                size_t idx = ((size_t)s * NNODES + m0g) * NFEAT + n;
                *(float2*)(out + idx) = make_float2(acc[i][j][0], acc[i][j][1]);
            }
            if (m0g + 8 < NNODES) {
                size_t idx = ((size_t)s * NNODES + m0g + 8) * NFEAT + n;
                *(float2*)(out + idx) = make_float2(acc[i][j][2], acc[i][j][3]);
            }
        }
    }
}

// ---------------- launch (single stream — graph-capture safe) ----------------
extern "C" void kernel_launch(void* const* d_in, const int* in_sizes, int n_in,
                              void* d_out, int out_size) {
    const float* x      = (const float*)d_in[0];
    const int*   ei     = (const int*)d_in[1];
    const float* scales = (const float*)d_in[2];
    float* out = (float*)d_out;

    float *pM, *pTa, *pTb, *pTc, *pW;
    cudaGetSymbolAddress((void**)&pM,  g_M);
    cudaGetSymbolAddress((void**)&pTa, g_Ta);
    cudaGetSymbolAddress((void**)&pTb, g_Tb);
    cudaGetSymbolAddress((void**)&pTc, g_Tc);
    cudaGetSymbolAddress((void**)&pW,  g_W);

    static int smem_set = 0;
    if (!smem_set) {
        cudaFuncSetAttribute(k_bigmma, cudaFuncAttributeMaxDynamicSharedMemorySize,
                             DSMEM_TOTAL);
        cudaFuncSetAttribute(k_mm3, cudaFuncAttributeMaxDynamicSharedMemorySize,
                             SQ_SMEM);
        smem_set = 1;
    }

    const size_t NPNP = (size_t)NP * NP;
    float* pW0 = pW;
    float* pW1 = pW + NPNP;
    float* pW2 = pW + 2 * NPNP;
    float* pW3 = pW + 3 * NPNP;

    // build
    k_zero<<<(NP * NP + 255) / 256, 256>>>();
    k_degree<<<(NEDGE + 255) / 256, 256>>>(ei);
    k_adj<<<(NEDGE + 255) / 256, 256>>>(ei);
    k_rows<<<NP, 128>>>();
    dim3 gc(NCOEF, 2);
    k_coef<<<gc, DCTN>>>(scales);
    k_scaleM<<<(NP * NP + 255) / 256, 256>>>();   // packs slot 4

    // x transpose + fp16 pack
    dim3 gx(256, 16);
    k_convX<<<gx, 256>>>(x);

    // Chebyshev via HMMA on packed slots (4=M, 5=T2, 6=T3, 7=T4)
    dim3 gz1(8, 8, 1), gz2(8, 8, 2), gz4(8, 8, 4);
    MMJob JD = {0, 0, nullptr, nullptr, 0, -1, 1};  // dummy filler

    // wave 1: T2 = 2 M M - I  (fp32 Ta + pack slot 5)
    MMJob w1 = {4, 4, nullptr, pTa, 1, 5, 0};
    k_mm3<<<gz1, 256, SQ_SMEM>>>(w1, JD, JD, JD);

    // wave 2: T3 = 2 M T2 - M ; T4 = 2 T2 T2 - I
    MMJob w2a = {4, 5, pM, pTb, 0, 6, 0};
    MMJob w2b = {5, 5, nullptr, pTc, 1, 7, 0};
    k_mm3<<<gz2, 256, SQ_SMEM>>>(w2a, w2b, JD, JD);

    // wave 3: T5 = 2 T2 T3 - M ; T6 = 2 T3 T3 - I ; T7 = 2 T3 T4 - M ; T8 = 2 T4 T4 - I
    MMJob w3a = {5, 6, pM, pW0, 0, -1, 0};
    MMJob w3b = {6, 6, nullptr, pW1, 1, -1, 0};
    MMJob w3c = {6, 7, pM, pW2, 0, -1, 0};
    MMJob w3d = {7, 7, nullptr, pW3, 1, -1, 0};
    k_mm3<<<gz4, 256, SQ_SMEM>>>(w3a, w3b, w3c, w3d);

    // W(0.5) -> slot 0 and W(1) -> slot 1 (dual coefficient sets)
    k_sum<<<(NP * NP + 255) / 256, 256>>>();

    // HMMA squaring ladder: 1 -> 2 -> 4 (slots 1->2->3)
    MMJob q2 = {1, 1, nullptr, nullptr, 0, 2, 1};
    MMJob q3 = {2, 2, nullptr, nullptr, 0, 3, 1};
    k_mm3<<<gz1, 256, SQ_SMEM>>>(q2, JD, JD, JD);
    k_mm3<<<gz1, 256, SQ_SMEM>>>(q3, JD, JD, JD);

    // big HMMA GEMM: blockIdx.x = mt + 4*s (16), blockIdx.y = n tile of 128 (256)
    dim3 gb(16, 256);
    k_bigmma<<<gb, 256, DSMEM_TOTAL>>>(out);
}

// round 16
// speedup vs baseline: 8.1899x; 1.0011x over previous
#include <cuda_runtime.h>
#include <cuda_fp16.h>
#include <math.h>
#include <stdint.h>

#define NNODES 500
#define NP     512
#define NFEAT  32768
#define NEDGE  16000
#define NSCALE 4
#define NCOEF 9
#define DCTN 128

// ---------------- device scratch (static, allocation-free) ----------------
__device__ float g_M [NP * NP];            // M = (L - c0 I)/h  (persists)
__device__ float g_Ta[NP * NP];            // T2
__device__ float g_Tb[NP * NP];            // T3
__device__ float g_Tc[NP * NP];            // T4
__device__ float g_W [NSCALE * NP * NP];   // T5..T8
__device__ float g_deg [NP];
__device__ float g_rlo[NP];
__device__ float g_rhi[NP];
__device__ float g_c0h[2];
__device__ float g_coef[2 * NCOEF];        // set 0: s0 (W 0.5), set 1: 2*s0 (W 1)

// Packed, pre-swizzled (SW128) fp16 hi/lo operand tiles.
// slots 0..3: W(0.5),W(1),W(2),W(4); slots 4..7: M,T2,T3,T4
#define NSLOT 8
__device__ __half g_Ah[NSLOT * 4 * 8 * 8192];
__device__ __half g_Al[NSLOT * 4 * 8 * 8192];
__device__ __half g_Bh[256 * 8 * 8192];

// pack one fp32 value into the SW128 fp16 hi/lo tile layout for a slot
__device__ __forceinline__ void packA2(int slot, int m, int k, float v) {
    int tile = ((slot * 4 + (m >> 7)) * 8) + (k >> 6);
    int off = (m & 127) * 128 + (k & 63) * 2;
    off ^= (off >> 3) & 0x70;
    int idx = tile * 8192 + (off >> 1);
    __half h = __float2half(v);
    g_Ah[idx] = h;
    g_Al[idx] = __float2half(v - __half2float(h));
}

// ---------------- graph / Laplacian build ----------------
__global__ void k_zero() {
    int i = blockIdx.x * blockDim.x + threadIdx.x;
    if (i < NP * NP) g_M[i] = 0.f;
    if (i < NP) g_deg[i] = 0.f;
}

__global__ void k_degree(const int* __restrict__ ei) {
    int e = blockIdx.x * blockDim.x + threadIdx.x;
    if (e < NEDGE) atomicAdd(&g_deg[ei[NEDGE + e]], 1.0f);
}

__global__ void k_adj(const int* __restrict__ ei) {
    int e = blockIdx.x * blockDim.x + threadIdx.x;
    if (e < NEDGE) {
        int s = ei[e], d = ei[NEDGE + e];
        float v = -rsqrtf(fmaxf(g_deg[s], 1.0f)) * rsqrtf(fmaxf(g_deg[d], 1.0f));
        g_M[s * NP + d] = v;
        g_M[d * NP + s] = v;
    }
}

// Per-row Gershgorin: one block per row, diag += 1 folded in
__global__ void __launch_bounds__(128) k_rows() {
    __shared__ float red[128];
    int i = blockIdx.x;
    int t = threadIdx.x;
    const float4* row = (const float4*)(g_M + i * NP);
    float4 v = row[t];
    red[t] = fabsf(v.x) + fabsf(v.y) + fabsf(v.z) + fabsf(v.w);
    __syncthreads();
    for (int s = 64; s > 0; s >>= 1) {
        if (t < s) red[t] += red[t + s];
        __syncthreads();
    }
    if (t == 0) {
        float cold = g_M[i * NP + i];
        float rr = red[0] - fabsf(cold);
        float c = cold + ((i < NNODES) ? 1.f : 0.f);
        g_M[i * NP + i] = c;
        g_rlo[i] = c - rr;
        g_rhi[i] = c + rr;
    }
}

// Chebyshev coefs of exp(-s(c0 + h t)) for s in {s0, 2*s0}; grid (NCOEF, 2).
__global__ void __launch_bounds__(DCTN) k_coef(const float* __restrict__ scales) {
    __shared__ float blo[DCTN], bhi[DCTN];
    __shared__ double red[DCTN];
    int j = threadIdx.x;
    int k = blockIdx.x;
    int set = blockIdx.y;
    float lo = 1e30f, hi = -1e30f;
    for (int t = j; t < NP; t += DCTN) {
        lo = fminf(lo, g_rlo[t]);
        hi = fmaxf(hi, g_rhi[t]);
    }
    blo[j] = lo; bhi[j] = hi;
    __syncthreads();
    for (int s = DCTN / 2; s > 0; s >>= 1) {
        if (j < s) {
            blo[j] = fminf(blo[j], blo[j + s]);
            bhi[j] = fmaxf(bhi[j], bhi[j + s]);
        }
        __syncthreads();
    }
    float c0f = 0.5f * (bhi[0] + blo[0]);
    float hf  = fmaxf(0.5f * (bhi[0] - blo[0]), 1e-4f) * 1.0001f;
    if (k == 0 && set == 0 && j == 0) {
        g_c0h[0] = c0f;
        g_c0h[1] = hf;
    }
    const double PI = 3.14159265358979323846;
    double s0 = (double)scales[0] * (double)(set + 1);
    double c0 = (double)c0f;
    double h  = (double)hf;
    double th = PI * (j + 0.5) / (double)DCTN;
    red[j] = exp(-s0 * (c0 + h * cos(th))) * cos((double)k * th);
    __syncthreads();
    for (int s = DCTN / 2; s > 0; s >>= 1) {
        if (j < s) red[j] += red[j + s];
        __syncthreads();
    }
    if (j == 0)
        g_coef[set * NCOEF + k] =
            (float)(red[0] * ((k == 0) ? 1.0 : 2.0) / (double)DCTN);
}

// M = (L - c0 I)/h in place; also packs slot 4 (hi/lo)
__global__ void k_scaleM() {
    int i = blockIdx.x * blockDim.x + threadIdx.x;
    if (i < NP * NP) {
        int r = i >> 9, c = i & (NP - 1);
        float c0 = g_c0h[0], h = g_c0h[1];
        float diag = (r == c) ? 1.f : 0.f;
        float m = (g_M[i] - c0 * diag) / h;
        g_M[i] = m;
        packA2(4, r, c, m);
    }
}

// W(0.5)->slot0 and W(1)->slot1 from the same T basis (two coef sets)
__global__ void k_sum() {
    int i = blockIdx.x * blockDim.x + threadIdx.x;
    if (i >= NP * NP) return;
    int r = i >> 9, c = i & (NP - 1);
    float tv[NCOEF];
    tv[0] = (r == c) ? 1.f : 0.f;
    tv[1] = g_M[i];
    tv[2] = g_Ta[i];
    tv[3] = g_Tb[i];
    tv[4] = g_Tc[i];
    tv[5] = g_W[i];
    tv[6] = g_W[NP * NP + i];
    tv[7] = g_W[2 * NP * NP + i];
    tv[8] = g_W[3 * NP * NP + i];
    float v0 = 0.f, v1 = 0.f;
#pragma unroll
    for (int k = 0; k < NCOEF; k++) {
        v0 += g_coef[k] * tv[k];
        v1 += g_coef[NCOEF + k] * tv[k];
    }
    packA2(0, r, c, v0);
    packA2(1, r, c, v1);
}

// ---------------- x transpose -> fp16 SW128 tiles ----------------
__global__ void __launch_bounds__(256) k_convX(const float* __restrict__ x) {
    __shared__ float t[32][132];
    int nt = blockIdx.x;
    int kb = blockIdx.y;
    int tid = threadIdx.x;

#pragma unroll
    for (int it = 0; it < 4; it++) {
        int f = tid + it * 256;
        int row = f >> 5, c4 = f & 31;
        int kg = kb * 32 + row;
        float4 v = make_float4(0.f, 0.f, 0.f, 0.f);
        if (kg < NNODES)
            v = *(const float4*)(x + (size_t)kg * NFEAT + nt * 128 + c4 * 4);
        t[row][c4 * 4 + 0] = v.x;
        t[row][c4 * 4 + 1] = v.y;
        t[row][c4 * 4 + 2] = v.z;
        t[row][c4 * 4 + 3] = v.w;
    }
    __syncthreads();

    size_t tile_bytes = (size_t)(nt * 8 + (kb >> 1)) * 16384;
    int halfk = (kb & 1) * 32;
    char* bh = (char*)g_Bh + tile_bytes;

#pragma unroll
    for (int it = 0; it < 2; it++) {
        int j = tid + it * 256;
        int n = j >> 2, q = j & 3;
        __align__(16) __half hs[8];
#pragma unroll
        for (int e = 0; e < 8; e++)
            hs[e] = __float2half(t[q * 8 + e][n]);
        int off = n * 128 + (halfk + q * 8) * 2;
        off ^= (off >> 3) & 0x70;
        *(uint4*)(bh + off) = *(const uint4*)hs;
    }
}

// ---------------- HMMA helpers ----------------
__device__ __forceinline__ void ldmx4(uint32_t* r, uint32_t addr) {
    asm volatile("ldmatrix.sync.aligned.m8n8.x4.shared.b16 {%0,%1,%2,%3}, [%4];"
                 : "=r"(r[0]), "=r"(r[1]), "=r"(r[2]), "=r"(r[3]) : "r"(addr));
}
__device__ __forceinline__ void mma16816(float* c, const uint32_t* a,
                                         const uint32_t* b) {
    asm volatile(
        "mma.sync.aligned.m16n8k16.row.col.f32.f16.f16.f32 "
        "{%0,%1,%2,%3}, {%4,%5,%6,%7}, {%8,%9}, {%0,%1,%2,%3};"
        : "+f"(c[0]), "+f"(c[1]), "+f"(c[2]), "+f"(c[3])
        : "r"(a[0]), "r"(a[1]), "r"(a[2]), "r"(a[3]), "r"(b[0]), "r"(b[1]));
}
__device__ __forceinline__ void cpasync16(uint32_t dst, const void* src) {
    asm volatile("cp.async.cg.shared.global [%0], [%1], 16;"
                 :: "r"(dst), "l"(src) : "memory");
}

// ---------------- generalized 512x512 HMMA 3-term GEMM on packed slots ----
struct MMJob {
    int sa, sb;
    const float* Q;
    float* D;
    int qid;
    int so;     // -1 = no pack
    int mode;   // 0: D=2AB-Q (+pack), 1: pack = AB
};

#define SQ_STAGE  32768
#define SQ_NSTAGE 4
#define SQ_SMEM   (SQ_NSTAGE * SQ_STAGE)

__global__ void __launch_bounds__(256, 1) k_mm3(MMJob j0, MMJob j1,
                                                MMJob j2, MMJob j3) {
    MMJob J = (blockIdx.z == 0) ? j0 : (blockIdx.z == 1) ? j1
            : (blockIdx.z == 2) ? j2 : j3;

    extern __shared__ __align__(1024) char smem[];
    uint32_t sb = (uint32_t)__cvta_generic_to_shared(smem);
    int tid = threadIdx.x, wid = tid >> 5, lid = tid & 31;
    int m0 = blockIdx.y * 64, n0 = blockIdx.x * 64;
    int wm = wid >> 2, wn = wid & 3;   // 2m x 4n warps, warp tile 32m x 16n

    const char* Ahb = (const char*)g_Ah;
    const char* Alb = (const char*)g_Al;

    float acc[2][2][4] = {};

    auto issue = [&](int c) {
        uint32_t dst = sb + (c & (SQ_NSTAGE - 1)) * SQ_STAGE;
        size_t baseA = ((size_t)((J.sa * 4 + (m0 >> 7)) * 8 + c)) * 16384 +
                       (size_t)(m0 & 127) * 128;
        size_t baseB = ((size_t)((J.sb * 4 + (n0 >> 7)) * 8 + c)) * 16384 +
                       (size_t)(n0 & 127) * 128;
#pragma unroll
        for (int it = 0; it < 8; it++) {
            int line = tid + it * 256;
            int reg = line >> 9;                // 0:Ah 1:Al 2:Bh 3:Bl
            uint32_t o = (uint32_t)(line & 511) * 16;
            const char* src;
            if (reg == 0)      src = Ahb + baseA + o;
            else if (reg == 1) src = Alb + baseA + o;
            else if (reg == 2) src = Ahb + baseB + o;
            else               src = Alb + baseB + o;
            cpasync16(dst + (uint32_t)line * 16, src);
        }
        asm volatile("cp.async.commit_group;");
    };

    issue(0);
    issue(1);
    issue(2);

    for (int c = 0; c < 8; c++) {
        asm volatile("cp.async.wait_group 2;");
        __syncthreads();

        uint32_t base = sb + (c & (SQ_NSTAGE - 1)) * SQ_STAGE;
        uint32_t sAh = base, sAl = base + 8192;
        uint32_t sBh = base + 16384, sBl = base + 24576;

#pragma unroll
        for (int kk = 0; kk < 4; kk++) {
            uint32_t ah[2][4], al[2][4], bh[4], bl[4];
#pragma unroll
            for (int i = 0; i < 2; i++) {
                uint32_t off = (uint32_t)(wm * 32 + i * 16 + (lid & 15)) * 128 +
                               kk * 32 + (lid >> 4) * 16;
                off ^= (off >> 3) & 0x70;
                ldmx4(ah[i], sAh + off);
                ldmx4(al[i], sAl + off);
            }
            {
                int nl = wn * 16 + ((lid >> 4) & 1) * 8 + (lid & 7);
                uint32_t off = (uint32_t)nl * 128 +
                               kk * 32 + ((lid >> 3) & 1) * 16;
                off ^= (off >> 3) & 0x70;
                ldmx4(bh, sBh + off);
                ldmx4(bl, sBl + off);
            }
#pragma unroll
            for (int i = 0; i < 2; i++) {
#pragma unroll
                for (int j = 0; j < 2; j++) {
                    mma16816(acc[i][j], ah[i], &bh[j * 2]);
                    mma16816(acc[i][j], ah[i], &bl[j * 2]);
                    mma16816(acc[i][j], al[i], &bh[j * 2]);
                }
            }
        }
        if (c + 3 < 8) issue(c + 3);
        else asm volatile("cp.async.commit_group;");
    }

    // epilogue
    int qrow = lid >> 2, qcol = (lid & 3) * 2;
#pragma unroll
    for (int i = 0; i < 2; i++) {
#pragma unroll
        for (int j = 0; j < 2; j++) {
#pragma unroll
            for (int e = 0; e < 4; e++) {
                int m = m0 + wm * 32 + i * 16 + qrow + (e >> 1) * 8;
                int n = n0 + wn * 16 + j * 8 + qcol + (e & 1);
                float v = acc[i][j][e];
                if (J.mode == 0) {
                    int idx = m * NP + n;
                    float q = J.qid ? ((m == n) ? 1.f : 0.f) : J.Q[idx];
                    v = 2.f * v - q;
                    J.D[idx] = v;
                }
                if (J.so >= 0) packA2(J.so, m, n, v);
            }
        }
    }
}

// ---------------- big GEMM: out[s] = W_s @ x via HMMA fp16 ----------------
// CTA tile 128m x 128n, 3-stage cp.async, 2 CTAs/SM (at mma.sync roofline)
#define STAGE_BYTES 32768
#define NSTAGE 3
#define DSMEM_TOTAL (NSTAGE * STAGE_BYTES)

__global__ void __launch_bounds__(256, 2) k_bigmma(float* __restrict__ out) {
    extern __shared__ __align__(1024) char smem[];
    uint32_t sb = (uint32_t)__cvta_generic_to_shared(smem);
    int tid = threadIdx.x, wid = tid >> 5, lid = tid & 31;
    int mt = blockIdx.x & 3, s = blockIdx.x >> 2, nt = blockIdx.y;
    int wm0 = (wid >> 2) * 64;
    int wn0 = (wid & 3) * 32;

    const char* pAh = (const char*)(g_Ah + ((size_t)((s * 4 + mt) * 8)) * 8192);

    float acc[4][4][4] = {};

    auto issue = [&](int c) {
        uint32_t dst = sb + (c % NSTAGE) * STAGE_BYTES;
        size_t aoff = (size_t)c * 16384;
        size_t boff = ((size_t)(nt * 8 + c)) * 16384;
#pragma unroll
        for (int it = 0; it < 4; it++) {
            uint32_t o = (uint32_t)(tid + it * 256) * 16;
            cpasync16(dst + o,         pAh + aoff + o);
            cpasync16(dst + 16384 + o, (const char*)g_Bh + boff + o);
        }
        asm volatile("cp.async.commit_group;");
    };

    issue(0);
    issue(1);

    for (int c = 0; c < 8; c++) {
        asm volatile("cp.async.wait_group 1;");
        __syncthreads();
        if (c + 2 < 8) issue(c + 2);
        else asm volatile("cp.async.commit_group;");

        uint32_t base = sb + (c % NSTAGE) * STAGE_BYTES;
        uint32_t sAh = base, sBh = base + 16384;

#pragma unroll
        for (int kk = 0; kk < 4; kk++) {
            uint32_t ah[4][4], bh[2][4];
#pragma unroll
            for (int i = 0; i < 4; i++) {
                uint32_t off = (uint32_t)(wm0 + i * 16 + (lid & 15)) * 128 +
                               kk * 32 + (lid >> 4) * 16;
                off ^= (off >> 3) & 0x70;
                ldmx4(ah[i], sAh + off);
            }
#pragma unroll
            for (int g = 0; g < 2; g++) {
                int nl = wn0 + g * 16 + ((lid >> 4) & 1) * 8 + (lid & 7);
                uint32_t off = (uint32_t)nl * 128 +
                               kk * 32 + ((lid >> 3) & 1) * 16;
                off ^= (off >> 3) & 0x70;
                ldmx4(bh[g], sBh + off);
            }
#pragma unroll
            for (int i = 0; i < 4; i++) {
#pragma unroll
                for (int j = 0; j < 4; j++) {
                    int g = j >> 1, h = (j & 1) * 2;
                    mma16816(acc[i][j], ah[i], &bh[g][h]);
                }
            }
        }
    }

    // epilogue
    int qrow = lid >> 2, qcol = (lid & 3) * 2;
#pragma unroll
    for (int i = 0; i < 4; i++) {
        int m0g = mt * 128 + wm0 + i * 16 + qrow;
#pragma unroll
        for (int j = 0; j < 4; j++) {
            int n = nt * 128 + wn0 + j * 8 + qcol;
            if (m0g < NNODES) {
                size_t idx = ((size_t)s * NNODES + m0g) * NFEAT + n;
                *(float2*)(out + idx) = make_float2(acc[i][j][0], acc[i][j][1]);
            }
            if (m0g + 8 < NNODES) {
                size_t idx = ((size_t)s * NNODES + m0g + 8) * NFEAT + n;
                *(float2*)(out + idx) = make_float2(acc[i][j][2], acc[i][j][3]);
            }
        }
    }
}

// ---------------- launch (single stream — graph-capture safe) ----------------
extern "C" void kernel_launch(void* const* d_in, const int* in_sizes, int n_in,
                              void* d_out, int out_size) {
    const float* x      = (const float*)d_in[0];
    const int*   ei     = (const int*)d_in[1];
    const float* scales = (const float*)d_in[2];
    float* out = (float*)d_out;

    float *pM, *pTa, *pTb, *pTc, *pW;
    cudaGetSymbolAddress((void**)&pM,  g_M);
    cudaGetSymbolAddress((void**)&pTa, g_Ta);
    cudaGetSymbolAddress((void**)&pTb, g_Tb);
    cudaGetSymbolAddress((void**)&pTc, g_Tc);
    cudaGetSymbolAddress((void**)&pW,  g_W);

    static int smem_set = 0;
    if (!smem_set) {
        cudaFuncSetAttribute(k_bigmma, cudaFuncAttributeMaxDynamicSharedMemorySize,
                             DSMEM_TOTAL);
        cudaFuncSetAttribute(k_mm3, cudaFuncAttributeMaxDynamicSharedMemorySize,
                             SQ_SMEM);
        smem_set = 1;
    }

    const size_t NPNP = (size_t)NP * NP;
    float* pW0 = pW;
    float* pW1 = pW + NPNP;
    float* pW2 = pW + 2 * NPNP;
    float* pW3 = pW + 3 * NPNP;

    // build
    k_zero<<<(NP * NP + 255) / 256, 256>>>();
    k_degree<<<(NEDGE + 255) / 256, 256>>>(ei);
    k_adj<<<(NEDGE + 255) / 256, 256>>>(ei);
    k_rows<<<NP, 128>>>();
    dim3 gc(NCOEF, 2);
    k_coef<<<gc, DCTN>>>(scales);
    k_scaleM<<<(NP * NP + 255) / 256, 256>>>();   // packs slot 4

    // x transpose + fp16 pack
    dim3 gx(256, 16);
    k_convX<<<gx, 256>>>(x);

    // Chebyshev via HMMA on packed slots (4=M, 5=T2, 6=T3, 7=T4)
    dim3 gz1(8, 8, 1), gz2(8, 8, 2), gz4(8, 8, 4);
    MMJob JD = {0, 0, nullptr, nullptr, 0, -1, 1};  // dummy filler

    // wave 1: T2 = 2 M M - I  (fp32 Ta + pack slot 5)
    MMJob w1 = {4, 4, nullptr, pTa, 1, 5, 0};
    k_mm3<<<gz1, 256, SQ_SMEM>>>(w1, JD, JD, JD);

    // wave 2: T3 = 2 M T2 - M ; T4 = 2 T2 T2 - I
    MMJob w2a = {4, 5, pM, pTb, 0, 6, 0};
    MMJob w2b = {5, 5, nullptr, pTc, 1, 7, 0};
    k_mm3<<<gz2, 256, SQ_SMEM>>>(w2a, w2b, JD, JD);

    // wave 3: T5 = 2 T2 T3 - M ; T6 = 2 T3 T3 - I ; T7 = 2 T3 T4 - M ; T8 = 2 T4 T4 - I
    MMJob w3a = {5, 6, pM, pW0, 0, -1, 0};
    MMJob w3b = {6, 6, nullptr, pW1, 1, -1, 0};
    MMJob w3c = {6, 7, pM, pW2, 0, -1, 0};
    MMJob w3d = {7, 7, nullptr, pW3, 1, -1, 0};
    k_mm3<<<gz4, 256, SQ_SMEM>>>(w3a, w3b, w3c, w3d);

    // W(0.5) -> slot 0 and W(1) -> slot 1 (dual coefficient sets)
    k_sum<<<(NP * NP + 255) / 256, 256>>>();

    // HMMA squaring ladder: 1 -> 2 -> 4 (slots 1->2->3)
    MMJob q2 = {1, 1, nullptr, nullptr, 0, 2, 1};
    MMJob q3 = {2, 2, nullptr, nullptr, 0, 3, 1};
    k_mm3<<<gz1, 256, SQ_SMEM>>>(q2, JD, JD, JD);
    k_mm3<<<gz1, 256, SQ_SMEM>>>(q3, JD, JD, JD);

    // big HMMA GEMM: blockIdx.x = mt + 4*s (16), blockIdx.y = n tile of 128 (256)
    dim3 gb(16, 256);
    k_bigmma<<<gb, 256, DSMEM_TOTAL>>>(out);
}